// round 1
// baseline (speedup 1.0000x reference)
#include <cuda_runtime.h>
#include <math.h>

#define NTOK 1024
#define DMODEL 512
#define NHEAD 8
#define DH 64
#define BATCH 8
#define DEPTH 4
#define ROWS (BATCH*NTOK)   // 8192

// ---------------- scratch (static device globals; no runtime allocation) ----
__device__ float g_t  [ROWS*DMODEL];      // residual stream           16 MB
__device__ float g_h  [ROWS*DMODEL];      // LN output                 16 MB
__device__ float g_qkv[ROWS*3*DMODEL];    // qkv                       48 MB
__device__ float g_o  [ROWS*DMODEL];      // attention output          16 MB
__device__ float g_f1 [ROWS*2*DMODEL];    // ffn hidden                32 MB

// ---------------- embed: transpose [b,c,n] -> [b,n,c] and add sinusoid PE ---
__global__ void embed_kernel(const float* __restrict__ x, float* __restrict__ t) {
    __shared__ float tile[32][33];
    int n0 = blockIdx.x * 32, c0 = blockIdx.y * 32, b = blockIdx.z;
    int tx = threadIdx.x, ty = threadIdx.y;
#pragma unroll
    for (int i = 0; i < 4; i++) {
        int c = c0 + ty + i * 8;
        tile[ty + i * 8][tx] = x[((size_t)b * DMODEL + c) * NTOK + n0 + tx];
    }
    __syncthreads();
#pragma unroll
    for (int i = 0; i < 4; i++) {
        int n = n0 + ty + i * 8;
        int c = c0 + tx;
        float e = (float)(c & ~1) * (1.0f / DMODEL);
        float ang = (float)n * expf(-9.210340371976184f * e);   // / 10000^(e)
        float pe = (c & 1) ? cosf(ang) : sinf(ang);
        t[((size_t)b * NTOK + n) * DMODEL + c] = tile[tx][ty + i * 8] + pe;
    }
}

// ---------------- unembed: transpose [b,n,c] -> [b,c,n] ---------------------
__global__ void unembed_kernel(const float* __restrict__ h, float* __restrict__ out) {
    __shared__ float tile[32][33];
    int n0 = blockIdx.x * 32, c0 = blockIdx.y * 32, b = blockIdx.z;
    int tx = threadIdx.x, ty = threadIdx.y;
#pragma unroll
    for (int i = 0; i < 4; i++) {
        int n = n0 + ty + i * 8;
        tile[ty + i * 8][tx] = h[((size_t)b * NTOK + n) * DMODEL + c0 + tx];
    }
    __syncthreads();
#pragma unroll
    for (int i = 0; i < 4; i++) {
        int c = c0 + ty + i * 8;
        out[((size_t)b * DMODEL + c) * NTOK + n0 + tx] = tile[tx][ty + i * 8];
    }
}

// ---------------- layernorm: one warp per 512-wide row ----------------------
__global__ void ln_kernel(const float* __restrict__ x, const float* __restrict__ w,
                          const float* __restrict__ bias, float* __restrict__ y) {
    int gw = (blockIdx.x * blockDim.x + threadIdx.x) >> 5;
    int lane = threadIdx.x & 31;
    if (gw >= ROWS) return;
    const float4* xr = (const float4*)(x + (size_t)gw * DMODEL);
    float4 v[4];
    float s = 0.0f;
#pragma unroll
    for (int u = 0; u < 4; u++) {
        v[u] = xr[u * 32 + lane];
        s += v[u].x + v[u].y + v[u].z + v[u].w;
    }
#pragma unroll
    for (int o = 16; o > 0; o >>= 1) s += __shfl_xor_sync(0xffffffffu, s, o);
    float mu = s * (1.0f / DMODEL);
    float q = 0.0f;
#pragma unroll
    for (int u = 0; u < 4; u++) {
        v[u].x -= mu; v[u].y -= mu; v[u].z -= mu; v[u].w -= mu;
        q += v[u].x * v[u].x + v[u].y * v[u].y + v[u].z * v[u].z + v[u].w * v[u].w;
    }
#pragma unroll
    for (int o = 16; o > 0; o >>= 1) q += __shfl_xor_sync(0xffffffffu, q, o);
    float rstd = rsqrtf(q * (1.0f / DMODEL) + 1e-5f);
    const float4* wr = (const float4*)w;
    const float4* br = (const float4*)bias;
    float4* yr = (float4*)(y + (size_t)gw * DMODEL);
#pragma unroll
    for (int u = 0; u < 4; u++) {
        float4 W = wr[u * 32 + lane], B = br[u * 32 + lane], o4;
        o4.x = v[u].x * rstd * W.x + B.x;
        o4.y = v[u].y * rstd * W.y + B.y;
        o4.z = v[u].z * rstd * W.z + B.z;
        o4.w = v[u].w * rstd * W.w + B.w;
        yr[u * 32 + lane] = o4;
    }
}

// ---------------- GEMM: C[M,N] = A[M,K] * W[N,K]^T (+bias,+gelu,+resid) -----
__device__ __forceinline__ float gelu_exact(float v) {
    return 0.5f * v * (1.0f + erff(v * 0.7071067811865476f));
}

template <bool GELU, bool RESID>
__global__ void __launch_bounds__(256) gemm_kernel(
    const float* __restrict__ A, const float* __restrict__ W,
    const float* __restrict__ bias, const float* __restrict__ resid,
    float* __restrict__ C, int M, int N, int K) {
    __shared__ float As[16][64];
    __shared__ float Bs[16][64];
    int n0 = blockIdx.x * 64, m0 = blockIdx.y * 64;
    int tid = threadIdx.x;
    int tx = tid & 15, ty = tid >> 4;
    int lr = tid >> 2;
    int lc = (tid & 3) * 4;
    const float* Ap = A + (size_t)(m0 + lr) * K + lc;
    const float* Wp = W + (size_t)(n0 + lr) * K + lc;
    float acc[4][4] = {};
    for (int k0 = 0; k0 < K; k0 += 16) {
        float4 av = *(const float4*)(Ap + k0);
        float4 bv = *(const float4*)(Wp + k0);
        As[lc + 0][lr] = av.x; As[lc + 1][lr] = av.y;
        As[lc + 2][lr] = av.z; As[lc + 3][lr] = av.w;
        Bs[lc + 0][lr] = bv.x; Bs[lc + 1][lr] = bv.y;
        Bs[lc + 2][lr] = bv.z; Bs[lc + 3][lr] = bv.w;
        __syncthreads();
#pragma unroll
        for (int k = 0; k < 16; k++) {
            float4 a4 = *(const float4*)&As[k][ty * 4];
            float4 b4 = *(const float4*)&Bs[k][tx * 4];
            float ar[4] = {a4.x, a4.y, a4.z, a4.w};
            float br[4] = {b4.x, b4.y, b4.z, b4.w};
#pragma unroll
            for (int i = 0; i < 4; i++)
#pragma unroll
                for (int j = 0; j < 4; j++) acc[i][j] += ar[i] * br[j];
        }
        __syncthreads();
    }
    int row = m0 + ty * 4, col = n0 + tx * 4;
#pragma unroll
    for (int i = 0; i < 4; i++) {
#pragma unroll
        for (int j = 0; j < 4; j++) {
            float v = acc[i][j];
            int cc = col + j;
            if (bias) v += bias[cc];
            if (GELU) v = gelu_exact(v);
            size_t off = (size_t)(row + i) * N + cc;
            if (RESID) v += resid[off];
            C[off] = v;
        }
    }
}

// ---------------- flash attention: block = (b,h) x 64 query rows ------------
#define FST 65
__global__ void __launch_bounds__(256) attn_kernel(const float* __restrict__ qkv,
                                                   float* __restrict__ o) {
    extern __shared__ float sm[];
    float* Qs = sm;                  // 64*FST
    float* Ks = Qs + 64 * FST;
    float* Vs = Ks + 64 * FST;
    float* Ss = Vs + 64 * FST;
    float* mrow = Ss + 64 * FST;     // 64
    float* lrow = mrow + 64;         // 64
    float* arow = lrow + 64;         // 64
    float* red  = arow + 64;         // 64*4

    int q0 = blockIdx.x * 64;
    int bh = blockIdx.y;
    int b = bh >> 3, h = bh & 7;
    int tid = threadIdx.x;
    int tx = tid & 15, ty = tid >> 4;
    const float scale = 0.125f;      // 1/sqrt(64)

    // Q tile (pre-scaled)
    for (int idx = tid; idx < 64 * 16; idx += 256) {
        int r = idx >> 4, c4 = (idx & 15) * 4;
        const float4 qv = *(const float4*)(qkv + ((size_t)(b * NTOK + q0 + r)) * 1536 + h * 64 + c4);
        float* dst = Qs + r * FST + c4;
        dst[0] = qv.x * scale; dst[1] = qv.y * scale;
        dst[2] = qv.z * scale; dst[3] = qv.w * scale;
    }
    if (tid < 64) { mrow[tid] = -1e30f; lrow[tid] = 0.0f; }
    float acc[4][4] = {};

    for (int kt = 0; kt < 16; kt++) {
        int k0 = kt * 64;
        for (int idx = tid; idx < 64 * 16; idx += 256) {
            int r = idx >> 4, c4 = (idx & 15) * 4;
            size_t base = ((size_t)(b * NTOK + k0 + r)) * 1536 + h * 64 + c4;
            float4 kv = *(const float4*)(qkv + base + 512);
            float4 vv = *(const float4*)(qkv + base + 1024);
            float* kd = Ks + r * FST + c4;
            kd[0] = kv.x; kd[1] = kv.y; kd[2] = kv.z; kd[3] = kv.w;
            float* vd = Vs + r * FST + c4;
            vd[0] = vv.x; vd[1] = vv.y; vd[2] = vv.z; vd[3] = vv.w;
        }
        __syncthreads();

        // S = Qs * Ks^T  (4x4 per thread)
        float s[4][4] = {};
        const float* qb = Qs + (ty * 4) * FST;
        const float* kb = Ks + (tx * 4) * FST;
#pragma unroll 4
        for (int k = 0; k < 64; k++) {
            float qr[4], kr[4];
#pragma unroll
            for (int i = 0; i < 4; i++) qr[i] = qb[i * FST + k];
#pragma unroll
            for (int j = 0; j < 4; j++) kr[j] = kb[j * FST + k];
#pragma unroll
            for (int i = 0; i < 4; i++)
#pragma unroll
                for (int j = 0; j < 4; j++) s[i][j] += qr[i] * kr[j];
        }
#pragma unroll
        for (int i = 0; i < 4; i++)
#pragma unroll
            for (int j = 0; j < 4; j++) Ss[(ty * 4 + i) * FST + tx * 4 + j] = s[i][j];
        __syncthreads();

        // row max (4 partial threads/row)
        {
            int r = tid >> 2, p = tid & 3;
            float mx = -1e30f;
            const float* sr = Ss + r * FST + p * 16;
#pragma unroll
            for (int u = 0; u < 16; u++) mx = fmaxf(mx, sr[u]);
            red[r * 4 + p] = mx;
        }
        __syncthreads();
        if (tid < 64) {
            float mx = fmaxf(fmaxf(red[tid * 4], red[tid * 4 + 1]),
                             fmaxf(red[tid * 4 + 2], red[tid * 4 + 3]));
            float mold = mrow[tid];
            float mnew = fmaxf(mold, mx);
            mrow[tid] = mnew;
            arow[tid] = __expf(mold - mnew);
        }
        __syncthreads();

        // P = exp(S - m), rescale accumulator
        float mr[4], al[4];
#pragma unroll
        for (int i = 0; i < 4; i++) { mr[i] = mrow[ty * 4 + i]; al[i] = arow[ty * 4 + i]; }
#pragma unroll
        for (int i = 0; i < 4; i++)
#pragma unroll
            for (int j = 0; j < 4; j++) {
                float p = __expf(s[i][j] - mr[i]);
                Ss[(ty * 4 + i) * FST + tx * 4 + j] = p;
                acc[i][j] *= al[i];
            }
        __syncthreads();

        // row sum
        {
            int r = tid >> 2, p = tid & 3;
            float sm_ = 0.0f;
            const float* sr = Ss + r * FST + p * 16;
#pragma unroll
            for (int u = 0; u < 16; u++) sm_ += sr[u];
            red[r * 4 + p] = sm_;
        }
        __syncthreads();
        if (tid < 64) {
            lrow[tid] = lrow[tid] * arow[tid] +
                        (red[tid * 4] + red[tid * 4 + 1] + red[tid * 4 + 2] + red[tid * 4 + 3]);
        }

        // O += P * V
        const float* pb = Ss + (ty * 4) * FST;
#pragma unroll 4
        for (int k = 0; k < 64; k++) {
            float pr[4], vr[4];
#pragma unroll
            for (int i = 0; i < 4; i++) pr[i] = pb[i * FST + k];
#pragma unroll
            for (int j = 0; j < 4; j++) vr[j] = Vs[k * FST + tx * 4 + j];
#pragma unroll
            for (int i = 0; i < 4; i++)
#pragma unroll
                for (int j = 0; j < 4; j++) acc[i][j] += pr[i] * vr[j];
        }
        __syncthreads();
    }

    float linv[4];
#pragma unroll
    for (int i = 0; i < 4; i++) linv[i] = 1.0f / lrow[ty * 4 + i];
#pragma unroll
    for (int i = 0; i < 4; i++)
#pragma unroll
        for (int j = 0; j < 4; j++)
            o[((size_t)(b * NTOK + q0 + ty * 4 + i)) * DMODEL + h * 64 + tx * 4 + j] =
                acc[i][j] * linv[i];
}

// ---------------- host orchestration ---------------------------------------
extern "C" void kernel_launch(void* const* d_in, const int* in_sizes, int n_in,
                              void* d_out, int out_size) {
    const float* x         = (const float*)d_in[0];
    const float* attn_ln_w = (const float*)d_in[1];
    const float* attn_ln_b = (const float*)d_in[2];
    const float* w_qkv     = (const float*)d_in[3];
    const float* w_out     = (const float*)d_in[4];
    const float* b_out     = (const float*)d_in[5];
    const float* ffn_ln_w  = (const float*)d_in[6];
    const float* ffn_ln_b  = (const float*)d_in[7];
    const float* w1        = (const float*)d_in[8];
    const float* b1        = (const float*)d_in[9];
    const float* w2        = (const float*)d_in[10];
    const float* b2        = (const float*)d_in[11];
    const float* ln_w      = (const float*)d_in[12];
    const float* ln_b      = (const float*)d_in[13];
    float* out = (float*)d_out;

    float *t, *h, *qkv, *o, *f1;
    cudaGetSymbolAddress((void**)&t,   g_t);
    cudaGetSymbolAddress((void**)&h,   g_h);
    cudaGetSymbolAddress((void**)&qkv, g_qkv);
    cudaGetSymbolAddress((void**)&o,   g_o);
    cudaGetSymbolAddress((void**)&f1,  g_f1);

    cudaFuncSetAttribute(attn_kernel, cudaFuncAttributeMaxDynamicSharedMemorySize, 68352);

    dim3 tb(32, 8);
    embed_kernel<<<dim3(32, 16, 8), tb>>>(x, t);

    for (int l = 0; l < DEPTH; l++) {
        ln_kernel<<<1024, 256>>>(t, attn_ln_w + l * DMODEL, attn_ln_b + l * DMODEL, h);
        gemm_kernel<false, false><<<dim3(24, 128), 256>>>(
            h, w_qkv + (size_t)l * 3 * DMODEL * DMODEL, nullptr, nullptr, qkv,
            ROWS, 3 * DMODEL, DMODEL);
        attn_kernel<<<dim3(16, 64), 256, 68352>>>(qkv, o);
        gemm_kernel<false, true><<<dim3(8, 128), 256>>>(
            o, w_out + (size_t)l * DMODEL * DMODEL, b_out + l * DMODEL, t, t,
            ROWS, DMODEL, DMODEL);
        ln_kernel<<<1024, 256>>>(t, ffn_ln_w, ffn_ln_b, h);
        gemm_kernel<true, false><<<dim3(16, 128), 256>>>(
            h, w1, b1, nullptr, f1, ROWS, 2 * DMODEL, DMODEL);
        gemm_kernel<false, true><<<dim3(8, 128), 256>>>(
            f1, w2, b2, t, t, ROWS, DMODEL, 2 * DMODEL);
    }

    ln_kernel<<<1024, 256>>>(t, ln_w, ln_b, h);
    unembed_kernel<<<dim3(32, 16, 8), tb>>>(h, out);
}

// round 3
// speedup vs baseline: 1.7430x; 1.7430x over previous
#include <cuda_runtime.h>
#include <cuda_bf16.h>
#include <math.h>
#include <stdint.h>

#define NTOK 1024
#define DMODEL 512
#define BATCH 8
#define DEPTH 4
#define ROWS (BATCH*NTOK)   // 8192

// ---------------- scratch (static device globals; no runtime allocation) ----
__device__ float g_t  [ROWS*DMODEL];
__device__ float g_h  [ROWS*DMODEL];
__device__ float g_qkv[ROWS*3*DMODEL];
__device__ __nv_bfloat16 g_hhi[ROWS*DMODEL], g_hlo[ROWS*DMODEL];
__device__ __nv_bfloat16 g_ohi[ROWS*DMODEL], g_olo[ROWS*DMODEL];
__device__ __nv_bfloat16 g_f1hi[ROWS*2*DMODEL], g_f1lo[ROWS*2*DMODEL];
__device__ __nv_bfloat16 g_wqkvhi[DEPTH*3*DMODEL*DMODEL], g_wqkvlo[DEPTH*3*DMODEL*DMODEL];
__device__ __nv_bfloat16 g_wouthi[DEPTH*DMODEL*DMODEL],   g_woutlo[DEPTH*DMODEL*DMODEL];
__device__ __nv_bfloat16 g_w1hi[2*DMODEL*DMODEL],         g_w1lo[2*DMODEL*DMODEL];
__device__ __nv_bfloat16 g_w2hi[2*DMODEL*DMODEL],         g_w2lo[2*DMODEL*DMODEL];

// ---------------- bf16 hi/lo split of an fp32 tensor ------------------------
__global__ void split_w(const float* __restrict__ w, __nv_bfloat16* __restrict__ hi,
                        __nv_bfloat16* __restrict__ lo, int n) {
    int i = blockIdx.x * 256 + threadIdx.x;
    if (i < n) {
        float v = w[i];
        __nv_bfloat16 h = __float2bfloat16_rn(v);
        hi[i] = h;
        lo[i] = __float2bfloat16_rn(v - __bfloat162float(h));
    }
}

// ---------------- embed: transpose [b,c,n] -> [b,n,c] and add sinusoid PE ---
__global__ void embed_kernel(const float* __restrict__ x, float* __restrict__ t) {
    __shared__ float tile[32][33];
    int n0 = blockIdx.x * 32, c0 = blockIdx.y * 32, b = blockIdx.z;
    int tx = threadIdx.x, ty = threadIdx.y;
#pragma unroll
    for (int i = 0; i < 4; i++) {
        int c = c0 + ty + i * 8;
        tile[ty + i * 8][tx] = x[((size_t)b * DMODEL + c) * NTOK + n0 + tx];
    }
    __syncthreads();
#pragma unroll
    for (int i = 0; i < 4; i++) {
        int n = n0 + ty + i * 8;
        int c = c0 + tx;
        float e = (float)(c & ~1) * (1.0f / DMODEL);
        float ang = (float)n * expf(-9.210340371976184f * e);
        float pe = (c & 1) ? cosf(ang) : sinf(ang);
        t[((size_t)b * NTOK + n) * DMODEL + c] = tile[tx][ty + i * 8] + pe;
    }
}

// ---------------- unembed -----------------------------------------------------
__global__ void unembed_kernel(const float* __restrict__ h, float* __restrict__ out) {
    __shared__ float tile[32][33];
    int n0 = blockIdx.x * 32, c0 = blockIdx.y * 32, b = blockIdx.z;
    int tx = threadIdx.x, ty = threadIdx.y;
#pragma unroll
    for (int i = 0; i < 4; i++) {
        int n = n0 + ty + i * 8;
        tile[ty + i * 8][tx] = h[((size_t)b * NTOK + n) * DMODEL + c0 + tx];
    }
    __syncthreads();
#pragma unroll
    for (int i = 0; i < 4; i++) {
        int c = c0 + ty + i * 8;
        out[((size_t)b * DMODEL + c) * NTOK + n0 + tx] = tile[tx][ty + i * 8];
    }
}

// ---------------- layernorm: one warp per row; SPLIT -> bf16 hi/lo planes ----
template <bool SPLIT>
__global__ void ln_kernel(const float* __restrict__ x, const float* __restrict__ w,
                          const float* __restrict__ bias, float* __restrict__ y,
                          __nv_bfloat16* __restrict__ yhi, __nv_bfloat16* __restrict__ ylo) {
    int gw = (blockIdx.x * blockDim.x + threadIdx.x) >> 5;
    int lane = threadIdx.x & 31;
    if (gw >= ROWS) return;
    const float4* xr = (const float4*)(x + (size_t)gw * DMODEL);
    float4 v[4];
    float s = 0.0f;
#pragma unroll
    for (int u = 0; u < 4; u++) {
        v[u] = xr[u * 32 + lane];
        s += v[u].x + v[u].y + v[u].z + v[u].w;
    }
#pragma unroll
    for (int o = 16; o > 0; o >>= 1) s += __shfl_xor_sync(0xffffffffu, s, o);
    float mu = s * (1.0f / DMODEL);
    float q = 0.0f;
#pragma unroll
    for (int u = 0; u < 4; u++) {
        v[u].x -= mu; v[u].y -= mu; v[u].z -= mu; v[u].w -= mu;
        q += v[u].x * v[u].x + v[u].y * v[u].y + v[u].z * v[u].z + v[u].w * v[u].w;
    }
#pragma unroll
    for (int o = 16; o > 0; o >>= 1) q += __shfl_xor_sync(0xffffffffu, q, o);
    float rstd = rsqrtf(q * (1.0f / DMODEL) + 1e-5f);
    const float4* wr = (const float4*)w;
    const float4* br = (const float4*)bias;
#pragma unroll
    for (int u = 0; u < 4; u++) {
        float4 W = wr[u * 32 + lane], B = br[u * 32 + lane], o4;
        o4.x = v[u].x * rstd * W.x + B.x;
        o4.y = v[u].y * rstd * W.y + B.y;
        o4.z = v[u].z * rstd * W.z + B.z;
        o4.w = v[u].w * rstd * W.w + B.w;
        if (SPLIT) {
            size_t off = (size_t)gw * DMODEL + (u * 32 + lane) * 4;
            __nv_bfloat16 h0 = __float2bfloat16_rn(o4.x), h1 = __float2bfloat16_rn(o4.y);
            __nv_bfloat16 h2 = __float2bfloat16_rn(o4.z), h3 = __float2bfloat16_rn(o4.w);
            *(__nv_bfloat162*)(yhi + off)     = __halves2bfloat162(h0, h1);
            *(__nv_bfloat162*)(yhi + off + 2) = __halves2bfloat162(h2, h3);
            *(__nv_bfloat162*)(ylo + off) = __halves2bfloat162(
                __float2bfloat16_rn(o4.x - __bfloat162float(h0)),
                __float2bfloat16_rn(o4.y - __bfloat162float(h1)));
            *(__nv_bfloat162*)(ylo + off + 2) = __halves2bfloat162(
                __float2bfloat16_rn(o4.z - __bfloat162float(h2)),
                __float2bfloat16_rn(o4.w - __bfloat162float(h3)));
        } else {
            ((float4*)(y + (size_t)gw * DMODEL))[u * 32 + lane] = o4;
        }
    }
}

// ---------------- tensor-core GEMM (bf16x3): C = A * W^T --------------------
#define BM 128
#define BN 128
#define BK 32
#define KST 40
#define PLANE (128*KST)      // 5120 bf16
#define STAGE (4*PLANE)      // 20480 bf16 per stage

__device__ __forceinline__ void ldsm4(uint32_t& r0, uint32_t& r1, uint32_t& r2, uint32_t& r3,
                                      uint32_t addr) {
    asm volatile("ldmatrix.sync.aligned.m8n8.x4.shared.b16 {%0,%1,%2,%3},[%4];"
                 : "=r"(r0), "=r"(r1), "=r"(r2), "=r"(r3) : "r"(addr));
}
__device__ __forceinline__ void mma_bf16(float* c, const uint32_t* a, const uint32_t* b) {
    asm volatile(
        "mma.sync.aligned.m16n8k16.row.col.f32.bf16.bf16.f32 "
        "{%0,%1,%2,%3},{%4,%5,%6,%7},{%8,%9},{%0,%1,%2,%3};"
        : "+f"(c[0]), "+f"(c[1]), "+f"(c[2]), "+f"(c[3])
        : "r"(a[0]), "r"(a[1]), "r"(a[2]), "r"(a[3]), "r"(b[0]), "r"(b[1]));
}
__device__ __forceinline__ void cpasync16(uint32_t saddr, const void* g) {
    asm volatile("cp.async.cg.shared.global [%0],[%1],16;" :: "r"(saddr), "l"(g));
}

__device__ __forceinline__ float gelu_exact(float v) {
    return 0.5f * v * (1.0f + erff(v * 0.7071067811865476f));
}

// MODE 0: plain fp32 out. MODE 1: fp32 = acc + bias + resid. MODE 2: bf16 hi/lo out = gelu(acc+bias)
template <int MODE>
__global__ void __launch_bounds__(256) gemm_tc(
    const __nv_bfloat16* __restrict__ Ahi, const __nv_bfloat16* __restrict__ Alo,
    const __nv_bfloat16* __restrict__ Bhi, const __nv_bfloat16* __restrict__ Blo,
    const float* __restrict__ bias, const float* __restrict__ resid,
    float* __restrict__ C, __nv_bfloat16* __restrict__ Chi, __nv_bfloat16* __restrict__ Clo,
    int N, int K) {
    extern __shared__ __nv_bfloat16 smbuf[];
    const int tid = threadIdx.x;
    const int lane = tid & 31, w = tid >> 5;
    const int wr = w >> 2, wc = w & 3;
    const int m0 = blockIdx.y * BM, n0 = blockIdx.x * BN;
    const uint32_t smbase = (uint32_t)__cvta_generic_to_shared(smbuf);

    const int r0i = tid >> 2;
    const int c0i = (tid & 3) * 8;

    auto load_stage = [&](int it, int buf) {
        const int k0 = it * BK;
        size_t aoff0 = (size_t)(m0 + r0i) * K + k0 + c0i;
        size_t aoff1 = aoff0 + (size_t)64 * K;
        size_t boff0 = (size_t)(n0 + r0i) * K + k0 + c0i;
        size_t boff1 = boff0 + (size_t)64 * K;
        uint32_t s0 = smbase + (uint32_t)(buf * STAGE + r0i * KST + c0i) * 2;
        uint32_t s1 = smbase + (uint32_t)(buf * STAGE + (r0i + 64) * KST + c0i) * 2;
        cpasync16(s0,                 Ahi + aoff0);
        cpasync16(s1,                 Ahi + aoff1);
        cpasync16(s0 + PLANE * 2,     Alo + aoff0);
        cpasync16(s1 + PLANE * 2,     Alo + aoff1);
        cpasync16(s0 + 2 * PLANE * 2, Bhi + boff0);
        cpasync16(s1 + 2 * PLANE * 2, Bhi + boff1);
        cpasync16(s0 + 3 * PLANE * 2, Blo + boff0);
        cpasync16(s1 + 3 * PLANE * 2, Blo + boff1);
    };

    float acc[4][4][4] = {};

    const int arow = wr * 64 + (lane & 15);
    const int acol = (lane >> 4) * 8;
    const int bn   = wc * 32 + ((lane >> 4) << 3) + (lane & 7);
    const int bk   = ((lane >> 3) & 1) << 3;

    const int niter = K / BK;
    load_stage(0, 0);
    asm volatile("cp.async.commit_group;");
    for (int it = 0; it < niter; ++it) {
        if (it + 1 < niter) {
            load_stage(it + 1, (it + 1) & 1);
            asm volatile("cp.async.commit_group;");
            asm volatile("cp.async.wait_group 1;");
        } else {
            asm volatile("cp.async.wait_group 0;");
        }
        __syncthreads();
        const uint32_t base = smbase + (uint32_t)(it & 1) * STAGE * 2;
#pragma unroll
        for (int kk = 0; kk < BK; kk += 16) {
            uint32_t ahi[4][4], alo[4][4], bhi[4][2], blo[4][2];
#pragma unroll
            for (int mt = 0; mt < 4; ++mt) {
                uint32_t ai = base + (uint32_t)((arow + mt * 16) * KST + kk + acol) * 2;
                ldsm4(ahi[mt][0], ahi[mt][1], ahi[mt][2], ahi[mt][3], ai);
                ldsm4(alo[mt][0], alo[mt][1], alo[mt][2], alo[mt][3], ai + PLANE * 2);
            }
#pragma unroll
            for (int g = 0; g < 2; ++g) {
                uint32_t bi = base + 2 * PLANE * 2 +
                              (uint32_t)((bn + g * 16) * KST + kk + bk) * 2;
                ldsm4(bhi[2 * g][0], bhi[2 * g][1], bhi[2 * g + 1][0], bhi[2 * g + 1][1], bi);
                ldsm4(blo[2 * g][0], blo[2 * g][1], blo[2 * g + 1][0], blo[2 * g + 1][1],
                      bi + PLANE * 2);
            }
#pragma unroll
            for (int mt = 0; mt < 4; ++mt)
#pragma unroll
                for (int nt = 0; nt < 4; ++nt) {
                    mma_bf16(acc[mt][nt], ahi[mt], bhi[nt]);
                    mma_bf16(acc[mt][nt], ahi[mt], blo[nt]);
                    mma_bf16(acc[mt][nt], alo[mt], bhi[nt]);
                }
        }
        __syncthreads();
    }

    const int erow = m0 + wr * 64 + (lane >> 2);
    const int ecol = n0 + wc * 32 + (lane & 3) * 2;
#pragma unroll
    for (int mt = 0; mt < 4; ++mt)
#pragma unroll
        for (int nt = 0; nt < 4; ++nt) {
            int c = ecol + nt * 8;
#pragma unroll
            for (int half = 0; half < 2; ++half) {
                int rr = erow + mt * 16 + half * 8;
                float v0 = acc[mt][nt][half * 2 + 0];
                float v1 = acc[mt][nt][half * 2 + 1];
                size_t off = (size_t)rr * N + c;
                if (MODE == 0) {
                    *(float2*)(C + off) = make_float2(v0, v1);
                } else if (MODE == 1) {
                    float2 rv = *(const float2*)(resid + off);
                    v0 += bias[c] + rv.x;
                    v1 += bias[c + 1] + rv.y;
                    *(float2*)(C + off) = make_float2(v0, v1);
                } else {
                    v0 = gelu_exact(v0 + bias[c]);
                    v1 = gelu_exact(v1 + bias[c + 1]);
                    __nv_bfloat16 h0 = __float2bfloat16_rn(v0);
                    __nv_bfloat16 h1 = __float2bfloat16_rn(v1);
                    *(__nv_bfloat162*)(Chi + off) = __halves2bfloat162(h0, h1);
                    *(__nv_bfloat162*)(Clo + off) = __halves2bfloat162(
                        __float2bfloat16_rn(v0 - __bfloat162float(h0)),
                        __float2bfloat16_rn(v1 - __bfloat162float(h1)));
                }
            }
        }
}

// ---------------- flash attention (fp32) -------------------------------------
#define FST 65
__global__ void __launch_bounds__(256) attn_kernel(const float* __restrict__ qkv,
                                                   __nv_bfloat16* __restrict__ ohi,
                                                   __nv_bfloat16* __restrict__ olo) {
    extern __shared__ float smf[];
    float* Qs = smf;
    float* Ks = Qs + 64 * FST;
    float* Vs = Ks + 64 * FST;
    float* Ss = Vs + 64 * FST;
    float* mrow = Ss + 64 * FST;
    float* lrow = mrow + 64;
    float* arow = lrow + 64;
    float* red  = arow + 64;

    int q0 = blockIdx.x * 64;
    int bh = blockIdx.y;
    int b = bh >> 3, h = bh & 7;
    int tid = threadIdx.x;
    int tx = tid & 15, ty = tid >> 4;
    const float scale = 0.125f;

    for (int idx = tid; idx < 64 * 16; idx += 256) {
        int r = idx >> 4, c4 = (idx & 15) * 4;
        const float4 qv = *(const float4*)(qkv + ((size_t)(b * NTOK + q0 + r)) * 1536 + h * 64 + c4);
        float* dst = Qs + r * FST + c4;
        dst[0] = qv.x * scale; dst[1] = qv.y * scale;
        dst[2] = qv.z * scale; dst[3] = qv.w * scale;
    }
    if (tid < 64) { mrow[tid] = -1e30f; lrow[tid] = 0.0f; }
    float acc[4][4] = {};

    for (int kt = 0; kt < 16; kt++) {
        int k0 = kt * 64;
        for (int idx = tid; idx < 64 * 16; idx += 256) {
            int r = idx >> 4, c4 = (idx & 15) * 4;
            size_t base = ((size_t)(b * NTOK + k0 + r)) * 1536 + h * 64 + c4;
            float4 kv = *(const float4*)(qkv + base + 512);
            float4 vv = *(const float4*)(qkv + base + 1024);
            float* kd = Ks + r * FST + c4;
            kd[0] = kv.x; kd[1] = kv.y; kd[2] = kv.z; kd[3] = kv.w;
            float* vd = Vs + r * FST + c4;
            vd[0] = vv.x; vd[1] = vv.y; vd[2] = vv.z; vd[3] = vv.w;
        }
        __syncthreads();

        float s[4][4] = {};
        const float* qb = Qs + (ty * 4) * FST;
        const float* kb = Ks + (tx * 4) * FST;
#pragma unroll 4
        for (int k = 0; k < 64; k++) {
            float qr[4], kr[4];
#pragma unroll
            for (int i = 0; i < 4; i++) qr[i] = qb[i * FST + k];
#pragma unroll
            for (int j = 0; j < 4; j++) kr[j] = kb[j * FST + k];
#pragma unroll
            for (int i = 0; i < 4; i++)
#pragma unroll
                for (int j = 0; j < 4; j++) s[i][j] += qr[i] * kr[j];
        }
#pragma unroll
        for (int i = 0; i < 4; i++)
#pragma unroll
            for (int j = 0; j < 4; j++) Ss[(ty * 4 + i) * FST + tx * 4 + j] = s[i][j];
        __syncthreads();

        {
            int r = tid >> 2, p = tid & 3;
            float mx = -1e30f;
            const float* sr = Ss + r * FST + p * 16;
#pragma unroll
            for (int u = 0; u < 16; u++) mx = fmaxf(mx, sr[u]);
            red[r * 4 + p] = mx;
        }
        __syncthreads();
        if (tid < 64) {
            float mx = fmaxf(fmaxf(red[tid * 4], red[tid * 4 + 1]),
                             fmaxf(red[tid * 4 + 2], red[tid * 4 + 3]));
            float mold = mrow[tid];
            float mnew = fmaxf(mold, mx);
            mrow[tid] = mnew;
            arow[tid] = __expf(mold - mnew);
        }
        __syncthreads();

        float mr[4], al[4];
#pragma unroll
        for (int i = 0; i < 4; i++) { mr[i] = mrow[ty * 4 + i]; al[i] = arow[ty * 4 + i]; }
#pragma unroll
        for (int i = 0; i < 4; i++)
#pragma unroll
            for (int j = 0; j < 4; j++) {
                float p = __expf(s[i][j] - mr[i]);
                Ss[(ty * 4 + i) * FST + tx * 4 + j] = p;
                acc[i][j] *= al[i];
            }
        __syncthreads();

        {
            int r = tid >> 2, p = tid & 3;
            float sm_ = 0.0f;
            const float* sr = Ss + r * FST + p * 16;
#pragma unroll
            for (int u = 0; u < 16; u++) sm_ += sr[u];
            red[r * 4 + p] = sm_;
        }
        __syncthreads();
        if (tid < 64) {
            lrow[tid] = lrow[tid] * arow[tid] +
                        (red[tid * 4] + red[tid * 4 + 1] + red[tid * 4 + 2] + red[tid * 4 + 3]);
        }

        const float* pb = Ss + (ty * 4) * FST;
#pragma unroll 4
        for (int k = 0; k < 64; k++) {
            float pr[4], vr[4];
#pragma unroll
            for (int i = 0; i < 4; i++) pr[i] = pb[i * FST + k];
#pragma unroll
            for (int j = 0; j < 4; j++) vr[j] = Vs[k * FST + tx * 4 + j];
#pragma unroll
            for (int i = 0; i < 4; i++)
#pragma unroll
                for (int j = 0; j < 4; j++) acc[i][j] += pr[i] * vr[j];
        }
        __syncthreads();
    }

    float linv[4];
#pragma unroll
    for (int i = 0; i < 4; i++) linv[i] = 1.0f / lrow[ty * 4 + i];
#pragma unroll
    for (int i = 0; i < 4; i++) {
        float v[4];
#pragma unroll
        for (int j = 0; j < 4; j++) v[j] = acc[i][j] * linv[i];
        size_t off = ((size_t)(b * NTOK + q0 + ty * 4 + i)) * DMODEL + h * 64 + tx * 4;
        __nv_bfloat16 h0 = __float2bfloat16_rn(v[0]), h1 = __float2bfloat16_rn(v[1]);
        __nv_bfloat16 h2 = __float2bfloat16_rn(v[2]), h3 = __float2bfloat16_rn(v[3]);
        *(__nv_bfloat162*)(ohi + off)     = __halves2bfloat162(h0, h1);
        *(__nv_bfloat162*)(ohi + off + 2) = __halves2bfloat162(h2, h3);
        *(__nv_bfloat162*)(olo + off) = __halves2bfloat162(
            __float2bfloat16_rn(v[0] - __bfloat162float(h0)),
            __float2bfloat16_rn(v[1] - __bfloat162float(h1)));
        *(__nv_bfloat162*)(olo + off + 2) = __halves2bfloat162(
            __float2bfloat16_rn(v[2] - __bfloat162float(h2)),
            __float2bfloat16_rn(v[3] - __bfloat162float(h3)));
    }
}

// ---------------- host orchestration ----------------------------------------
extern "C" void kernel_launch(void* const* d_in, const int* in_sizes, int n_in,
                              void* d_out, int out_size) {
    const float* x         = (const float*)d_in[0];
    const float* attn_ln_w = (const float*)d_in[1];
    const float* attn_ln_b = (const float*)d_in[2];
    const float* w_qkv     = (const float*)d_in[3];
    const float* w_out     = (const float*)d_in[4];
    const float* b_out     = (const float*)d_in[5];
    const float* ffn_ln_w  = (const float*)d_in[6];
    const float* ffn_ln_b  = (const float*)d_in[7];
    const float* w1        = (const float*)d_in[8];
    const float* b1        = (const float*)d_in[9];
    const float* w2        = (const float*)d_in[10];
    const float* b2        = (const float*)d_in[11];
    const float* ln_w      = (const float*)d_in[12];
    const float* ln_b      = (const float*)d_in[13];
    float* out = (float*)d_out;

    float *t, *h, *qkv;
    __nv_bfloat16 *hhi, *hlo, *ohi, *olo, *f1hi, *f1lo;
    __nv_bfloat16 *wqkvhi, *wqkvlo, *wouthi, *woutlo, *w1hi, *w1lo, *w2hi, *w2lo;
    cudaGetSymbolAddress((void**)&t,    g_t);
    cudaGetSymbolAddress((void**)&h,    g_h);
    cudaGetSymbolAddress((void**)&qkv,  g_qkv);
    cudaGetSymbolAddress((void**)&hhi,  g_hhi);
    cudaGetSymbolAddress((void**)&hlo,  g_hlo);
    cudaGetSymbolAddress((void**)&ohi,  g_ohi);
    cudaGetSymbolAddress((void**)&olo,  g_olo);
    cudaGetSymbolAddress((void**)&f1hi, g_f1hi);
    cudaGetSymbolAddress((void**)&f1lo, g_f1lo);
    cudaGetSymbolAddress((void**)&wqkvhi, g_wqkvhi);
    cudaGetSymbolAddress((void**)&wqkvlo, g_wqkvlo);
    cudaGetSymbolAddress((void**)&wouthi, g_wouthi);
    cudaGetSymbolAddress((void**)&woutlo, g_woutlo);
    cudaGetSymbolAddress((void**)&w1hi, g_w1hi);
    cudaGetSymbolAddress((void**)&w1lo, g_w1lo);
    cudaGetSymbolAddress((void**)&w2hi, g_w2hi);
    cudaGetSymbolAddress((void**)&w2lo, g_w2lo);

    cudaFuncSetAttribute(attn_kernel, cudaFuncAttributeMaxDynamicSharedMemorySize, 68352);
    cudaFuncSetAttribute(gemm_tc<0>, cudaFuncAttributeMaxDynamicSharedMemorySize, 81920);
    cudaFuncSetAttribute(gemm_tc<1>, cudaFuncAttributeMaxDynamicSharedMemorySize, 81920);
    cudaFuncSetAttribute(gemm_tc<2>, cudaFuncAttributeMaxDynamicSharedMemorySize, 81920);

    {
        int n;
        n = DEPTH * 3 * DMODEL * DMODEL;
        split_w<<<(n + 255) / 256, 256>>>(w_qkv, wqkvhi, wqkvlo, n);
        n = DEPTH * DMODEL * DMODEL;
        split_w<<<(n + 255) / 256, 256>>>(w_out, wouthi, woutlo, n);
        n = 2 * DMODEL * DMODEL;
        split_w<<<(n + 255) / 256, 256>>>(w1, w1hi, w1lo, n);
        n = 2 * DMODEL * DMODEL;
        split_w<<<(n + 255) / 256, 256>>>(w2, w2hi, w2lo, n);
    }

    dim3 tb(32, 8);
    embed_kernel<<<dim3(32, 16, 8), tb>>>(x, t);

    for (int l = 0; l < DEPTH; l++) {
        ln_kernel<true><<<1024, 256>>>(t, attn_ln_w + l * DMODEL, attn_ln_b + l * DMODEL,
                                       nullptr, hhi, hlo);
        gemm_tc<0><<<dim3(12, 64), 256, 81920>>>(
            hhi, hlo, wqkvhi + (size_t)l * 3 * DMODEL * DMODEL,
            wqkvlo + (size_t)l * 3 * DMODEL * DMODEL,
            nullptr, nullptr, qkv, nullptr, nullptr, 3 * DMODEL, DMODEL);
        attn_kernel<<<dim3(16, 64), 256, 68352>>>(qkv, ohi, olo);
        gemm_tc<1><<<dim3(4, 64), 256, 81920>>>(
            ohi, olo, wouthi + (size_t)l * DMODEL * DMODEL,
            woutlo + (size_t)l * DMODEL * DMODEL,
            b_out + l * DMODEL, t, t, nullptr, nullptr, DMODEL, DMODEL);
        ln_kernel<true><<<1024, 256>>>(t, ffn_ln_w, ffn_ln_b, nullptr, hhi, hlo);
        gemm_tc<2><<<dim3(8, 64), 256, 81920>>>(
            hhi, hlo, w1hi, w1lo, b1, nullptr, nullptr, f1hi, f1lo, 2 * DMODEL, DMODEL);
        gemm_tc<1><<<dim3(4, 64), 256, 81920>>>(
            f1hi, f1lo, w2hi, w2lo, b2, t, t, nullptr, nullptr, DMODEL, 2 * DMODEL);
    }

    ln_kernel<false><<<1024, 256>>>(t, ln_w, ln_b, h, nullptr, nullptr);
    unembed_kernel<<<dim3(32, 16, 8), tb>>>(h, out);
}

// round 4
// speedup vs baseline: 2.9568x; 1.6964x over previous
#include <cuda_runtime.h>
#include <cuda_bf16.h>
#include <math.h>
#include <stdint.h>

#define NTOK 1024
#define DMODEL 512
#define BATCH 8
#define DEPTH 4
#define ROWS (BATCH*NTOK)   // 8192

// ---------------- scratch (static device globals; no runtime allocation) ----
__device__ float g_t  [ROWS*DMODEL];
__device__ float g_h  [ROWS*DMODEL];
__device__ float g_qkv[ROWS*3*DMODEL];
__device__ __nv_bfloat16 g_hhi[ROWS*DMODEL], g_hlo[ROWS*DMODEL];
__device__ __nv_bfloat16 g_ohi[ROWS*DMODEL], g_olo[ROWS*DMODEL];
__device__ __nv_bfloat16 g_f1hi[ROWS*2*DMODEL], g_f1lo[ROWS*2*DMODEL];
__device__ __nv_bfloat16 g_wqkvhi[DEPTH*3*DMODEL*DMODEL], g_wqkvlo[DEPTH*3*DMODEL*DMODEL];
__device__ __nv_bfloat16 g_wouthi[DEPTH*DMODEL*DMODEL],   g_woutlo[DEPTH*DMODEL*DMODEL];
__device__ __nv_bfloat16 g_w1hi[2*DMODEL*DMODEL],         g_w1lo[2*DMODEL*DMODEL];
__device__ __nv_bfloat16 g_w2hi[2*DMODEL*DMODEL],         g_w2lo[2*DMODEL*DMODEL];

// ---------------- bf16 hi/lo split of an fp32 tensor ------------------------
__global__ void split_w(const float* __restrict__ w, __nv_bfloat16* __restrict__ hi,
                        __nv_bfloat16* __restrict__ lo, int n) {
    int i = blockIdx.x * 256 + threadIdx.x;
    if (i < n) {
        float v = w[i];
        __nv_bfloat16 h = __float2bfloat16_rn(v);
        hi[i] = h;
        lo[i] = __float2bfloat16_rn(v - __bfloat162float(h));
    }
}

// ---------------- embed: transpose [b,c,n] -> [b,n,c] and add sinusoid PE ---
__global__ void embed_kernel(const float* __restrict__ x, float* __restrict__ t) {
    __shared__ float tile[32][33];
    int n0 = blockIdx.x * 32, c0 = blockIdx.y * 32, b = blockIdx.z;
    int tx = threadIdx.x, ty = threadIdx.y;
#pragma unroll
    for (int i = 0; i < 4; i++) {
        int c = c0 + ty + i * 8;
        tile[ty + i * 8][tx] = x[((size_t)b * DMODEL + c) * NTOK + n0 + tx];
    }
    __syncthreads();
#pragma unroll
    for (int i = 0; i < 4; i++) {
        int n = n0 + ty + i * 8;
        int c = c0 + tx;
        float e = (float)(c & ~1) * (1.0f / DMODEL);
        float ang = (float)n * expf(-9.210340371976184f * e);
        float pe = (c & 1) ? cosf(ang) : sinf(ang);
        t[((size_t)b * NTOK + n) * DMODEL + c] = tile[tx][ty + i * 8] + pe;
    }
}

// ---------------- unembed -----------------------------------------------------
__global__ void unembed_kernel(const float* __restrict__ h, float* __restrict__ out) {
    __shared__ float tile[32][33];
    int n0 = blockIdx.x * 32, c0 = blockIdx.y * 32, b = blockIdx.z;
    int tx = threadIdx.x, ty = threadIdx.y;
#pragma unroll
    for (int i = 0; i < 4; i++) {
        int n = n0 + ty + i * 8;
        tile[ty + i * 8][tx] = h[((size_t)b * NTOK + n) * DMODEL + c0 + tx];
    }
    __syncthreads();
#pragma unroll
    for (int i = 0; i < 4; i++) {
        int c = c0 + ty + i * 8;
        out[((size_t)b * DMODEL + c) * NTOK + n0 + tx] = tile[tx][ty + i * 8];
    }
}

// ---------------- layernorm: one warp per row; SPLIT -> bf16 hi/lo planes ----
template <bool SPLIT>
__global__ void ln_kernel(const float* __restrict__ x, const float* __restrict__ w,
                          const float* __restrict__ bias, float* __restrict__ y,
                          __nv_bfloat16* __restrict__ yhi, __nv_bfloat16* __restrict__ ylo) {
    int gw = (blockIdx.x * blockDim.x + threadIdx.x) >> 5;
    int lane = threadIdx.x & 31;
    if (gw >= ROWS) return;
    const float4* xr = (const float4*)(x + (size_t)gw * DMODEL);
    float4 v[4];
    float s = 0.0f;
#pragma unroll
    for (int u = 0; u < 4; u++) {
        v[u] = xr[u * 32 + lane];
        s += v[u].x + v[u].y + v[u].z + v[u].w;
    }
#pragma unroll
    for (int o = 16; o > 0; o >>= 1) s += __shfl_xor_sync(0xffffffffu, s, o);
    float mu = s * (1.0f / DMODEL);
    float q = 0.0f;
#pragma unroll
    for (int u = 0; u < 4; u++) {
        v[u].x -= mu; v[u].y -= mu; v[u].z -= mu; v[u].w -= mu;
        q += v[u].x * v[u].x + v[u].y * v[u].y + v[u].z * v[u].z + v[u].w * v[u].w;
    }
#pragma unroll
    for (int o = 16; o > 0; o >>= 1) q += __shfl_xor_sync(0xffffffffu, q, o);
    float rstd = rsqrtf(q * (1.0f / DMODEL) + 1e-5f);
    const float4* wr = (const float4*)w;
    const float4* br = (const float4*)bias;
#pragma unroll
    for (int u = 0; u < 4; u++) {
        float4 W = wr[u * 32 + lane], B = br[u * 32 + lane], o4;
        o4.x = v[u].x * rstd * W.x + B.x;
        o4.y = v[u].y * rstd * W.y + B.y;
        o4.z = v[u].z * rstd * W.z + B.z;
        o4.w = v[u].w * rstd * W.w + B.w;
        if (SPLIT) {
            size_t off = (size_t)gw * DMODEL + (u * 32 + lane) * 4;
            __nv_bfloat16 h0 = __float2bfloat16_rn(o4.x), h1 = __float2bfloat16_rn(o4.y);
            __nv_bfloat16 h2 = __float2bfloat16_rn(o4.z), h3 = __float2bfloat16_rn(o4.w);
            *(__nv_bfloat162*)(yhi + off)     = __halves2bfloat162(h0, h1);
            *(__nv_bfloat162*)(yhi + off + 2) = __halves2bfloat162(h2, h3);
            *(__nv_bfloat162*)(ylo + off) = __halves2bfloat162(
                __float2bfloat16_rn(o4.x - __bfloat162float(h0)),
                __float2bfloat16_rn(o4.y - __bfloat162float(h1)));
            *(__nv_bfloat162*)(ylo + off + 2) = __halves2bfloat162(
                __float2bfloat16_rn(o4.z - __bfloat162float(h2)),
                __float2bfloat16_rn(o4.w - __bfloat162float(h3)));
        } else {
            ((float4*)(y + (size_t)gw * DMODEL))[u * 32 + lane] = o4;
        }
    }
}

// ---------------- common mma/ldmatrix helpers --------------------------------
__device__ __forceinline__ void ldsm4(uint32_t& r0, uint32_t& r1, uint32_t& r2, uint32_t& r3,
                                      uint32_t addr) {
    asm volatile("ldmatrix.sync.aligned.m8n8.x4.shared.b16 {%0,%1,%2,%3},[%4];"
                 : "=r"(r0), "=r"(r1), "=r"(r2), "=r"(r3) : "r"(addr));
}
__device__ __forceinline__ void mma_bf16(float* c, const uint32_t* a, const uint32_t* b) {
    asm volatile(
        "mma.sync.aligned.m16n8k16.row.col.f32.bf16.bf16.f32 "
        "{%0,%1,%2,%3},{%4,%5,%6,%7},{%8,%9},{%0,%1,%2,%3};"
        : "+f"(c[0]), "+f"(c[1]), "+f"(c[2]), "+f"(c[3])
        : "r"(a[0]), "r"(a[1]), "r"(a[2]), "r"(a[3]), "r"(b[0]), "r"(b[1]));
}
__device__ __forceinline__ void cpasync16(uint32_t saddr, const void* g) {
    asm volatile("cp.async.cg.shared.global [%0],[%1],16;" :: "r"(saddr), "l"(g));
}
__device__ __forceinline__ float gelu_exact(float v) {
    return 0.5f * v * (1.0f + erff(v * 0.7071067811865476f));
}

// ---------------- tensor-core GEMM (bf16x3): C = A * W^T --------------------
#define BM 128
#define BN 128
#define BK 32
#define KST 40
#define PLANE (128*KST)
#define STAGE (4*PLANE)

template <int MODE>
__global__ void __launch_bounds__(256) gemm_tc(
    const __nv_bfloat16* __restrict__ Ahi, const __nv_bfloat16* __restrict__ Alo,
    const __nv_bfloat16* __restrict__ Bhi, const __nv_bfloat16* __restrict__ Blo,
    const float* __restrict__ bias, const float* __restrict__ resid,
    float* __restrict__ C, __nv_bfloat16* __restrict__ Chi, __nv_bfloat16* __restrict__ Clo,
    int N, int K) {
    extern __shared__ __nv_bfloat16 smbuf[];
    const int tid = threadIdx.x;
    const int lane = tid & 31, w = tid >> 5;
    const int wr = w >> 2, wc = w & 3;
    const int m0 = blockIdx.y * BM, n0 = blockIdx.x * BN;
    const uint32_t smbase = (uint32_t)__cvta_generic_to_shared(smbuf);

    const int r0i = tid >> 2;
    const int c0i = (tid & 3) * 8;

    auto load_stage = [&](int it, int buf) {
        const int k0 = it * BK;
        size_t aoff0 = (size_t)(m0 + r0i) * K + k0 + c0i;
        size_t aoff1 = aoff0 + (size_t)64 * K;
        size_t boff0 = (size_t)(n0 + r0i) * K + k0 + c0i;
        size_t boff1 = boff0 + (size_t)64 * K;
        uint32_t s0 = smbase + (uint32_t)(buf * STAGE + r0i * KST + c0i) * 2;
        uint32_t s1 = smbase + (uint32_t)(buf * STAGE + (r0i + 64) * KST + c0i) * 2;
        cpasync16(s0,                 Ahi + aoff0);
        cpasync16(s1,                 Ahi + aoff1);
        cpasync16(s0 + PLANE * 2,     Alo + aoff0);
        cpasync16(s1 + PLANE * 2,     Alo + aoff1);
        cpasync16(s0 + 2 * PLANE * 2, Bhi + boff0);
        cpasync16(s1 + 2 * PLANE * 2, Bhi + boff1);
        cpasync16(s0 + 3 * PLANE * 2, Blo + boff0);
        cpasync16(s1 + 3 * PLANE * 2, Blo + boff1);
    };

    float acc[4][4][4] = {};

    const int arow = wr * 64 + (lane & 15);
    const int acol = (lane >> 4) * 8;
    const int bn   = wc * 32 + ((lane >> 4) << 3) + (lane & 7);
    const int bk   = ((lane >> 3) & 1) << 3;

    const int niter = K / BK;
    load_stage(0, 0);
    asm volatile("cp.async.commit_group;");
    for (int it = 0; it < niter; ++it) {
        if (it + 1 < niter) {
            load_stage(it + 1, (it + 1) & 1);
            asm volatile("cp.async.commit_group;");
            asm volatile("cp.async.wait_group 1;");
        } else {
            asm volatile("cp.async.wait_group 0;");
        }
        __syncthreads();
        const uint32_t base = smbase + (uint32_t)(it & 1) * STAGE * 2;
#pragma unroll
        for (int kk = 0; kk < BK; kk += 16) {
            uint32_t ahi[4][4], alo[4][4], bhi[4][2], blo[4][2];
#pragma unroll
            for (int mt = 0; mt < 4; ++mt) {
                uint32_t ai = base + (uint32_t)((arow + mt * 16) * KST + kk + acol) * 2;
                ldsm4(ahi[mt][0], ahi[mt][1], ahi[mt][2], ahi[mt][3], ai);
                ldsm4(alo[mt][0], alo[mt][1], alo[mt][2], alo[mt][3], ai + PLANE * 2);
            }
#pragma unroll
            for (int g = 0; g < 2; ++g) {
                uint32_t bi = base + 2 * PLANE * 2 +
                              (uint32_t)((bn + g * 16) * KST + kk + bk) * 2;
                ldsm4(bhi[2 * g][0], bhi[2 * g][1], bhi[2 * g + 1][0], bhi[2 * g + 1][1], bi);
                ldsm4(blo[2 * g][0], blo[2 * g][1], blo[2 * g + 1][0], blo[2 * g + 1][1],
                      bi + PLANE * 2);
            }
#pragma unroll
            for (int mt = 0; mt < 4; ++mt)
#pragma unroll
                for (int nt = 0; nt < 4; ++nt) {
                    mma_bf16(acc[mt][nt], ahi[mt], bhi[nt]);
                    mma_bf16(acc[mt][nt], ahi[mt], blo[nt]);
                    mma_bf16(acc[mt][nt], alo[mt], bhi[nt]);
                }
        }
        __syncthreads();
    }

    const int erow = m0 + wr * 64 + (lane >> 2);
    const int ecol = n0 + wc * 32 + (lane & 3) * 2;
#pragma unroll
    for (int mt = 0; mt < 4; ++mt)
#pragma unroll
        for (int nt = 0; nt < 4; ++nt) {
            int c = ecol + nt * 8;
#pragma unroll
            for (int half = 0; half < 2; ++half) {
                int rr = erow + mt * 16 + half * 8;
                float v0 = acc[mt][nt][half * 2 + 0];
                float v1 = acc[mt][nt][half * 2 + 1];
                size_t off = (size_t)rr * N + c;
                if (MODE == 0) {
                    *(float2*)(C + off) = make_float2(v0, v1);
                } else if (MODE == 1) {
                    float2 rv = *(const float2*)(resid + off);
                    v0 += bias[c] + rv.x;
                    v1 += bias[c + 1] + rv.y;
                    *(float2*)(C + off) = make_float2(v0, v1);
                } else {
                    v0 = gelu_exact(v0 + bias[c]);
                    v1 = gelu_exact(v1 + bias[c + 1]);
                    __nv_bfloat16 h0 = __float2bfloat16_rn(v0);
                    __nv_bfloat16 h1 = __float2bfloat16_rn(v1);
                    *(__nv_bfloat162*)(Chi + off) = __halves2bfloat162(h0, h1);
                    *(__nv_bfloat162*)(Clo + off) = __halves2bfloat162(
                        __float2bfloat16_rn(v0 - __bfloat162float(h0)),
                        __float2bfloat16_rn(v1 - __bfloat162float(h1)));
                }
            }
        }
}

// ---------------- tensor-core flash attention (bf16x3) -----------------------
#define AST 72
#define QHI_E 0
#define QLO_E (128*AST)
#define KHI_E (2*128*AST)
#define KLO_E (KHI_E + 64*AST)
#define VHI_E (KLO_E + 64*AST)
#define VLO_E (VHI_E + 64*AST)
#define ATT_SMEM ((VLO_E + 64*AST)*2)   // 73728 bytes

__device__ __forceinline__ void split2(float a, float b, uint32_t& hi, uint32_t& lo) {
    __nv_bfloat16 ha = __float2bfloat16_rn(a), hb = __float2bfloat16_rn(b);
    __nv_bfloat162 hp = __halves2bfloat162(ha, hb);
    hi = *(uint32_t*)&hp;
    __nv_bfloat162 lp = __halves2bfloat162(
        __float2bfloat16_rn(a - __bfloat162float(ha)),
        __float2bfloat16_rn(b - __bfloat162float(hb)));
    lo = *(uint32_t*)&lp;
}

__global__ void __launch_bounds__(128) attn_tc(const float* __restrict__ qkv,
                                               __nv_bfloat16* __restrict__ ohi,
                                               __nv_bfloat16* __restrict__ olo) {
    extern __shared__ __nv_bfloat16 sb[];
    const uint32_t smb = (uint32_t)__cvta_generic_to_shared(sb);
    const int tid = threadIdx.x, lane = tid & 31, wid = tid >> 5;
    const int q0 = blockIdx.x * 128;
    const int b = blockIdx.y >> 3, h = blockIdx.y & 7;

    // Q fill (prescaled by 1/8 * log2(e)), split hi/lo
    {
        const float qs = 0.18033688011112042f;
        const float* src = qkv + ((size_t)(b * NTOK + q0 + tid)) * 1536 + h * 64;
#pragma unroll
        for (int c = 0; c < 64; c += 4) {
            float4 v = *(const float4*)(src + c);
            uint32_t h0, l0, h1, l1;
            split2(v.x * qs, v.y * qs, h0, l0);
            split2(v.z * qs, v.w * qs, h1, l1);
            int e = tid * AST + c;
            *(uint32_t*)(sb + QHI_E + e)     = h0;
            *(uint32_t*)(sb + QHI_E + e + 2) = h1;
            *(uint32_t*)(sb + QLO_E + e)     = l0;
            *(uint32_t*)(sb + QLO_E + e + 2) = l1;
        }
    }

    float oacc[2][8][4] = {};
    float mst[2][2] = {{-1e30f, -1e30f}, {-1e30f, -1e30f}};
    float lst[2][2] = {};

    for (int kt = 0; kt < 16; kt++) {
        if (kt) __syncthreads();
        {
            int r = tid & 63;
            const float* src = qkv + ((size_t)(b * NTOK + kt * 64 + r)) * 1536 + h * 64 +
                               (tid < 64 ? 512 : 1024);
            if (tid < 64) {            // K rows, row-major [kv][dh]
#pragma unroll
                for (int c = 0; c < 64; c += 4) {
                    float4 v = *(const float4*)(src + c);
                    uint32_t h0, l0, h1, l1;
                    split2(v.x, v.y, h0, l0);
                    split2(v.z, v.w, h1, l1);
                    int e = r * AST + c;
                    *(uint32_t*)(sb + KHI_E + e)     = h0;
                    *(uint32_t*)(sb + KHI_E + e + 2) = h1;
                    *(uint32_t*)(sb + KLO_E + e)     = l0;
                    *(uint32_t*)(sb + KLO_E + e + 2) = l1;
                }
            } else {                   // V rows, transposed to [dh][kv]
#pragma unroll
                for (int c = 0; c < 64; c += 4) {
                    float4 v = *(const float4*)(src + c);
                    float f[4] = {v.x, v.y, v.z, v.w};
#pragma unroll
                    for (int i = 0; i < 4; i++) {
                        __nv_bfloat16 hh = __float2bfloat16_rn(f[i]);
                        sb[VHI_E + (c + i) * AST + r] = hh;
                        sb[VLO_E + (c + i) * AST + r] =
                            __float2bfloat16_rn(f[i] - __bfloat162float(hh));
                    }
                }
            }
        }
        __syncthreads();

#pragma unroll
        for (int mt = 0; mt < 2; mt++) {
            // ---- S = Q K^T ----
            float s[8][4];
#pragma unroll
            for (int nt = 0; nt < 8; nt++)
#pragma unroll
                for (int c = 0; c < 4; c++) s[nt][c] = 0.0f;

#pragma unroll
            for (int k8 = 0; k8 < 4; k8++) {
                uint32_t qh[4], ql[4];
                int ar = wid * 32 + mt * 16 + (lane & 15);
                uint32_t qa = smb + (uint32_t)(ar * AST + k8 * 16 + ((lane >> 4) << 3)) * 2;
                ldsm4(qh[0], qh[1], qh[2], qh[3], qa);
                ldsm4(ql[0], ql[1], ql[2], ql[3], qa + QLO_E * 2);
#pragma unroll
                for (int g = 0; g < 4; g++) {
                    int br = g * 16 + ((lane >> 4) << 3) + (lane & 7);
                    int bc = k8 * 16 + (((lane >> 3) & 1) << 3);
                    uint32_t ka = smb + (uint32_t)(KHI_E + br * AST + bc) * 2;
                    uint32_t bh[4], bl[4];
                    ldsm4(bh[0], bh[1], bh[2], bh[3], ka);
                    ldsm4(bl[0], bl[1], bl[2], bl[3], ka + (KLO_E - KHI_E) * 2);
                    mma_bf16(s[2 * g],     qh, bh);
                    mma_bf16(s[2 * g],     qh, bl);
                    mma_bf16(s[2 * g],     ql, bh);
                    mma_bf16(s[2 * g + 1], qh, bh + 2);
                    mma_bf16(s[2 * g + 1], qh, bl + 2);
                    mma_bf16(s[2 * g + 1], ql, bh + 2);
                }
            }

            // ---- online softmax (logits already in log2 units) ----
            float m0 = -1e30f, m1 = -1e30f;
#pragma unroll
            for (int nt = 0; nt < 8; nt++) {
                m0 = fmaxf(m0, fmaxf(s[nt][0], s[nt][1]));
                m1 = fmaxf(m1, fmaxf(s[nt][2], s[nt][3]));
            }
            m0 = fmaxf(m0, __shfl_xor_sync(0xffffffffu, m0, 1));
            m0 = fmaxf(m0, __shfl_xor_sync(0xffffffffu, m0, 2));
            m1 = fmaxf(m1, __shfl_xor_sync(0xffffffffu, m1, 1));
            m1 = fmaxf(m1, __shfl_xor_sync(0xffffffffu, m1, 2));
            float mn0 = fmaxf(mst[mt][0], m0), mn1 = fmaxf(mst[mt][1], m1);
            float a0 = exp2f(mst[mt][0] - mn0), a1 = exp2f(mst[mt][1] - mn1);
            mst[mt][0] = mn0; mst[mt][1] = mn1;
            float rs0 = 0.0f, rs1 = 0.0f;
#pragma unroll
            for (int nt = 0; nt < 8; nt++) {
                s[nt][0] = exp2f(s[nt][0] - mn0); rs0 += s[nt][0];
                s[nt][1] = exp2f(s[nt][1] - mn0); rs0 += s[nt][1];
                s[nt][2] = exp2f(s[nt][2] - mn1); rs1 += s[nt][2];
                s[nt][3] = exp2f(s[nt][3] - mn1); rs1 += s[nt][3];
            }
            rs0 += __shfl_xor_sync(0xffffffffu, rs0, 1);
            rs0 += __shfl_xor_sync(0xffffffffu, rs0, 2);
            rs1 += __shfl_xor_sync(0xffffffffu, rs1, 1);
            rs1 += __shfl_xor_sync(0xffffffffu, rs1, 2);
            lst[mt][0] = lst[mt][0] * a0 + rs0;
            lst[mt][1] = lst[mt][1] * a1 + rs1;
#pragma unroll
            for (int nt = 0; nt < 8; nt++) {
                oacc[mt][nt][0] *= a0; oacc[mt][nt][1] *= a0;
                oacc[mt][nt][2] *= a1; oacc[mt][nt][3] *= a1;
            }

            // ---- pack P into A-fragments (S c-frag == P a-frag layout) ----
            uint32_t phi[4][4], plo[4][4];
#pragma unroll
            for (int j = 0; j < 4; j++) {
                split2(s[2 * j][0],     s[2 * j][1],     phi[j][0], plo[j][0]);
                split2(s[2 * j][2],     s[2 * j][3],     phi[j][1], plo[j][1]);
                split2(s[2 * j + 1][0], s[2 * j + 1][1], phi[j][2], plo[j][2]);
                split2(s[2 * j + 1][2], s[2 * j + 1][3], phi[j][3], plo[j][3]);
            }

            // ---- O += P V ----
#pragma unroll
            for (int j = 0; j < 4; j++) {
#pragma unroll
                for (int g = 0; g < 4; g++) {
                    int br = g * 16 + ((lane >> 4) << 3) + (lane & 7);   // dh
                    int bc = j * 16 + (((lane >> 3) & 1) << 3);          // kv
                    uint32_t va = smb + (uint32_t)(VHI_E + br * AST + bc) * 2;
                    uint32_t vh[4], vl[4];
                    ldsm4(vh[0], vh[1], vh[2], vh[3], va);
                    ldsm4(vl[0], vl[1], vl[2], vl[3], va + (VLO_E - VHI_E) * 2);
                    mma_bf16(oacc[mt][2 * g],     phi[j], vh);
                    mma_bf16(oacc[mt][2 * g],     plo[j], vh);
                    mma_bf16(oacc[mt][2 * g],     phi[j], vl);
                    mma_bf16(oacc[mt][2 * g + 1], phi[j], vh + 2);
                    mma_bf16(oacc[mt][2 * g + 1], plo[j], vh + 2);
                    mma_bf16(oacc[mt][2 * g + 1], phi[j], vl + 2);
                }
            }
        }
    }

    // ---- epilogue: o / l, split to bf16 hi/lo ----
#pragma unroll
    for (int mt = 0; mt < 2; mt++) {
        float li0 = 1.0f / lst[mt][0], li1 = 1.0f / lst[mt][1];
#pragma unroll
        for (int half = 0; half < 2; half++) {
            int row = q0 + wid * 32 + mt * 16 + half * 8 + (lane >> 2);
            float li = half ? li1 : li0;
            size_t base = (size_t)(b * NTOK + row) * DMODEL + h * 64 + (lane & 3) * 2;
#pragma unroll
            for (int nt = 0; nt < 8; nt++) {
                float v0 = oacc[mt][nt][half * 2 + 0] * li;
                float v1 = oacc[mt][nt][half * 2 + 1] * li;
                uint32_t hp, lp;
                split2(v0, v1, hp, lp);
                *(uint32_t*)(ohi + base + nt * 8) = hp;
                *(uint32_t*)(olo + base + nt * 8) = lp;
            }
        }
    }
}

// ---------------- host orchestration ----------------------------------------
extern "C" void kernel_launch(void* const* d_in, const int* in_sizes, int n_in,
                              void* d_out, int out_size) {
    const float* x         = (const float*)d_in[0];
    const float* attn_ln_w = (const float*)d_in[1];
    const float* attn_ln_b = (const float*)d_in[2];
    const float* w_qkv     = (const float*)d_in[3];
    const float* w_out     = (const float*)d_in[4];
    const float* b_out     = (const float*)d_in[5];
    const float* ffn_ln_w  = (const float*)d_in[6];
    const float* ffn_ln_b  = (const float*)d_in[7];
    const float* w1        = (const float*)d_in[8];
    const float* b1        = (const float*)d_in[9];
    const float* w2        = (const float*)d_in[10];
    const float* b2        = (const float*)d_in[11];
    const float* ln_w      = (const float*)d_in[12];
    const float* ln_b      = (const float*)d_in[13];
    float* out = (float*)d_out;

    float *t, *h, *qkv;
    __nv_bfloat16 *hhi, *hlo, *ohi, *olo, *f1hi, *f1lo;
    __nv_bfloat16 *wqkvhi, *wqkvlo, *wouthi, *woutlo, *w1hi, *w1lo, *w2hi, *w2lo;
    cudaGetSymbolAddress((void**)&t,    g_t);
    cudaGetSymbolAddress((void**)&h,    g_h);
    cudaGetSymbolAddress((void**)&qkv,  g_qkv);
    cudaGetSymbolAddress((void**)&hhi,  g_hhi);
    cudaGetSymbolAddress((void**)&hlo,  g_hlo);
    cudaGetSymbolAddress((void**)&ohi,  g_ohi);
    cudaGetSymbolAddress((void**)&olo,  g_olo);
    cudaGetSymbolAddress((void**)&f1hi, g_f1hi);
    cudaGetSymbolAddress((void**)&f1lo, g_f1lo);
    cudaGetSymbolAddress((void**)&wqkvhi, g_wqkvhi);
    cudaGetSymbolAddress((void**)&wqkvlo, g_wqkvlo);
    cudaGetSymbolAddress((void**)&wouthi, g_wouthi);
    cudaGetSymbolAddress((void**)&woutlo, g_woutlo);
    cudaGetSymbolAddress((void**)&w1hi, g_w1hi);
    cudaGetSymbolAddress((void**)&w1lo, g_w1lo);
    cudaGetSymbolAddress((void**)&w2hi, g_w2hi);
    cudaGetSymbolAddress((void**)&w2lo, g_w2lo);

    cudaFuncSetAttribute(attn_tc, cudaFuncAttributeMaxDynamicSharedMemorySize, ATT_SMEM);
    cudaFuncSetAttribute(gemm_tc<0>, cudaFuncAttributeMaxDynamicSharedMemorySize, 81920);
    cudaFuncSetAttribute(gemm_tc<1>, cudaFuncAttributeMaxDynamicSharedMemorySize, 81920);
    cudaFuncSetAttribute(gemm_tc<2>, cudaFuncAttributeMaxDynamicSharedMemorySize, 81920);

    {
        int n;
        n = DEPTH * 3 * DMODEL * DMODEL;
        split_w<<<(n + 255) / 256, 256>>>(w_qkv, wqkvhi, wqkvlo, n);
        n = DEPTH * DMODEL * DMODEL;
        split_w<<<(n + 255) / 256, 256>>>(w_out, wouthi, woutlo, n);
        n = 2 * DMODEL * DMODEL;
        split_w<<<(n + 255) / 256, 256>>>(w1, w1hi, w1lo, n);
        n = 2 * DMODEL * DMODEL;
        split_w<<<(n + 255) / 256, 256>>>(w2, w2hi, w2lo, n);
    }

    dim3 tb(32, 8);
    embed_kernel<<<dim3(32, 16, 8), tb>>>(x, t);

    for (int l = 0; l < DEPTH; l++) {
        ln_kernel<true><<<1024, 256>>>(t, attn_ln_w + l * DMODEL, attn_ln_b + l * DMODEL,
                                       nullptr, hhi, hlo);
        gemm_tc<0><<<dim3(12, 64), 256, 81920>>>(
            hhi, hlo, wqkvhi + (size_t)l * 3 * DMODEL * DMODEL,
            wqkvlo + (size_t)l * 3 * DMODEL * DMODEL,
            nullptr, nullptr, qkv, nullptr, nullptr, 3 * DMODEL, DMODEL);
        attn_tc<<<dim3(8, 64), 128, ATT_SMEM>>>(qkv, ohi, olo);
        gemm_tc<1><<<dim3(4, 64), 256, 81920>>>(
            ohi, olo, wouthi + (size_t)l * DMODEL * DMODEL,
            woutlo + (size_t)l * DMODEL * DMODEL,
            b_out + l * DMODEL, t, t, nullptr, nullptr, DMODEL, DMODEL);
        ln_kernel<true><<<1024, 256>>>(t, ffn_ln_w, ffn_ln_b, nullptr, hhi, hlo);
        gemm_tc<2><<<dim3(8, 64), 256, 81920>>>(
            hhi, hlo, w1hi, w1lo, b1, nullptr, nullptr, f1hi, f1lo, 2 * DMODEL, DMODEL);
        gemm_tc<1><<<dim3(4, 64), 256, 81920>>>(
            f1hi, f1lo, w2hi, w2lo, b2, t, t, nullptr, nullptr, DMODEL, 2 * DMODEL);
    }

    ln_kernel<false><<<1024, 256>>>(t, ln_w, ln_b, h, nullptr, nullptr);
    unembed_kernel<<<dim3(32, 16, 8), tb>>>(h, out);
}

// round 6
// speedup vs baseline: 3.1587x; 1.0683x over previous
#include <cuda_runtime.h>
#include <cuda_bf16.h>
#include <math.h>
#include <stdint.h>

#define NTOK 1024
#define DMODEL 512
#define BATCH 8
#define DEPTH 4
#define ROWS (BATCH*NTOK)   // 8192

// ---------------- scratch (static device globals; no runtime allocation) ----
__device__ float g_t  [ROWS*DMODEL];
__device__ float g_h  [ROWS*DMODEL];
__device__ __nv_bfloat16 g_qkvhi[ROWS*3*DMODEL], g_qkvlo[ROWS*3*DMODEL];
__device__ __nv_bfloat16 g_hhi[ROWS*DMODEL], g_hlo[ROWS*DMODEL];
__device__ __nv_bfloat16 g_ohi[ROWS*DMODEL], g_olo[ROWS*DMODEL];
__device__ __nv_bfloat16 g_f1hi[ROWS*2*DMODEL], g_f1lo[ROWS*2*DMODEL];
__device__ __nv_bfloat16 g_wqkvhi[DEPTH*3*DMODEL*DMODEL], g_wqkvlo[DEPTH*3*DMODEL*DMODEL];
__device__ __nv_bfloat16 g_wouthi[DEPTH*DMODEL*DMODEL],   g_woutlo[DEPTH*DMODEL*DMODEL];
__device__ __nv_bfloat16 g_w1hi[2*DMODEL*DMODEL],         g_w1lo[2*DMODEL*DMODEL];
__device__ __nv_bfloat16 g_w2hi[2*DMODEL*DMODEL],         g_w2lo[2*DMODEL*DMODEL];

// ---------------- helpers ----------------------------------------------------
__device__ __forceinline__ void split2(float a, float b, uint32_t& hi, uint32_t& lo) {
    __nv_bfloat16 ha = __float2bfloat16_rn(a), hb = __float2bfloat16_rn(b);
    __nv_bfloat162 hp = __halves2bfloat162(ha, hb);
    hi = *(uint32_t*)&hp;
    __nv_bfloat162 lp = __halves2bfloat162(
        __float2bfloat16_rn(a - __bfloat162float(ha)),
        __float2bfloat16_rn(b - __bfloat162float(hb)));
    lo = *(uint32_t*)&lp;
}
__device__ __forceinline__ void ldsm4(uint32_t& r0, uint32_t& r1, uint32_t& r2, uint32_t& r3,
                                      uint32_t addr) {
    asm volatile("ldmatrix.sync.aligned.m8n8.x4.shared.b16 {%0,%1,%2,%3},[%4];"
                 : "=r"(r0), "=r"(r1), "=r"(r2), "=r"(r3) : "r"(addr));
}
__device__ __forceinline__ void ldsm4t(uint32_t& r0, uint32_t& r1, uint32_t& r2, uint32_t& r3,
                                       uint32_t addr) {
    asm volatile("ldmatrix.sync.aligned.m8n8.x4.trans.shared.b16 {%0,%1,%2,%3},[%4];"
                 : "=r"(r0), "=r"(r1), "=r"(r2), "=r"(r3) : "r"(addr));
}
__device__ __forceinline__ void mma_bf16(float* c, const uint32_t* a, const uint32_t* b) {
    asm volatile(
        "mma.sync.aligned.m16n8k16.row.col.f32.bf16.bf16.f32 "
        "{%0,%1,%2,%3},{%4,%5,%6,%7},{%8,%9},{%0,%1,%2,%3};"
        : "+f"(c[0]), "+f"(c[1]), "+f"(c[2]), "+f"(c[3])
        : "r"(a[0]), "r"(a[1]), "r"(a[2]), "r"(a[3]), "r"(b[0]), "r"(b[1]));
}
__device__ __forceinline__ void cpasync16(uint32_t saddr, const void* g) {
    asm volatile("cp.async.cg.shared.global [%0],[%1],16;" :: "r"(saddr), "l"(g));
}
__device__ __forceinline__ float gelu_exact(float v) {
    return 0.5f * v * (1.0f + erff(v * 0.7071067811865476f));
}

// ---------------- bf16 hi/lo split of an fp32 tensor ------------------------
__global__ void split_w(const float* __restrict__ w, __nv_bfloat16* __restrict__ hi,
                        __nv_bfloat16* __restrict__ lo, int n) {
    int i = blockIdx.x * 256 + threadIdx.x;
    if (i < n) {
        float v = w[i];
        __nv_bfloat16 h = __float2bfloat16_rn(v);
        hi[i] = h;
        lo[i] = __float2bfloat16_rn(v - __bfloat162float(h));
    }
}

// ---------------- embed: transpose [b,c,n] -> [b,n,c] and add sinusoid PE ---
__global__ void embed_kernel(const float* __restrict__ x, float* __restrict__ t) {
    __shared__ float tile[32][33];
    int n0 = blockIdx.x * 32, c0 = blockIdx.y * 32, b = blockIdx.z;
    int tx = threadIdx.x, ty = threadIdx.y;
#pragma unroll
    for (int i = 0; i < 4; i++) {
        int c = c0 + ty + i * 8;
        tile[ty + i * 8][tx] = x[((size_t)b * DMODEL + c) * NTOK + n0 + tx];
    }
    __syncthreads();
#pragma unroll
    for (int i = 0; i < 4; i++) {
        int n = n0 + ty + i * 8;
        int c = c0 + tx;
        float e = (float)(c & ~1) * (1.0f / DMODEL);
        float ang = (float)n * expf(-9.210340371976184f * e);
        float pe = (c & 1) ? cosf(ang) : sinf(ang);
        t[((size_t)b * NTOK + n) * DMODEL + c] = tile[tx][ty + i * 8] + pe;
    }
}

// ---------------- unembed -----------------------------------------------------
__global__ void unembed_kernel(const float* __restrict__ h, float* __restrict__ out) {
    __shared__ float tile[32][33];
    int n0 = blockIdx.x * 32, c0 = blockIdx.y * 32, b = blockIdx.z;
    int tx = threadIdx.x, ty = threadIdx.y;
#pragma unroll
    for (int i = 0; i < 4; i++) {
        int n = n0 + ty + i * 8;
        tile[ty + i * 8][tx] = h[((size_t)b * NTOK + n) * DMODEL + c0 + tx];
    }
    __syncthreads();
#pragma unroll
    for (int i = 0; i < 4; i++) {
        int c = c0 + ty + i * 8;
        out[((size_t)b * DMODEL + c) * NTOK + n0 + tx] = tile[tx][ty + i * 8];
    }
}

// ---------------- layernorm: one warp per row; SPLIT -> bf16 hi/lo planes ----
template <bool SPLIT>
__global__ void ln_kernel(const float* __restrict__ x, const float* __restrict__ w,
                          const float* __restrict__ bias, float* __restrict__ y,
                          __nv_bfloat16* __restrict__ yhi, __nv_bfloat16* __restrict__ ylo) {
    int gw = (blockIdx.x * blockDim.x + threadIdx.x) >> 5;
    int lane = threadIdx.x & 31;
    if (gw >= ROWS) return;
    const float4* xr = (const float4*)(x + (size_t)gw * DMODEL);
    float4 v[4];
    float s = 0.0f;
#pragma unroll
    for (int u = 0; u < 4; u++) {
        v[u] = xr[u * 32 + lane];
        s += v[u].x + v[u].y + v[u].z + v[u].w;
    }
#pragma unroll
    for (int o = 16; o > 0; o >>= 1) s += __shfl_xor_sync(0xffffffffu, s, o);
    float mu = s * (1.0f / DMODEL);
    float q = 0.0f;
#pragma unroll
    for (int u = 0; u < 4; u++) {
        v[u].x -= mu; v[u].y -= mu; v[u].z -= mu; v[u].w -= mu;
        q += v[u].x * v[u].x + v[u].y * v[u].y + v[u].z * v[u].z + v[u].w * v[u].w;
    }
#pragma unroll
    for (int o = 16; o > 0; o >>= 1) q += __shfl_xor_sync(0xffffffffu, q, o);
    float rstd = rsqrtf(q * (1.0f / DMODEL) + 1e-5f);
    const float4* wr = (const float4*)w;
    const float4* br = (const float4*)bias;
#pragma unroll
    for (int u = 0; u < 4; u++) {
        float4 W = wr[u * 32 + lane], B = br[u * 32 + lane], o4;
        o4.x = v[u].x * rstd * W.x + B.x;
        o4.y = v[u].y * rstd * W.y + B.y;
        o4.z = v[u].z * rstd * W.z + B.z;
        o4.w = v[u].w * rstd * W.w + B.w;
        if (SPLIT) {
            size_t off = (size_t)gw * DMODEL + (u * 32 + lane) * 4;
            uint32_t h0, l0, h1, l1;
            split2(o4.x, o4.y, h0, l0);
            split2(o4.z, o4.w, h1, l1);
            *(uint32_t*)(yhi + off)     = h0;
            *(uint32_t*)(yhi + off + 2) = h1;
            *(uint32_t*)(ylo + off)     = l0;
            *(uint32_t*)(ylo + off + 2) = l1;
        } else {
            ((float4*)(y + (size_t)gw * DMODEL))[u * 32 + lane] = o4;
        }
    }
}

// ---------------- tensor-core GEMM (bf16x3): C = A * W^T --------------------
#define BM 128
#define BN 128
#define BK 32
#define KST 40
#define PLANE (128*KST)
#define STAGE (4*PLANE)

// MODE 0: fp32 out. MODE 1: fp32 = acc+bias+resid. MODE 2: bf16 hi/lo = gelu(acc+bias).
// MODE 3: bf16 hi/lo = acc (raw).
template <int MODE>
__global__ void __launch_bounds__(256) gemm_tc(
    const __nv_bfloat16* __restrict__ Ahi, const __nv_bfloat16* __restrict__ Alo,
    const __nv_bfloat16* __restrict__ Bhi, const __nv_bfloat16* __restrict__ Blo,
    const float* __restrict__ bias, const float* __restrict__ resid,
    float* __restrict__ C, __nv_bfloat16* __restrict__ Chi, __nv_bfloat16* __restrict__ Clo,
    int N, int K) {
    extern __shared__ __nv_bfloat16 smbuf[];
    const int tid = threadIdx.x;
    const int lane = tid & 31, w = tid >> 5;
    const int wr = w >> 2, wc = w & 3;
    const int m0 = blockIdx.y * BM, n0 = blockIdx.x * BN;
    const uint32_t smbase = (uint32_t)__cvta_generic_to_shared(smbuf);

    const int r0i = tid >> 2;
    const int c0i = (tid & 3) * 8;

    auto load_stage = [&](int it, int buf) {
        const int k0 = it * BK;
        size_t aoff0 = (size_t)(m0 + r0i) * K + k0 + c0i;
        size_t aoff1 = aoff0 + (size_t)64 * K;
        size_t boff0 = (size_t)(n0 + r0i) * K + k0 + c0i;
        size_t boff1 = boff0 + (size_t)64 * K;
        uint32_t s0 = smbase + (uint32_t)(buf * STAGE + r0i * KST + c0i) * 2;
        uint32_t s1 = smbase + (uint32_t)(buf * STAGE + (r0i + 64) * KST + c0i) * 2;
        cpasync16(s0,                 Ahi + aoff0);
        cpasync16(s1,                 Ahi + aoff1);
        cpasync16(s0 + PLANE * 2,     Alo + aoff0);
        cpasync16(s1 + PLANE * 2,     Alo + aoff1);
        cpasync16(s0 + 2 * PLANE * 2, Bhi + boff0);
        cpasync16(s1 + 2 * PLANE * 2, Bhi + boff1);
        cpasync16(s0 + 3 * PLANE * 2, Blo + boff0);
        cpasync16(s1 + 3 * PLANE * 2, Blo + boff1);
    };

    float acc[4][4][4] = {};

    const int arow = wr * 64 + (lane & 15);
    const int acol = (lane >> 4) * 8;
    const int bn   = wc * 32 + ((lane >> 4) << 3) + (lane & 7);
    const int bk   = ((lane >> 3) & 1) << 3;

    const int niter = K / BK;
    load_stage(0, 0);
    asm volatile("cp.async.commit_group;");
    for (int it = 0; it < niter; ++it) {
        if (it + 1 < niter) {
            load_stage(it + 1, (it + 1) & 1);
            asm volatile("cp.async.commit_group;");
            asm volatile("cp.async.wait_group 1;");
        } else {
            asm volatile("cp.async.wait_group 0;");
        }
        __syncthreads();
        const uint32_t base = smbase + (uint32_t)(it & 1) * STAGE * 2;
#pragma unroll
        for (int kk = 0; kk < BK; kk += 16) {
            uint32_t ahi[4][4], alo[4][4], bhi[4][2], blo[4][2];
#pragma unroll
            for (int mt = 0; mt < 4; ++mt) {
                uint32_t ai = base + (uint32_t)((arow + mt * 16) * KST + kk + acol) * 2;
                ldsm4(ahi[mt][0], ahi[mt][1], ahi[mt][2], ahi[mt][3], ai);
                ldsm4(alo[mt][0], alo[mt][1], alo[mt][2], alo[mt][3], ai + PLANE * 2);
            }
#pragma unroll
            for (int g = 0; g < 2; ++g) {
                uint32_t bi = base + 2 * PLANE * 2 +
                              (uint32_t)((bn + g * 16) * KST + kk + bk) * 2;
                ldsm4(bhi[2 * g][0], bhi[2 * g][1], bhi[2 * g + 1][0], bhi[2 * g + 1][1], bi);
                ldsm4(blo[2 * g][0], blo[2 * g][1], blo[2 * g + 1][0], blo[2 * g + 1][1],
                      bi + PLANE * 2);
            }
#pragma unroll
            for (int mt = 0; mt < 4; ++mt)
#pragma unroll
                for (int nt = 0; nt < 4; ++nt) {
                    mma_bf16(acc[mt][nt], ahi[mt], bhi[nt]);
                    mma_bf16(acc[mt][nt], ahi[mt], blo[nt]);
                    mma_bf16(acc[mt][nt], alo[mt], bhi[nt]);
                }
        }
        __syncthreads();
    }

    const int erow = m0 + wr * 64 + (lane >> 2);
    const int ecol = n0 + wc * 32 + (lane & 3) * 2;
#pragma unroll
    for (int mt = 0; mt < 4; ++mt)
#pragma unroll
        for (int nt = 0; nt < 4; ++nt) {
            int c = ecol + nt * 8;
#pragma unroll
            for (int half = 0; half < 2; ++half) {
                int rr = erow + mt * 16 + half * 8;
                float v0 = acc[mt][nt][half * 2 + 0];
                float v1 = acc[mt][nt][half * 2 + 1];
                size_t off = (size_t)rr * N + c;
                if (MODE == 0) {
                    *(float2*)(C + off) = make_float2(v0, v1);
                } else if (MODE == 1) {
                    float2 rv = *(const float2*)(resid + off);
                    v0 += bias[c] + rv.x;
                    v1 += bias[c + 1] + rv.y;
                    *(float2*)(C + off) = make_float2(v0, v1);
                } else if (MODE == 2) {
                    v0 = gelu_exact(v0 + bias[c]);
                    v1 = gelu_exact(v1 + bias[c + 1]);
                    uint32_t hp, lp;
                    split2(v0, v1, hp, lp);
                    *(uint32_t*)(Chi + off) = hp;
                    *(uint32_t*)(Clo + off) = lp;
                } else {
                    uint32_t hp, lp;
                    split2(v0, v1, hp, lp);
                    *(uint32_t*)(Chi + off) = hp;
                    *(uint32_t*)(Clo + off) = lp;
                }
            }
        }
}

// ---------------- tensor-core flash attention v2 (bf16x3, cp.async) ---------
#define AST 72
#define Q_ELE (128*AST)        // per Q plane
#define KV_PLANE (64*AST)      // 4608 elems per K/V plane
#define STG_ELE (4*KV_PLANE)   // 18432 elems per stage
#define STG0 (2*Q_ELE)         // stage 0 base (elems)
#define ATT_SMEM ((STG0 + 2*STG_ELE)*2)   // 110592 bytes

__global__ void __launch_bounds__(256) attn_tc(
    const __nv_bfloat16* __restrict__ qkvhi, const __nv_bfloat16* __restrict__ qkvlo,
    __nv_bfloat16* __restrict__ ohi, __nv_bfloat16* __restrict__ olo) {
    extern __shared__ __nv_bfloat16 sb[];
    const uint32_t smb = (uint32_t)__cvta_generic_to_shared(sb);
    const int tid = threadIdx.x, lane = tid & 31, wid = tid >> 5;
    const int q0 = blockIdx.x * 128;
    const int b = blockIdx.y >> 3, h = blockIdx.y & 7;

    const __nv_bfloat16* hbase = qkvhi + (size_t)(b * NTOK) * 1536 + h * 64;
    const __nv_bfloat16* lbase = qkvlo + (size_t)(b * NTOK) * 1536 + h * 64;

    // Q fill: 2 planes x 128 rows x 8 chunks of 16B
#pragma unroll
    for (int i = 0; i < 8; i++) {
        int c = tid + 256 * i;
        int plane = c >> 10, rem = c & 1023;
        int row = rem >> 3, col = (rem & 7) * 8;
        const __nv_bfloat16* src = (plane ? lbase : hbase) + (size_t)(q0 + row) * 1536 + col;
        cpasync16(smb + (uint32_t)(plane * Q_ELE + row * AST + col) * 2, src);
    }

    auto load_kv = [&](int kt, int buf) {
#pragma unroll
        for (int i = 0; i < 8; i++) {
            int c = tid + 256 * i;
            int plane = c >> 9, rem = c & 511;     // 0:Khi 1:Klo 2:Vhi 3:Vlo
            int row = rem >> 3, col = (rem & 7) * 8;
            const __nv_bfloat16* src = ((plane & 1) ? lbase : hbase) +
                                       ((plane >> 1) ? 1024 : 512) +
                                       (size_t)(kt * 64 + row) * 1536 + col;
            uint32_t dst = (uint32_t)(STG0 + buf * STG_ELE + plane * KV_PLANE +
                                      row * AST + col) * 2;
            cpasync16(smb + dst, src);
        }
    };

    float oacc[8][4] = {};
    float m0s = -1e30f, m1s = -1e30f, l0s = 0.0f, l1s = 0.0f;
    const float sc = 0.18033688011112042f;   // 0.125 * log2(e)

    load_kv(0, 0);
    asm volatile("cp.async.commit_group;");

    for (int kt = 0; kt < 16; kt++) {
        if (kt + 1 < 16) {
            load_kv(kt + 1, (kt + 1) & 1);
            asm volatile("cp.async.commit_group;");
            asm volatile("cp.async.wait_group 1;");
        } else {
            asm volatile("cp.async.wait_group 0;");
        }
        __syncthreads();
        const uint32_t base = (uint32_t)(STG0 + (kt & 1) * STG_ELE) * 2;

        // ---- S = Q K^T ----
        float s[8][4] = {};
#pragma unroll
        for (int k8 = 0; k8 < 4; k8++) {
            uint32_t qh[4], ql[4];
            uint32_t qa = smb + (uint32_t)((wid * 16 + (lane & 15)) * AST + k8 * 16 +
                                           ((lane >> 4) << 3)) * 2;
            ldsm4(qh[0], qh[1], qh[2], qh[3], qa);
            ldsm4(ql[0], ql[1], ql[2], ql[3], qa + Q_ELE * 2);
#pragma unroll
            for (int g = 0; g < 4; g++) {
                int br = g * 16 + ((lane >> 4) << 3) + (lane & 7);
                int bc = k8 * 16 + (((lane >> 3) & 1) << 3);
                uint32_t ka = smb + base + (uint32_t)(br * AST + bc) * 2;
                uint32_t bh[4], bl[4];
                ldsm4(bh[0], bh[1], bh[2], bh[3], ka);
                ldsm4(bl[0], bl[1], bl[2], bl[3], ka + KV_PLANE * 2);
                mma_bf16(s[2 * g],     qh, bh);
                mma_bf16(s[2 * g],     qh, bl);
                mma_bf16(s[2 * g],     ql, bh);
                mma_bf16(s[2 * g + 1], qh, bh + 2);
                mma_bf16(s[2 * g + 1], qh, bl + 2);
                mma_bf16(s[2 * g + 1], ql, bh + 2);
            }
        }

        // ---- online softmax in log2 units ----
        float m0 = -1e30f, m1 = -1e30f;
#pragma unroll
        for (int nt = 0; nt < 8; nt++) {
            s[nt][0] *= sc; s[nt][1] *= sc; s[nt][2] *= sc; s[nt][3] *= sc;
            m0 = fmaxf(m0, fmaxf(s[nt][0], s[nt][1]));
            m1 = fmaxf(m1, fmaxf(s[nt][2], s[nt][3]));
        }
        m0 = fmaxf(m0, __shfl_xor_sync(0xffffffffu, m0, 1));
        m0 = fmaxf(m0, __shfl_xor_sync(0xffffffffu, m0, 2));
        m1 = fmaxf(m1, __shfl_xor_sync(0xffffffffu, m1, 1));
        m1 = fmaxf(m1, __shfl_xor_sync(0xffffffffu, m1, 2));
        float mn0 = fmaxf(m0s, m0), mn1 = fmaxf(m1s, m1);
        float a0 = exp2f(m0s - mn0), a1 = exp2f(m1s - mn1);
        m0s = mn0; m1s = mn1;
        float rs0 = 0.0f, rs1 = 0.0f;
#pragma unroll
        for (int nt = 0; nt < 8; nt++) {
            s[nt][0] = exp2f(s[nt][0] - mn0); rs0 += s[nt][0];
            s[nt][1] = exp2f(s[nt][1] - mn0); rs0 += s[nt][1];
            s[nt][2] = exp2f(s[nt][2] - mn1); rs1 += s[nt][2];
            s[nt][3] = exp2f(s[nt][3] - mn1); rs1 += s[nt][3];
        }
        rs0 += __shfl_xor_sync(0xffffffffu, rs0, 1);
        rs0 += __shfl_xor_sync(0xffffffffu, rs0, 2);
        rs1 += __shfl_xor_sync(0xffffffffu, rs1, 1);
        rs1 += __shfl_xor_sync(0xffffffffu, rs1, 2);
        l0s = l0s * a0 + rs0;
        l1s = l1s * a1 + rs1;
#pragma unroll
        for (int nt = 0; nt < 8; nt++) {
            oacc[nt][0] *= a0; oacc[nt][1] *= a0;
            oacc[nt][2] *= a1; oacc[nt][3] *= a1;
        }

        // ---- pack P into A-fragments ----
        uint32_t phi[4][4], plo[4][4];
#pragma unroll
        for (int j = 0; j < 4; j++) {
            split2(s[2 * j][0],     s[2 * j][1],     phi[j][0], plo[j][0]);
            split2(s[2 * j][2],     s[2 * j][3],     phi[j][1], plo[j][1]);
            split2(s[2 * j + 1][0], s[2 * j + 1][1], phi[j][2], plo[j][2]);
            split2(s[2 * j + 1][2], s[2 * j + 1][3], phi[j][3], plo[j][3]);
        }

        // ---- O += P V (V row-major [kv][dh]; B-frags via ldmatrix.trans) ----
#pragma unroll
        for (int j = 0; j < 4; j++) {
#pragma unroll
            for (int g = 0; g < 4; g++) {
                uint32_t va = smb + base + (uint32_t)(2 * KV_PLANE +
                              (j * 16 + (lane & 15)) * AST + g * 16 +
                              ((lane >> 4) << 3)) * 2;
                uint32_t vh[4], vl[4];
                ldsm4t(vh[0], vh[1], vh[2], vh[3], va);
                ldsm4t(vl[0], vl[1], vl[2], vl[3], va + KV_PLANE * 2);
                mma_bf16(oacc[2 * g],     phi[j], vh);
                mma_bf16(oacc[2 * g],     plo[j], vh);
                mma_bf16(oacc[2 * g],     phi[j], vl);
                mma_bf16(oacc[2 * g + 1], phi[j], vh + 2);
                mma_bf16(oacc[2 * g + 1], plo[j], vh + 2);
                mma_bf16(oacc[2 * g + 1], phi[j], vl + 2);
            }
        }
        __syncthreads();
    }

    // ---- epilogue ----
    float li0 = 1.0f / l0s, li1 = 1.0f / l1s;
#pragma unroll
    for (int half = 0; half < 2; half++) {
        int row = q0 + wid * 16 + half * 8 + (lane >> 2);
        float li = half ? li1 : li0;
        size_t baseo = (size_t)(b * NTOK + row) * DMODEL + h * 64 + (lane & 3) * 2;
#pragma unroll
        for (int nt = 0; nt < 8; nt++) {
            float v0 = oacc[nt][half * 2 + 0] * li;
            float v1 = oacc[nt][half * 2 + 1] * li;
            uint32_t hp, lp;
            split2(v0, v1, hp, lp);
            *(uint32_t*)(ohi + baseo + nt * 8) = hp;
            *(uint32_t*)(olo + baseo + nt * 8) = lp;
        }
    }
}

// ---------------- host orchestration ----------------------------------------
extern "C" void kernel_launch(void* const* d_in, const int* in_sizes, int n_in,
                              void* d_out, int out_size) {
    const float* x         = (const float*)d_in[0];
    const float* attn_ln_w = (const float*)d_in[1];
    const float* attn_ln_b = (const float*)d_in[2];
    const float* w_qkv     = (const float*)d_in[3];
    const float* w_out     = (const float*)d_in[4];
    const float* b_out     = (const float*)d_in[5];
    const float* ffn_ln_w  = (const float*)d_in[6];
    const float* ffn_ln_b  = (const float*)d_in[7];
    const float* w1        = (const float*)d_in[8];
    const float* b1        = (const float*)d_in[9];
    const float* w2        = (const float*)d_in[10];
    const float* b2        = (const float*)d_in[11];
    const float* ln_w      = (const float*)d_in[12];
    const float* ln_b      = (const float*)d_in[13];
    float* out = (float*)d_out;

    float *t, *h;
    __nv_bfloat16 *qkvhi, *qkvlo, *hhi, *hlo, *ohi, *olo, *f1hi, *f1lo;
    __nv_bfloat16 *wqkvhi, *wqkvlo, *wouthi, *woutlo, *w1hi, *w1lo, *w2hi, *w2lo;
    cudaGetSymbolAddress((void**)&t,      g_t);
    cudaGetSymbolAddress((void**)&h,      g_h);
    cudaGetSymbolAddress((void**)&qkvhi,  g_qkvhi);
    cudaGetSymbolAddress((void**)&qkvlo,  g_qkvlo);
    cudaGetSymbolAddress((void**)&hhi,    g_hhi);
    cudaGetSymbolAddress((void**)&hlo,    g_hlo);
    cudaGetSymbolAddress((void**)&ohi,    g_ohi);
    cudaGetSymbolAddress((void**)&olo,    g_olo);
    cudaGetSymbolAddress((void**)&f1hi,   g_f1hi);
    cudaGetSymbolAddress((void**)&f1lo,   g_f1lo);
    cudaGetSymbolAddress((void**)&wqkvhi, g_wqkvhi);
    cudaGetSymbolAddress((void**)&wqkvlo, g_wqkvlo);
    cudaGetSymbolAddress((void**)&wouthi, g_wouthi);
    cudaGetSymbolAddress((void**)&woutlo, g_woutlo);
    cudaGetSymbolAddress((void**)&w1hi,   g_w1hi);
    cudaGetSymbolAddress((void**)&w1lo,   g_w1lo);
    cudaGetSymbolAddress((void**)&w2hi,   g_w2hi);
    cudaGetSymbolAddress((void**)&w2lo,   g_w2lo);

    cudaFuncSetAttribute(attn_tc, cudaFuncAttributeMaxDynamicSharedMemorySize, ATT_SMEM);
    cudaFuncSetAttribute(gemm_tc<1>, cudaFuncAttributeMaxDynamicSharedMemorySize, 81920);
    cudaFuncSetAttribute(gemm_tc<2>, cudaFuncAttributeMaxDynamicSharedMemorySize, 81920);
    cudaFuncSetAttribute(gemm_tc<3>, cudaFuncAttributeMaxDynamicSharedMemorySize, 81920);

    {
        int n;
        n = DEPTH * 3 * DMODEL * DMODEL;
        split_w<<<(n + 255) / 256, 256>>>(w_qkv, wqkvhi, wqkvlo, n);
        n = DEPTH * DMODEL * DMODEL;
        split_w<<<(n + 255) / 256, 256>>>(w_out, wouthi, woutlo, n);
        n = 2 * DMODEL * DMODEL;
        split_w<<<(n + 255) / 256, 256>>>(w1, w1hi, w1lo, n);
        n = 2 * DMODEL * DMODEL;
        split_w<<<(n + 255) / 256, 256>>>(w2, w2hi, w2lo, n);
    }

    dim3 tb(32, 8);
    embed_kernel<<<dim3(32, 16, 8), tb>>>(x, t);

    for (int l = 0; l < DEPTH; l++) {
        ln_kernel<true><<<1024, 256>>>(t, attn_ln_w + l * DMODEL, attn_ln_b + l * DMODEL,
                                       nullptr, hhi, hlo);
        gemm_tc<3><<<dim3(12, 64), 256, 81920>>>(
            hhi, hlo, wqkvhi + (size_t)l * 3 * DMODEL * DMODEL,
            wqkvlo + (size_t)l * 3 * DMODEL * DMODEL,
            nullptr, nullptr, nullptr, qkvhi, qkvlo, 3 * DMODEL, DMODEL);
        attn_tc<<<dim3(8, 64), 256, ATT_SMEM>>>(qkvhi, qkvlo, ohi, olo);
        gemm_tc<1><<<dim3(4, 64), 256, 81920>>>(
            ohi, olo, wouthi + (size_t)l * DMODEL * DMODEL,
            woutlo + (size_t)l * DMODEL * DMODEL,
            b_out + l * DMODEL, t, t, nullptr, nullptr, DMODEL, DMODEL);
        ln_kernel<true><<<1024, 256>>>(t, ffn_ln_w, ffn_ln_b, nullptr, hhi, hlo);
        gemm_tc<2><<<dim3(8, 64), 256, 81920>>>(
            hhi, hlo, w1hi, w1lo, b1, nullptr, nullptr, f1hi, f1lo, 2 * DMODEL, DMODEL);
        gemm_tc<1><<<dim3(4, 64), 256, 81920>>>(
            f1hi, f1lo, w2hi, w2lo, b2, t, t, nullptr, nullptr, DMODEL, 2 * DMODEL);
    }

    ln_kernel<false><<<1024, 256>>>(t, ln_w, ln_b, h, nullptr, nullptr);
    unembed_kernel<<<dim3(32, 16, 8), tb>>>(h, out);
}

// round 8
// speedup vs baseline: 3.1815x; 1.0072x over previous
#include <cuda_runtime.h>
#include <cuda_bf16.h>
#include <math.h>
#include <stdint.h>

#define NTOK 1024
#define DMODEL 512
#define BATCH 8
#define DEPTH 4
#define ROWS (BATCH*NTOK)   // 8192

// ---------------- scratch (static device globals; no runtime allocation) ----
__device__ float g_t  [ROWS*DMODEL];
__device__ float g_h  [ROWS*DMODEL];
__device__ __nv_bfloat16 g_qkvhi[ROWS*3*DMODEL], g_qkvlo[ROWS*3*DMODEL];
__device__ __nv_bfloat16 g_hhi[ROWS*DMODEL], g_hlo[ROWS*DMODEL];
__device__ __nv_bfloat16 g_ohi[ROWS*DMODEL], g_olo[ROWS*DMODEL];
__device__ __nv_bfloat16 g_f1hi[ROWS*2*DMODEL], g_f1lo[ROWS*2*DMODEL];
__device__ __nv_bfloat16 g_wqkvhi[DEPTH*3*DMODEL*DMODEL], g_wqkvlo[DEPTH*3*DMODEL*DMODEL];
__device__ __nv_bfloat16 g_wouthi[DEPTH*DMODEL*DMODEL],   g_woutlo[DEPTH*DMODEL*DMODEL];
__device__ __nv_bfloat16 g_w1hi[2*DMODEL*DMODEL],         g_w1lo[2*DMODEL*DMODEL];
__device__ __nv_bfloat16 g_w2hi[2*DMODEL*DMODEL],         g_w2lo[2*DMODEL*DMODEL];

// ---------------- helpers ----------------------------------------------------
__device__ __forceinline__ void split2(float a, float b, uint32_t& hi, uint32_t& lo) {
    __nv_bfloat16 ha = __float2bfloat16_rn(a), hb = __float2bfloat16_rn(b);
    __nv_bfloat162 hp = __halves2bfloat162(ha, hb);
    hi = *(uint32_t*)&hp;
    __nv_bfloat162 lp = __halves2bfloat162(
        __float2bfloat16_rn(a - __bfloat162float(ha)),
        __float2bfloat16_rn(b - __bfloat162float(hb)));
    lo = *(uint32_t*)&lp;
}
__device__ __forceinline__ void ldsm4(uint32_t& r0, uint32_t& r1, uint32_t& r2, uint32_t& r3,
                                      uint32_t addr) {
    asm volatile("ldmatrix.sync.aligned.m8n8.x4.shared.b16 {%0,%1,%2,%3},[%4];"
                 : "=r"(r0), "=r"(r1), "=r"(r2), "=r"(r3) : "r"(addr));
}
__device__ __forceinline__ void ldsm4t(uint32_t& r0, uint32_t& r1, uint32_t& r2, uint32_t& r3,
                                       uint32_t addr) {
    asm volatile("ldmatrix.sync.aligned.m8n8.x4.trans.shared.b16 {%0,%1,%2,%3},[%4];"
                 : "=r"(r0), "=r"(r1), "=r"(r2), "=r"(r3) : "r"(addr));
}
__device__ __forceinline__ void mma_bf16(float* c, const uint32_t* a, const uint32_t* b) {
    asm volatile(
        "mma.sync.aligned.m16n8k16.row.col.f32.bf16.bf16.f32 "
        "{%0,%1,%2,%3},{%4,%5,%6,%7},{%8,%9},{%0,%1,%2,%3};"
        : "+f"(c[0]), "+f"(c[1]), "+f"(c[2]), "+f"(c[3])
        : "r"(a[0]), "r"(a[1]), "r"(a[2]), "r"(a[3]), "r"(b[0]), "r"(b[1]));
}
__device__ __forceinline__ void cpasync16(uint32_t saddr, const void* g) {
    asm volatile("cp.async.cg.shared.global [%0],[%1],16;" :: "r"(saddr), "l"(g));
}
__device__ __forceinline__ float gelu_exact(float v) {
    return 0.5f * v * (1.0f + erff(v * 0.7071067811865476f));
}

// ---------------- bf16 hi/lo split of ALL weight tensors (one launch) -------
__global__ void split_all(const float* __restrict__ w0, __nv_bfloat16* __restrict__ h0,
                          __nv_bfloat16* __restrict__ l0, int n0,
                          const float* __restrict__ w1, __nv_bfloat16* __restrict__ h1,
                          __nv_bfloat16* __restrict__ l1, int n1,
                          const float* __restrict__ w2, __nv_bfloat16* __restrict__ h2,
                          __nv_bfloat16* __restrict__ l2, int n2,
                          const float* __restrict__ w3, __nv_bfloat16* __restrict__ h3,
                          __nv_bfloat16* __restrict__ l3, int n3) {
    int i = blockIdx.x * 256 + threadIdx.x;
    const float* w; __nv_bfloat16 *hi, *lo;
    if (i < n0) { w = w0 + i; hi = h0 + i; lo = l0 + i; }
    else if (i < n0 + n1) { i -= n0; w = w1 + i; hi = h1 + i; lo = l1 + i; }
    else if (i < n0 + n1 + n2) { i -= n0 + n1; w = w2 + i; hi = h2 + i; lo = l2 + i; }
    else if (i < n0 + n1 + n2 + n3) { i -= n0 + n1 + n2; w = w3 + i; hi = h3 + i; lo = l3 + i; }
    else return;
    float v = *w;
    __nv_bfloat16 h = __float2bfloat16_rn(v);
    *hi = h;
    *lo = __float2bfloat16_rn(v - __bfloat162float(h));
}

// ---------------- embed: transpose [b,c,n] -> [b,n,c] and add sinusoid PE ---
__global__ void embed_kernel(const float* __restrict__ x, float* __restrict__ t) {
    __shared__ float tile[32][33];
    int n0 = blockIdx.x * 32, c0 = blockIdx.y * 32, b = blockIdx.z;
    int tx = threadIdx.x, ty = threadIdx.y;
#pragma unroll
    for (int i = 0; i < 4; i++) {
        int c = c0 + ty + i * 8;
        tile[ty + i * 8][tx] = x[((size_t)b * DMODEL + c) * NTOK + n0 + tx];
    }
    __syncthreads();
#pragma unroll
    for (int i = 0; i < 4; i++) {
        int n = n0 + ty + i * 8;
        int c = c0 + tx;
        float e = (float)(c & ~1) * (1.0f / DMODEL);
        float ang = (float)n * expf(-9.210340371976184f * e);
        float pe = (c & 1) ? cosf(ang) : sinf(ang);
        t[((size_t)b * NTOK + n) * DMODEL + c] = tile[tx][ty + i * 8] + pe;
    }
}

// ---------------- unembed -----------------------------------------------------
__global__ void unembed_kernel(const float* __restrict__ h, float* __restrict__ out) {
    __shared__ float tile[32][33];
    int n0 = blockIdx.x * 32, c0 = blockIdx.y * 32, b = blockIdx.z;
    int tx = threadIdx.x, ty = threadIdx.y;
#pragma unroll
    for (int i = 0; i < 4; i++) {
        int n = n0 + ty + i * 8;
        tile[ty + i * 8][tx] = h[((size_t)b * NTOK + n) * DMODEL + c0 + tx];
    }
    __syncthreads();
#pragma unroll
    for (int i = 0; i < 4; i++) {
        int c = c0 + ty + i * 8;
        out[((size_t)b * DMODEL + c) * NTOK + n0 + tx] = tile[tx][ty + i * 8];
    }
}

// ---------------- layernorm: one warp per row; SPLIT -> bf16 hi/lo planes ----
template <bool SPLIT>
__global__ void ln_kernel(const float* __restrict__ x, const float* __restrict__ w,
                          const float* __restrict__ bias, float* __restrict__ y,
                          __nv_bfloat16* __restrict__ yhi, __nv_bfloat16* __restrict__ ylo) {
    int gw = (blockIdx.x * blockDim.x + threadIdx.x) >> 5;
    int lane = threadIdx.x & 31;
    if (gw >= ROWS) return;
    const float4* xr = (const float4*)(x + (size_t)gw * DMODEL);
    float4 v[4];
    float s = 0.0f;
#pragma unroll
    for (int u = 0; u < 4; u++) {
        v[u] = xr[u * 32 + lane];
        s += v[u].x + v[u].y + v[u].z + v[u].w;
    }
#pragma unroll
    for (int o = 16; o > 0; o >>= 1) s += __shfl_xor_sync(0xffffffffu, s, o);
    float mu = s * (1.0f / DMODEL);
    float q = 0.0f;
#pragma unroll
    for (int u = 0; u < 4; u++) {
        v[u].x -= mu; v[u].y -= mu; v[u].z -= mu; v[u].w -= mu;
        q += v[u].x * v[u].x + v[u].y * v[u].y + v[u].z * v[u].z + v[u].w * v[u].w;
    }
#pragma unroll
    for (int o = 16; o > 0; o >>= 1) q += __shfl_xor_sync(0xffffffffu, q, o);
    float rstd = rsqrtf(q * (1.0f / DMODEL) + 1e-5f);
    const float4* wr = (const float4*)w;
    const float4* br = (const float4*)bias;
#pragma unroll
    for (int u = 0; u < 4; u++) {
        float4 W = wr[u * 32 + lane], B = br[u * 32 + lane], o4;
        o4.x = v[u].x * rstd * W.x + B.x;
        o4.y = v[u].y * rstd * W.y + B.y;
        o4.z = v[u].z * rstd * W.z + B.z;
        o4.w = v[u].w * rstd * W.w + B.w;
        if (SPLIT) {
            size_t off = (size_t)gw * DMODEL + (u * 32 + lane) * 4;
            uint32_t h0, l0, h1, l1;
            split2(o4.x, o4.y, h0, l0);
            split2(o4.z, o4.w, h1, l1);
            *(uint32_t*)(yhi + off)     = h0;
            *(uint32_t*)(yhi + off + 2) = h1;
            *(uint32_t*)(ylo + off)     = l0;
            *(uint32_t*)(ylo + off + 2) = l1;
        } else {
            ((float4*)(y + (size_t)gw * DMODEL))[u * 32 + lane] = o4;
        }
    }
}

// ---------------- tensor-core GEMM (bf16x3): C = A * W^T --------------------
#define BM 128
#define BN 128
#define BK 32
#define KST 40
#define PLANE (128*KST)
#define STAGE (4*PLANE)

// MODE 0: fp32 out. MODE 1: fp32 = acc+bias+resid. MODE 2: bf16 hi/lo = gelu(acc+bias).
// MODE 3: bf16 hi/lo = acc (raw).
template <int MODE>
__global__ void __launch_bounds__(256, 2) gemm_tc(
    const __nv_bfloat16* __restrict__ Ahi, const __nv_bfloat16* __restrict__ Alo,
    const __nv_bfloat16* __restrict__ Bhi, const __nv_bfloat16* __restrict__ Blo,
    const float* __restrict__ bias, const float* __restrict__ resid,
    float* __restrict__ C, __nv_bfloat16* __restrict__ Chi, __nv_bfloat16* __restrict__ Clo,
    int N, int K) {
    extern __shared__ __nv_bfloat16 smbuf[];
    const int tid = threadIdx.x;
    const int lane = tid & 31, w = tid >> 5;
    const int wr = w >> 2, wc = w & 3;
    const int m0 = blockIdx.y * BM, n0 = blockIdx.x * BN;
    const uint32_t smbase = (uint32_t)__cvta_generic_to_shared(smbuf);

    const int r0i = tid >> 2;
    const int c0i = (tid & 3) * 8;

    auto load_stage = [&](int it, int buf) {
        const int k0 = it * BK;
        size_t aoff0 = (size_t)(m0 + r0i) * K + k0 + c0i;
        size_t aoff1 = aoff0 + (size_t)64 * K;
        size_t boff0 = (size_t)(n0 + r0i) * K + k0 + c0i;
        size_t boff1 = boff0 + (size_t)64 * K;
        uint32_t s0 = smbase + (uint32_t)(buf * STAGE + r0i * KST + c0i) * 2;
        uint32_t s1 = smbase + (uint32_t)(buf * STAGE + (r0i + 64) * KST + c0i) * 2;
        cpasync16(s0,                 Ahi + aoff0);
        cpasync16(s1,                 Ahi + aoff1);
        cpasync16(s0 + PLANE * 2,     Alo + aoff0);
        cpasync16(s1 + PLANE * 2,     Alo + aoff1);
        cpasync16(s0 + 2 * PLANE * 2, Bhi + boff0);
        cpasync16(s1 + 2 * PLANE * 2, Bhi + boff1);
        cpasync16(s0 + 3 * PLANE * 2, Blo + boff0);
        cpasync16(s1 + 3 * PLANE * 2, Blo + boff1);
    };

    float acc[4][4][4] = {};

    const int arow = wr * 64 + (lane & 15);
    const int acol = (lane >> 4) * 8;
    const int bn   = wc * 32 + ((lane >> 4) << 3) + (lane & 7);
    const int bk   = ((lane >> 3) & 1) << 3;

    const int niter = K / BK;
    load_stage(0, 0);
    asm volatile("cp.async.commit_group;");
    for (int it = 0; it < niter; ++it) {
        if (it + 1 < niter) {
            load_stage(it + 1, (it + 1) & 1);
            asm volatile("cp.async.commit_group;");
            asm volatile("cp.async.wait_group 1;");
        } else {
            asm volatile("cp.async.wait_group 0;");
        }
        __syncthreads();
        const uint32_t base = smbase + (uint32_t)(it & 1) * STAGE * 2;
#pragma unroll
        for (int kk = 0; kk < BK; kk += 16) {
            uint32_t ahi[4][4], alo[4][4];
#pragma unroll
            for (int mt = 0; mt < 4; ++mt) {
                uint32_t ai = base + (uint32_t)((arow + mt * 16) * KST + kk + acol) * 2;
                ldsm4(ahi[mt][0], ahi[mt][1], ahi[mt][2], ahi[mt][3], ai);
                ldsm4(alo[mt][0], alo[mt][1], alo[mt][2], alo[mt][3], ai + PLANE * 2);
            }
            // load B fragments per 16-col group to keep the live set small
#pragma unroll
            for (int g = 0; g < 2; ++g) {
                uint32_t bhi[4], blo[4];
                uint32_t bi = base + 2 * PLANE * 2 +
                              (uint32_t)((bn + g * 16) * KST + kk + bk) * 2;
                ldsm4(bhi[0], bhi[1], bhi[2], bhi[3], bi);
                ldsm4(blo[0], blo[1], blo[2], blo[3], bi + PLANE * 2);
#pragma unroll
                for (int half = 0; half < 2; ++half) {
                    int nt = 2 * g + half;
#pragma unroll
                    for (int mt = 0; mt < 4; ++mt) {
                        mma_bf16(acc[mt][nt], ahi[mt], bhi + 2 * half);
                        mma_bf16(acc[mt][nt], ahi[mt], blo + 2 * half);
                        mma_bf16(acc[mt][nt], alo[mt], bhi + 2 * half);
                    }
                }
            }
        }
        __syncthreads();
    }

    const int erow = m0 + wr * 64 + (lane >> 2);
    const int ecol = n0 + wc * 32 + (lane & 3) * 2;
#pragma unroll
    for (int mt = 0; mt < 4; ++mt)
#pragma unroll
        for (int nt = 0; nt < 4; ++nt) {
            int c = ecol + nt * 8;
#pragma unroll
            for (int half = 0; half < 2; ++half) {
                int rr = erow + mt * 16 + half * 8;
                float v0 = acc[mt][nt][half * 2 + 0];
                float v1 = acc[mt][nt][half * 2 + 1];
                size_t off = (size_t)rr * N + c;
                if (MODE == 0) {
                    *(float2*)(C + off) = make_float2(v0, v1);
                } else if (MODE == 1) {
                    float2 rv = *(const float2*)(resid + off);
                    v0 += bias[c] + rv.x;
                    v1 += bias[c + 1] + rv.y;
                    *(float2*)(C + off) = make_float2(v0, v1);
                } else if (MODE == 2) {
                    v0 = gelu_exact(v0 + bias[c]);
                    v1 = gelu_exact(v1 + bias[c + 1]);
                    uint32_t hp, lp;
                    split2(v0, v1, hp, lp);
                    *(uint32_t*)(Chi + off) = hp;
                    *(uint32_t*)(Clo + off) = lp;
                } else {
                    uint32_t hp, lp;
                    split2(v0, v1, hp, lp);
                    *(uint32_t*)(Chi + off) = hp;
                    *(uint32_t*)(Clo + off) = lp;
                }
            }
        }
}

// ---------------- tensor-core flash attention v2 (bf16x3, cp.async) ---------
#define AST 72
#define Q_ELE (128*AST)        // per Q plane
#define KV_PLANE (64*AST)      // 4608 elems per K/V plane
#define STG_ELE (4*KV_PLANE)   // 18432 elems per stage
#define STG0 (2*Q_ELE)         // stage 0 base (elems)
#define ATT_SMEM ((STG0 + 2*STG_ELE)*2)   // 110592 bytes

__global__ void __launch_bounds__(256, 2) attn_tc(
    const __nv_bfloat16* __restrict__ qkvhi, const __nv_bfloat16* __restrict__ qkvlo,
    __nv_bfloat16* __restrict__ ohi, __nv_bfloat16* __restrict__ olo) {
    extern __shared__ __nv_bfloat16 sb[];
    const uint32_t smb = (uint32_t)__cvta_generic_to_shared(sb);
    const int tid = threadIdx.x, lane = tid & 31, wid = tid >> 5;
    const int q0 = blockIdx.x * 128;
    const int b = blockIdx.y >> 3, h = blockIdx.y & 7;

    const __nv_bfloat16* hbase = qkvhi + (size_t)(b * NTOK) * 1536 + h * 64;
    const __nv_bfloat16* lbase = qkvlo + (size_t)(b * NTOK) * 1536 + h * 64;

    // Q fill: 2 planes x 128 rows x 8 chunks of 16B
#pragma unroll
    for (int i = 0; i < 8; i++) {
        int c = tid + 256 * i;
        int plane = c >> 10, rem = c & 1023;
        int row = rem >> 3, col = (rem & 7) * 8;
        const __nv_bfloat16* src = (plane ? lbase : hbase) + (size_t)(q0 + row) * 1536 + col;
        cpasync16(smb + (uint32_t)(plane * Q_ELE + row * AST + col) * 2, src);
    }

    auto load_kv = [&](int kt, int buf) {
#pragma unroll
        for (int i = 0; i < 8; i++) {
            int c = tid + 256 * i;
            int plane = c >> 9, rem = c & 511;     // 0:Khi 1:Klo 2:Vhi 3:Vlo
            int row = rem >> 3, col = (rem & 7) * 8;
            const __nv_bfloat16* src = ((plane & 1) ? lbase : hbase) +
                                       ((plane >> 1) ? 1024 : 512) +
                                       (size_t)(kt * 64 + row) * 1536 + col;
            uint32_t dst = (uint32_t)(STG0 + buf * STG_ELE + plane * KV_PLANE +
                                      row * AST + col) * 2;
            cpasync16(smb + dst, src);
        }
    };

    float oacc[8][4] = {};
    float m0s = -1e30f, m1s = -1e30f, l0s = 0.0f, l1s = 0.0f;
    const float sc = 0.18033688011112042f;   // 0.125 * log2(e)

    load_kv(0, 0);
    asm volatile("cp.async.commit_group;");

    for (int kt = 0; kt < 16; kt++) {
        if (kt + 1 < 16) {
            load_kv(kt + 1, (kt + 1) & 1);
            asm volatile("cp.async.commit_group;");
            asm volatile("cp.async.wait_group 1;");
        } else {
            asm volatile("cp.async.wait_group 0;");
        }
        __syncthreads();
        const uint32_t base = (uint32_t)(STG0 + (kt & 1) * STG_ELE) * 2;

        // ---- S = Q K^T ----
        float s[8][4] = {};
#pragma unroll
        for (int k8 = 0; k8 < 4; k8++) {
            uint32_t qh[4], ql[4];
            uint32_t qa = smb + (uint32_t)((wid * 16 + (lane & 15)) * AST + k8 * 16 +
                                           ((lane >> 4) << 3)) * 2;
            ldsm4(qh[0], qh[1], qh[2], qh[3], qa);
            ldsm4(ql[0], ql[1], ql[2], ql[3], qa + Q_ELE * 2);
#pragma unroll
            for (int g = 0; g < 4; g++) {
                int br = g * 16 + ((lane >> 4) << 3) + (lane & 7);
                int bc = k8 * 16 + (((lane >> 3) & 1) << 3);
                uint32_t ka = smb + base + (uint32_t)(br * AST + bc) * 2;
                uint32_t bh[4], bl[4];
                ldsm4(bh[0], bh[1], bh[2], bh[3], ka);
                ldsm4(bl[0], bl[1], bl[2], bl[3], ka + KV_PLANE * 2);
                mma_bf16(s[2 * g],     qh, bh);
                mma_bf16(s[2 * g],     qh, bl);
                mma_bf16(s[2 * g],     ql, bh);
                mma_bf16(s[2 * g + 1], qh, bh + 2);
                mma_bf16(s[2 * g + 1], qh, bl + 2);
                mma_bf16(s[2 * g + 1], ql, bh + 2);
            }
        }

        // ---- online softmax in log2 units ----
        float m0 = -1e30f, m1 = -1e30f;
#pragma unroll
        for (int nt = 0; nt < 8; nt++) {
            s[nt][0] *= sc; s[nt][1] *= sc; s[nt][2] *= sc; s[nt][3] *= sc;
            m0 = fmaxf(m0, fmaxf(s[nt][0], s[nt][1]));
            m1 = fmaxf(m1, fmaxf(s[nt][2], s[nt][3]));
        }
        m0 = fmaxf(m0, __shfl_xor_sync(0xffffffffu, m0, 1));
        m0 = fmaxf(m0, __shfl_xor_sync(0xffffffffu, m0, 2));
        m1 = fmaxf(m1, __shfl_xor_sync(0xffffffffu, m1, 1));
        m1 = fmaxf(m1, __shfl_xor_sync(0xffffffffu, m1, 2));
        float mn0 = fmaxf(m0s, m0), mn1 = fmaxf(m1s, m1);
        float a0 = exp2f(m0s - mn0), a1 = exp2f(m1s - mn1);
        m0s = mn0; m1s = mn1;
        float rs0 = 0.0f, rs1 = 0.0f;
#pragma unroll
        for (int nt = 0; nt < 8; nt++) {
            s[nt][0] = exp2f(s[nt][0] - mn0); rs0 += s[nt][0];
            s[nt][1] = exp2f(s[nt][1] - mn0); rs0 += s[nt][1];
            s[nt][2] = exp2f(s[nt][2] - mn1); rs1 += s[nt][2];
            s[nt][3] = exp2f(s[nt][3] - mn1); rs1 += s[nt][3];
        }
        rs0 += __shfl_xor_sync(0xffffffffu, rs0, 1);
        rs0 += __shfl_xor_sync(0xffffffffu, rs0, 2);
        rs1 += __shfl_xor_sync(0xffffffffu, rs1, 1);
        rs1 += __shfl_xor_sync(0xffffffffu, rs1, 2);
        l0s = l0s * a0 + rs0;
        l1s = l1s * a1 + rs1;
#pragma unroll
        for (int nt = 0; nt < 8; nt++) {
            oacc[nt][0] *= a0; oacc[nt][1] *= a0;
            oacc[nt][2] *= a1; oacc[nt][3] *= a1;
        }

        // ---- pack P into A-fragments ----
        uint32_t phi[4][4], plo[4][4];
#pragma unroll
        for (int j = 0; j < 4; j++) {
            split2(s[2 * j][0],     s[2 * j][1],     phi[j][0], plo[j][0]);
            split2(s[2 * j][2],     s[2 * j][3],     phi[j][1], plo[j][1]);
            split2(s[2 * j + 1][0], s[2 * j + 1][1], phi[j][2], plo[j][2]);
            split2(s[2 * j + 1][2], s[2 * j + 1][3], phi[j][3], plo[j][3]);
        }

        // ---- O += P V (V row-major [kv][dh]; B-frags via ldmatrix.trans) ----
#pragma unroll
        for (int j = 0; j < 4; j++) {
#pragma unroll
            for (int g = 0; g < 4; g++) {
                uint32_t va = smb + base + (uint32_t)(2 * KV_PLANE +
                              (j * 16 + (lane & 15)) * AST + g * 16 +
                              ((lane >> 4) << 3)) * 2;
                uint32_t vh[4], vl[4];
                ldsm4t(vh[0], vh[1], vh[2], vh[3], va);
                ldsm4t(vl[0], vl[1], vl[2], vl[3], va + KV_PLANE * 2);
                mma_bf16(oacc[2 * g],     phi[j], vh);
                mma_bf16(oacc[2 * g],     plo[j], vh);
                mma_bf16(oacc[2 * g],     phi[j], vl);
                mma_bf16(oacc[2 * g + 1], phi[j], vh + 2);
                mma_bf16(oacc[2 * g + 1], plo[j], vh + 2);
                mma_bf16(oacc[2 * g + 1], phi[j], vl + 2);
            }
        }
        __syncthreads();
    }

    // ---- epilogue ----
    float li0 = 1.0f / l0s, li1 = 1.0f / l1s;
#pragma unroll
    for (int half = 0; half < 2; half++) {
        int row = q0 + wid * 16 + half * 8 + (lane >> 2);
        float li = half ? li1 : li0;
        size_t baseo = (size_t)(b * NTOK + row) * DMODEL + h * 64 + (lane & 3) * 2;
#pragma unroll
        for (int nt = 0; nt < 8; nt++) {
            float v0 = oacc[nt][half * 2 + 0] * li;
            float v1 = oacc[nt][half * 2 + 1] * li;
            uint32_t hp, lp;
            split2(v0, v1, hp, lp);
            *(uint32_t*)(ohi + baseo + nt * 8) = hp;
            *(uint32_t*)(olo + baseo + nt * 8) = lp;
        }
    }
}

// ---------------- host orchestration ----------------------------------------
extern "C" void kernel_launch(void* const* d_in, const int* in_sizes, int n_in,
                              void* d_out, int out_size) {
    const float* x         = (const float*)d_in[0];
    const float* attn_ln_w = (const float*)d_in[1];
    const float* attn_ln_b = (const float*)d_in[2];
    const float* w_qkv     = (const float*)d_in[3];
    const float* w_out     = (const float*)d_in[4];
    const float* b_out     = (const float*)d_in[5];
    const float* ffn_ln_w  = (const float*)d_in[6];
    const float* ffn_ln_b  = (const float*)d_in[7];
    const float* w1        = (const float*)d_in[8];
    const float* b1        = (const float*)d_in[9];
    const float* w2        = (const float*)d_in[10];
    const float* b2        = (const float*)d_in[11];
    const float* ln_w      = (const float*)d_in[12];
    const float* ln_b      = (const float*)d_in[13];
    float* out = (float*)d_out;

    float *t, *h;
    __nv_bfloat16 *qkvhi, *qkvlo, *hhi, *hlo, *ohi, *olo, *f1hi, *f1lo;
    __nv_bfloat16 *wqkvhi, *wqkvlo, *wouthi, *woutlo, *w1hi, *w1lo, *w2hi, *w2lo;
    cudaGetSymbolAddress((void**)&t,      g_t);
    cudaGetSymbolAddress((void**)&h,      g_h);
    cudaGetSymbolAddress((void**)&qkvhi,  g_qkvhi);
    cudaGetSymbolAddress((void**)&qkvlo,  g_qkvlo);
    cudaGetSymbolAddress((void**)&hhi,    g_hhi);
    cudaGetSymbolAddress((void**)&hlo,    g_hlo);
    cudaGetSymbolAddress((void**)&ohi,    g_ohi);
    cudaGetSymbolAddress((void**)&olo,    g_olo);
    cudaGetSymbolAddress((void**)&f1hi,   g_f1hi);
    cudaGetSymbolAddress((void**)&f1lo,   g_f1lo);
    cudaGetSymbolAddress((void**)&wqkvhi, g_wqkvhi);
    cudaGetSymbolAddress((void**)&wqkvlo, g_wqkvlo);
    cudaGetSymbolAddress((void**)&wouthi, g_wouthi);
    cudaGetSymbolAddress((void**)&woutlo, g_woutlo);
    cudaGetSymbolAddress((void**)&w1hi,   g_w1hi);
    cudaGetSymbolAddress((void**)&w1lo,   g_w1lo);
    cudaGetSymbolAddress((void**)&w2hi,   g_w2hi);
    cudaGetSymbolAddress((void**)&w2lo,   g_w2lo);

    cudaFuncSetAttribute(attn_tc, cudaFuncAttributeMaxDynamicSharedMemorySize, ATT_SMEM);
    cudaFuncSetAttribute(gemm_tc<1>, cudaFuncAttributeMaxDynamicSharedMemorySize, 81920);
    cudaFuncSetAttribute(gemm_tc<2>, cudaFuncAttributeMaxDynamicSharedMemorySize, 81920);
    cudaFuncSetAttribute(gemm_tc<3>, cudaFuncAttributeMaxDynamicSharedMemorySize, 81920);

    {
        const int n0 = DEPTH * 3 * DMODEL * DMODEL;
        const int n1 = DEPTH * DMODEL * DMODEL;
        const int n2 = 2 * DMODEL * DMODEL;
        const int n3 = 2 * DMODEL * DMODEL;
        const int ntot = n0 + n1 + n2 + n3;
        split_all<<<(ntot + 255) / 256, 256>>>(
            w_qkv, wqkvhi, wqkvlo, n0,
            w_out, wouthi, woutlo, n1,
            w1, w1hi, w1lo, n2,
            w2, w2hi, w2lo, n3);
    }

    dim3 tb(32, 8);
    embed_kernel<<<dim3(32, 16, 8), tb>>>(x, t);

    for (int l = 0; l < DEPTH; l++) {
        ln_kernel<true><<<1024, 256>>>(t, attn_ln_w + l * DMODEL, attn_ln_b + l * DMODEL,
                                       nullptr, hhi, hlo);
        gemm_tc<3><<<dim3(12, 64), 256, 81920>>>(
            hhi, hlo, wqkvhi + (size_t)l * 3 * DMODEL * DMODEL,
            wqkvlo + (size_t)l * 3 * DMODEL * DMODEL,
            nullptr, nullptr, nullptr, qkvhi, qkvlo, 3 * DMODEL, DMODEL);
        attn_tc<<<dim3(8, 64), 256, ATT_SMEM>>>(qkvhi, qkvlo, ohi, olo);
        gemm_tc<1><<<dim3(4, 64), 256, 81920>>>(
            ohi, olo, wouthi + (size_t)l * DMODEL * DMODEL,
            woutlo + (size_t)l * DMODEL * DMODEL,
            b_out + l * DMODEL, t, t, nullptr, nullptr, DMODEL, DMODEL);
        ln_kernel<true><<<1024, 256>>>(t, ffn_ln_w, ffn_ln_b, nullptr, hhi, hlo);
        gemm_tc<2><<<dim3(8, 64), 256, 81920>>>(
            hhi, hlo, w1hi, w1lo, b1, nullptr, nullptr, f1hi, f1lo, 2 * DMODEL, DMODEL);
        gemm_tc<1><<<dim3(4, 64), 256, 81920>>>(
            f1hi, f1lo, w2hi, w2lo, b2, t, t, nullptr, nullptr, DMODEL, 2 * DMODEL);
    }

    ln_kernel<false><<<1024, 256>>>(t, ln_w, ln_b, h, nullptr, nullptr);
    unembed_kernel<<<dim3(32, 16, 8), tb>>>(h, out);
}

// round 11
// speedup vs baseline: 4.5476x; 1.4294x over previous
#include <cuda_runtime.h>
#include <cuda_fp16.h>
#include <math.h>
#include <stdint.h>

#define NTOK 1024
#define DMODEL 512
#define BATCH 8
#define DEPTH 4
#define ROWS (BATCH*NTOK)   // 8192

// ---------------- scratch (static device globals; no runtime allocation) ----
__device__ float g_t  [ROWS*DMODEL];
__device__ float g_h  [ROWS*DMODEL];
__device__ __half g_qkvhi[ROWS*3*DMODEL], g_qkvlo[ROWS*3*DMODEL];
__device__ __half g_hhi[ROWS*DMODEL], g_hlo[ROWS*DMODEL];
__device__ __half g_ohi[ROWS*DMODEL], g_olo[ROWS*DMODEL];
__device__ __half g_f1hi[ROWS*2*DMODEL], g_f1lo[ROWS*2*DMODEL];
__device__ __half g_wqkv[DEPTH*3*DMODEL*DMODEL];
__device__ __half g_wout[DEPTH*DMODEL*DMODEL];
__device__ __half g_w1[2*DMODEL*DMODEL];
__device__ __half g_w2[2*DMODEL*DMODEL];

// ---------------- helpers ----------------------------------------------------
__device__ __forceinline__ void split2h(float a, float b, uint32_t& hi, uint32_t& lo) {
    __half ha = __float2half_rn(a), hb = __float2half_rn(b);
    __half2 hp = __halves2half2(ha, hb);
    hi = *(uint32_t*)&hp;
    __half2 lp = __halves2half2(
        __float2half_rn(a - __half2float(ha)),
        __float2half_rn(b - __half2float(hb)));
    lo = *(uint32_t*)&lp;
}
__device__ __forceinline__ void ldsm4(uint32_t& r0, uint32_t& r1, uint32_t& r2, uint32_t& r3,
                                      uint32_t addr) {
    asm volatile("ldmatrix.sync.aligned.m8n8.x4.shared.b16 {%0,%1,%2,%3},[%4];"
                 : "=r"(r0), "=r"(r1), "=r"(r2), "=r"(r3) : "r"(addr));
}
__device__ __forceinline__ void ldsm4t(uint32_t& r0, uint32_t& r1, uint32_t& r2, uint32_t& r3,
                                       uint32_t addr) {
    asm volatile("ldmatrix.sync.aligned.m8n8.x4.trans.shared.b16 {%0,%1,%2,%3},[%4];"
                 : "=r"(r0), "=r"(r1), "=r"(r2), "=r"(r3) : "r"(addr));
}
__device__ __forceinline__ void mma_f16(float* c, const uint32_t* a, const uint32_t* b) {
    asm volatile(
        "mma.sync.aligned.m16n8k16.row.col.f32.f16.f16.f32 "
        "{%0,%1,%2,%3},{%4,%5,%6,%7},{%8,%9},{%0,%1,%2,%3};"
        : "+f"(c[0]), "+f"(c[1]), "+f"(c[2]), "+f"(c[3])
        : "r"(a[0]), "r"(a[1]), "r"(a[2]), "r"(a[3]), "r"(b[0]), "r"(b[1]));
}
__device__ __forceinline__ void cpasync16(uint32_t saddr, const void* g) {
    asm volatile("cp.async.cg.shared.global [%0],[%1],16;" :: "r"(saddr), "l"(g));
}
__device__ __forceinline__ float gelu_exact(float v) {
    return 0.5f * v * (1.0f + erff(v * 0.7071067811865476f));
}

// ---------------- fp16 convert of ALL weight tensors (one launch) -----------
__global__ void split_allh(const float* __restrict__ w0, __half* __restrict__ h0, int n0,
                           const float* __restrict__ w1, __half* __restrict__ h1, int n1,
                           const float* __restrict__ w2, __half* __restrict__ h2, int n2,
                           const float* __restrict__ w3, __half* __restrict__ h3, int n3) {
    int i = blockIdx.x * 256 + threadIdx.x;
    const float* w; __half* h;
    if (i < n0) { w = w0 + i; h = h0 + i; }
    else if (i < n0 + n1) { i -= n0; w = w1 + i; h = h1 + i; }
    else if (i < n0 + n1 + n2) { i -= n0 + n1; w = w2 + i; h = h2 + i; }
    else if (i < n0 + n1 + n2 + n3) { i -= n0 + n1 + n2; w = w3 + i; h = h3 + i; }
    else return;
    *h = __float2half_rn(*w);
}

// ---------------- embed / unembed -------------------------------------------
__global__ void embed_kernel(const float* __restrict__ x, float* __restrict__ t) {
    __shared__ float tile[32][33];
    int n0 = blockIdx.x * 32, c0 = blockIdx.y * 32, b = blockIdx.z;
    int tx = threadIdx.x, ty = threadIdx.y;
#pragma unroll
    for (int i = 0; i < 4; i++) {
        int c = c0 + ty + i * 8;
        tile[ty + i * 8][tx] = x[((size_t)b * DMODEL + c) * NTOK + n0 + tx];
    }
    __syncthreads();
#pragma unroll
    for (int i = 0; i < 4; i++) {
        int n = n0 + ty + i * 8;
        int c = c0 + tx;
        float e = (float)(c & ~1) * (1.0f / DMODEL);
        float ang = (float)n * expf(-9.210340371976184f * e);
        float pe = (c & 1) ? cosf(ang) : sinf(ang);
        t[((size_t)b * NTOK + n) * DMODEL + c] = tile[tx][ty + i * 8] + pe;
    }
}
__global__ void unembed_kernel(const float* __restrict__ h, float* __restrict__ out) {
    __shared__ float tile[32][33];
    int n0 = blockIdx.x * 32, c0 = blockIdx.y * 32, b = blockIdx.z;
    int tx = threadIdx.x, ty = threadIdx.y;
#pragma unroll
    for (int i = 0; i < 4; i++) {
        int n = n0 + ty + i * 8;
        tile[ty + i * 8][tx] = h[((size_t)b * NTOK + n) * DMODEL + c0 + tx];
    }
    __syncthreads();
#pragma unroll
    for (int i = 0; i < 4; i++) {
        int c = c0 + ty + i * 8;
        out[((size_t)b * DMODEL + c) * NTOK + n0 + tx] = tile[tx][ty + i * 8];
    }
}

// ---------------- layernorm: one warp per row; SPLIT -> fp16 hi/lo planes ---
template <bool SPLIT>
__global__ void ln_kernel(const float* __restrict__ x, const float* __restrict__ w,
                          const float* __restrict__ bias, float* __restrict__ y,
                          __half* __restrict__ yhi, __half* __restrict__ ylo) {
    int gw = (blockIdx.x * blockDim.x + threadIdx.x) >> 5;
    int lane = threadIdx.x & 31;
    if (gw >= ROWS) return;
    const float4* xr = (const float4*)(x + (size_t)gw * DMODEL);
    float4 v[4];
    float s = 0.0f;
#pragma unroll
    for (int u = 0; u < 4; u++) {
        v[u] = xr[u * 32 + lane];
        s += v[u].x + v[u].y + v[u].z + v[u].w;
    }
#pragma unroll
    for (int o = 16; o > 0; o >>= 1) s += __shfl_xor_sync(0xffffffffu, s, o);
    float mu = s * (1.0f / DMODEL);
    float q = 0.0f;
#pragma unroll
    for (int u = 0; u < 4; u++) {
        v[u].x -= mu; v[u].y -= mu; v[u].z -= mu; v[u].w -= mu;
        q += v[u].x * v[u].x + v[u].y * v[u].y + v[u].z * v[u].z + v[u].w * v[u].w;
    }
#pragma unroll
    for (int o = 16; o > 0; o >>= 1) q += __shfl_xor_sync(0xffffffffu, q, o);
    float rstd = rsqrtf(q * (1.0f / DMODEL) + 1e-5f);
    const float4* wr = (const float4*)w;
    const float4* br = (const float4*)bias;
#pragma unroll
    for (int u = 0; u < 4; u++) {
        float4 W = wr[u * 32 + lane], B = br[u * 32 + lane], o4;
        o4.x = v[u].x * rstd * W.x + B.x;
        o4.y = v[u].y * rstd * W.y + B.y;
        o4.z = v[u].z * rstd * W.z + B.z;
        o4.w = v[u].w * rstd * W.w + B.w;
        if (SPLIT) {
            size_t off = (size_t)gw * DMODEL + (u * 32 + lane) * 4;
            uint32_t h0, l0, h1, l1;
            split2h(o4.x, o4.y, h0, l0);
            split2h(o4.z, o4.w, h1, l1);
            *(uint32_t*)(yhi + off)     = h0;
            *(uint32_t*)(yhi + off + 2) = h1;
            *(uint32_t*)(ylo + off)     = l0;
            *(uint32_t*)(ylo + off + 2) = l1;
        } else {
            ((float4*)(y + (size_t)gw * DMODEL))[u * 32 + lane] = o4;
        }
    }
}

// ---------------- tensor-core GEMM (fp16x2): C = (Ahi+Alo) * Wh^T -----------
// 3 planes per stage: Ahi, Alo, W. BK=64, row stride KST=72 halves (144B, 16B-mult).
#define BK 64
#define KST 72
#define PLANE (128*KST)      // 9216 halves
#define STAGE (3*PLANE)      // 27648 halves per stage
#define GEMM_SMEM (2*STAGE*2)  // 110592 bytes

// MODE 1: fp32 = acc+bias+resid. MODE 2: fp16 hi/lo = gelu(acc+bias).
// MODE 3: fp16 hi/lo = acc (lo written only for cols < 512 == Q region).
template <int MODE>
__global__ void __launch_bounds__(256, 2) gemm_tc(
    const __half* __restrict__ Ahi, const __half* __restrict__ Alo,
    const __half* __restrict__ Bh,
    const float* __restrict__ bias, const float* __restrict__ resid,
    float* __restrict__ C, __half* __restrict__ Chi, __half* __restrict__ Clo,
    int N, int K) {
    extern __shared__ __half smbuf[];
    const int tid = threadIdx.x;
    const int lane = tid & 31, w = tid >> 5;
    const int wr = w >> 2, wc = w & 3;
    const int m0 = blockIdx.y * 128, n0 = blockIdx.x * 128;
    const uint32_t smbase = (uint32_t)__cvta_generic_to_shared(smbuf);

    auto load_stage = [&](int it, int buf) {
        const int k0 = it * BK;
#pragma unroll
        for (int i = 0; i < 12; i++) {
            int c = tid + 256 * i;          // 0..3071
            int plane = c >> 10;            // 0:Ahi 1:Alo 2:B
            int rem = c & 1023;
            int r = rem >> 3;               // row 0..127
            int cc = (rem & 7) * 8;         // half-col offset
            const __half* src;
            if (plane == 0)      src = Ahi + (size_t)(m0 + r) * K + k0 + cc;
            else if (plane == 1) src = Alo + (size_t)(m0 + r) * K + k0 + cc;
            else                 src = Bh + (size_t)(n0 + r) * K + k0 + cc;
            cpasync16(smbase + (uint32_t)(buf * STAGE + plane * PLANE + r * KST + cc) * 2,
                      src);
        }
    };

    float acc[4][4][4] = {};

    const int arow = wr * 64 + (lane & 15);
    const int acol = (lane >> 4) * 8;
    const int bn   = wc * 32 + ((lane >> 4) << 3) + (lane & 7);
    const int bk   = ((lane >> 3) & 1) << 3;

    const int niter = K / BK;
    load_stage(0, 0);
    asm volatile("cp.async.commit_group;");
    for (int it = 0; it < niter; ++it) {
        if (it + 1 < niter) {
            load_stage(it + 1, (it + 1) & 1);
            asm volatile("cp.async.commit_group;");
            asm volatile("cp.async.wait_group 1;");
        } else {
            asm volatile("cp.async.wait_group 0;");
        }
        __syncthreads();
        const uint32_t base = smbase + (uint32_t)(it & 1) * STAGE * 2;
#pragma unroll
        for (int kk = 0; kk < BK; kk += 16) {
            uint32_t ahi[4][4], alo[4][4];
#pragma unroll
            for (int mt = 0; mt < 4; ++mt) {
                uint32_t ai = base + (uint32_t)((arow + mt * 16) * KST + kk + acol) * 2;
                ldsm4(ahi[mt][0], ahi[mt][1], ahi[mt][2], ahi[mt][3], ai);
                ldsm4(alo[mt][0], alo[mt][1], alo[mt][2], alo[mt][3], ai + PLANE * 2);
            }
#pragma unroll
            for (int g = 0; g < 2; ++g) {
                uint32_t bf[4];
                uint32_t bi = base + 2 * PLANE * 2 +
                              (uint32_t)((bn + g * 16) * KST + kk + bk) * 2;
                ldsm4(bf[0], bf[1], bf[2], bf[3], bi);
#pragma unroll
                for (int half = 0; half < 2; ++half) {
                    int nt = 2 * g + half;
#pragma unroll
                    for (int mt = 0; mt < 4; ++mt) {
                        mma_f16(acc[mt][nt], ahi[mt], bf + 2 * half);
                        mma_f16(acc[mt][nt], alo[mt], bf + 2 * half);
                    }
                }
            }
        }
        __syncthreads();
    }

    const int erow = m0 + wr * 64 + (lane >> 2);
    const int ecol = n0 + wc * 32 + (lane & 3) * 2;
#pragma unroll
    for (int mt = 0; mt < 4; ++mt)
#pragma unroll
        for (int nt = 0; nt < 4; ++nt) {
            int c = ecol + nt * 8;
#pragma unroll
            for (int half = 0; half < 2; ++half) {
                int rr = erow + mt * 16 + half * 8;
                float v0 = acc[mt][nt][half * 2 + 0];
                float v1 = acc[mt][nt][half * 2 + 1];
                size_t off = (size_t)rr * N + c;
                if (MODE == 1) {
                    float2 rv = *(const float2*)(resid + off);
                    v0 += bias[c] + rv.x;
                    v1 += bias[c + 1] + rv.y;
                    *(float2*)(C + off) = make_float2(v0, v1);
                } else if (MODE == 2) {
                    v0 = gelu_exact(v0 + bias[c]);
                    v1 = gelu_exact(v1 + bias[c + 1]);
                    uint32_t hp, lp;
                    split2h(v0, v1, hp, lp);
                    *(uint32_t*)(Chi + off) = hp;
                    *(uint32_t*)(Clo + off) = lp;
                } else {
                    uint32_t hp, lp;
                    split2h(v0, v1, hp, lp);
                    *(uint32_t*)(Chi + off) = hp;
                    if (c < 512) *(uint32_t*)(Clo + off) = lp;   // lo only needed for Q
                }
            }
        }
}

// ---------------- tensor-core flash attention (fp16x2, cp.async) ------------
#define AST 72
#define Q_ELE (128*AST)        // per Q plane
#define KV_PLANE (64*AST)      // 4608 halves per K/V plane
#define STG_ELE (2*KV_PLANE)   // K + V (single plane each)
#define STG0 (2*Q_ELE)
#define ATT_SMEM ((STG0 + 2*STG_ELE)*2)   // 73728 bytes

__global__ void __launch_bounds__(256, 2) attn_tc(
    const __half* __restrict__ qkvhi, const __half* __restrict__ qkvlo,
    __half* __restrict__ ohi, __half* __restrict__ olo) {
    extern __shared__ __half sb[];
    const uint32_t smb = (uint32_t)__cvta_generic_to_shared(sb);
    const int tid = threadIdx.x, lane = tid & 31, wid = tid >> 5;
    const int q0 = blockIdx.x * 128;
    const int b = blockIdx.y >> 3, h = blockIdx.y & 7;

    const __half* hbase = qkvhi + (size_t)(b * NTOK) * 1536 + h * 64;
    const __half* lbase = qkvlo + (size_t)(b * NTOK) * 1536 + h * 64;

    // Q fill: hi + lo planes, 128 rows x 8 chunks
#pragma unroll
    for (int i = 0; i < 8; i++) {
        int c = tid + 256 * i;
        int plane = c >> 10, rem = c & 1023;
        int row = rem >> 3, col = (rem & 7) * 8;
        const __half* src = (plane ? lbase : hbase) + (size_t)(q0 + row) * 1536 + col;
        cpasync16(smb + (uint32_t)(plane * Q_ELE + row * AST + col) * 2, src);
    }

    auto load_kv = [&](int kt, int buf) {
#pragma unroll
        for (int i = 0; i < 4; i++) {
            int c = tid + 256 * i;
            int plane = c >> 9, rem = c & 511;   // 0:K 1:V (hi planes only)
            int row = rem >> 3, col = (rem & 7) * 8;
            const __half* src = hbase + (plane ? 1024 : 512) +
                                (size_t)(kt * 64 + row) * 1536 + col;
            uint32_t dst = (uint32_t)(STG0 + buf * STG_ELE + plane * KV_PLANE +
                                      row * AST + col) * 2;
            cpasync16(smb + dst, src);
        }
    };

    float oacc[8][4] = {};
    float m0s = -1e30f, m1s = -1e30f, l0s = 0.0f, l1s = 0.0f;
    const float sc = 0.18033688011112042f;   // 0.125 * log2(e)

    load_kv(0, 0);
    asm volatile("cp.async.commit_group;");

    for (int kt = 0; kt < 16; kt++) {
        if (kt + 1 < 16) {
            load_kv(kt + 1, (kt + 1) & 1);
            asm volatile("cp.async.commit_group;");
            asm volatile("cp.async.wait_group 1;");
        } else {
            asm volatile("cp.async.wait_group 0;");
        }
        __syncthreads();
        const uint32_t base = (uint32_t)(STG0 + (kt & 1) * STG_ELE) * 2;

        // ---- S = (Qh+Ql) K^T ----
        float s[8][4] = {};
#pragma unroll
        for (int k8 = 0; k8 < 4; k8++) {
            uint32_t qh[4], ql[4];
            uint32_t qa = smb + (uint32_t)((wid * 16 + (lane & 15)) * AST + k8 * 16 +
                                           ((lane >> 4) << 3)) * 2;
            ldsm4(qh[0], qh[1], qh[2], qh[3], qa);
            ldsm4(ql[0], ql[1], ql[2], ql[3], qa + Q_ELE * 2);
#pragma unroll
            for (int g = 0; g < 4; g++) {
                int br = g * 16 + ((lane >> 4) << 3) + (lane & 7);
                int bc = k8 * 16 + (((lane >> 3) & 1) << 3);
                uint32_t ka = smb + base + (uint32_t)(br * AST + bc) * 2;
                uint32_t bh[4];
                ldsm4(bh[0], bh[1], bh[2], bh[3], ka);
                mma_f16(s[2 * g],     qh, bh);
                mma_f16(s[2 * g],     ql, bh);
                mma_f16(s[2 * g + 1], qh, bh + 2);
                mma_f16(s[2 * g + 1], ql, bh + 2);
            }
        }

        // ---- online softmax in log2 units ----
        float m0 = -1e30f, m1 = -1e30f;
#pragma unroll
        for (int nt = 0; nt < 8; nt++) {
            s[nt][0] *= sc; s[nt][1] *= sc; s[nt][2] *= sc; s[nt][3] *= sc;
            m0 = fmaxf(m0, fmaxf(s[nt][0], s[nt][1]));
            m1 = fmaxf(m1, fmaxf(s[nt][2], s[nt][3]));
        }
        m0 = fmaxf(m0, __shfl_xor_sync(0xffffffffu, m0, 1));
        m0 = fmaxf(m0, __shfl_xor_sync(0xffffffffu, m0, 2));
        m1 = fmaxf(m1, __shfl_xor_sync(0xffffffffu, m1, 1));
        m1 = fmaxf(m1, __shfl_xor_sync(0xffffffffu, m1, 2));
        float mn0 = fmaxf(m0s, m0), mn1 = fmaxf(m1s, m1);
        float a0 = exp2f(m0s - mn0), a1 = exp2f(m1s - mn1);
        m0s = mn0; m1s = mn1;
        float rs0 = 0.0f, rs1 = 0.0f;
#pragma unroll
        for (int nt = 0; nt < 8; nt++) {
            s[nt][0] = exp2f(s[nt][0] - mn0); rs0 += s[nt][0];
            s[nt][1] = exp2f(s[nt][1] - mn0); rs0 += s[nt][1];
            s[nt][2] = exp2f(s[nt][2] - mn1); rs1 += s[nt][2];
            s[nt][3] = exp2f(s[nt][3] - mn1); rs1 += s[nt][3];
        }
        rs0 += __shfl_xor_sync(0xffffffffu, rs0, 1);
        rs0 += __shfl_xor_sync(0xffffffffu, rs0, 2);
        rs1 += __shfl_xor_sync(0xffffffffu, rs1, 1);
        rs1 += __shfl_xor_sync(0xffffffffu, rs1, 2);
        l0s = l0s * a0 + rs0;
        l1s = l1s * a1 + rs1;
#pragma unroll
        for (int nt = 0; nt < 8; nt++) {
            oacc[nt][0] *= a0; oacc[nt][1] *= a0;
            oacc[nt][2] *= a1; oacc[nt][3] *= a1;
        }

        // ---- pack P into fp16 hi/lo A-fragments ----
        uint32_t phi[4][4], plo[4][4];
#pragma unroll
        for (int j = 0; j < 4; j++) {
            split2h(s[2 * j][0],     s[2 * j][1],     phi[j][0], plo[j][0]);
            split2h(s[2 * j][2],     s[2 * j][3],     phi[j][1], plo[j][1]);
            split2h(s[2 * j + 1][0], s[2 * j + 1][1], phi[j][2], plo[j][2]);
            split2h(s[2 * j + 1][2], s[2 * j + 1][3], phi[j][3], plo[j][3]);
        }

        // ---- O += (Ph+Pl) V (V row-major; B-frags via ldmatrix.trans) ----
#pragma unroll
        for (int j = 0; j < 4; j++) {
#pragma unroll
            for (int g = 0; g < 4; g++) {
                uint32_t va = smb + base + (uint32_t)(KV_PLANE +
                              (j * 16 + (lane & 15)) * AST + g * 16 +
                              ((lane >> 4) << 3)) * 2;
                uint32_t vh[4];
                ldsm4t(vh[0], vh[1], vh[2], vh[3], va);
                mma_f16(oacc[2 * g],     phi[j], vh);
                mma_f16(oacc[2 * g],     plo[j], vh);
                mma_f16(oacc[2 * g + 1], phi[j], vh + 2);
                mma_f16(oacc[2 * g + 1], plo[j], vh + 2);
            }
        }
        __syncthreads();
    }

    // ---- epilogue ----
    float li0 = 1.0f / l0s, li1 = 1.0f / l1s;
#pragma unroll
    for (int half = 0; half < 2; half++) {
        int row = q0 + wid * 16 + half * 8 + (lane >> 2);
        float li = half ? li1 : li0;
        size_t baseo = (size_t)(b * NTOK + row) * DMODEL + h * 64 + (lane & 3) * 2;
#pragma unroll
        for (int nt = 0; nt < 8; nt++) {
            float v0 = oacc[nt][half * 2 + 0] * li;
            float v1 = oacc[nt][half * 2 + 1] * li;
            uint32_t hp, lp;
            split2h(v0, v1, hp, lp);
            *(uint32_t*)(ohi + baseo + nt * 8) = hp;
            *(uint32_t*)(olo + baseo + nt * 8) = lp;
        }
    }
}

// ---------------- host orchestration ----------------------------------------
extern "C" void kernel_launch(void* const* d_in, const int* in_sizes, int n_in,
                              void* d_out, int out_size) {
    const float* x         = (const float*)d_in[0];
    const float* attn_ln_w = (const float*)d_in[1];
    const float* attn_ln_b = (const float*)d_in[2];
    const float* w_qkv     = (const float*)d_in[3];
    const float* w_out     = (const float*)d_in[4];
    const float* b_out     = (const float*)d_in[5];
    const float* ffn_ln_w  = (const float*)d_in[6];
    const float* ffn_ln_b  = (const float*)d_in[7];
    const float* w1        = (const float*)d_in[8];
    const float* b1        = (const float*)d_in[9];
    const float* w2        = (const float*)d_in[10];
    const float* b2        = (const float*)d_in[11];
    const float* ln_w      = (const float*)d_in[12];
    const float* ln_b      = (const float*)d_in[13];
    float* out = (float*)d_out;

    float *t, *h;
    __half *qkvhi, *qkvlo, *hhi, *hlo, *ohi, *olo, *f1hi, *f1lo;
    __half *wqkv, *wout, *w1h, *w2h;
    cudaGetSymbolAddress((void**)&t,      g_t);
    cudaGetSymbolAddress((void**)&h,      g_h);
    cudaGetSymbolAddress((void**)&qkvhi,  g_qkvhi);
    cudaGetSymbolAddress((void**)&qkvlo,  g_qkvlo);
    cudaGetSymbolAddress((void**)&hhi,    g_hhi);
    cudaGetSymbolAddress((void**)&hlo,    g_hlo);
    cudaGetSymbolAddress((void**)&ohi,    g_ohi);
    cudaGetSymbolAddress((void**)&olo,    g_olo);
    cudaGetSymbolAddress((void**)&f1hi,   g_f1hi);
    cudaGetSymbolAddress((void**)&f1lo,   g_f1lo);
    cudaGetSymbolAddress((void**)&wqkv,   g_wqkv);
    cudaGetSymbolAddress((void**)&wout,   g_wout);
    cudaGetSymbolAddress((void**)&w1h,    g_w1);
    cudaGetSymbolAddress((void**)&w2h,    g_w2);

    cudaFuncSetAttribute(attn_tc, cudaFuncAttributeMaxDynamicSharedMemorySize, ATT_SMEM);
    cudaFuncSetAttribute(gemm_tc<1>, cudaFuncAttributeMaxDynamicSharedMemorySize, GEMM_SMEM);
    cudaFuncSetAttribute(gemm_tc<2>, cudaFuncAttributeMaxDynamicSharedMemorySize, GEMM_SMEM);
    cudaFuncSetAttribute(gemm_tc<3>, cudaFuncAttributeMaxDynamicSharedMemorySize, GEMM_SMEM);

    {
        const int n0 = DEPTH * 3 * DMODEL * DMODEL;
        const int n1 = DEPTH * DMODEL * DMODEL;
        const int n2 = 2 * DMODEL * DMODEL;
        const int n3 = 2 * DMODEL * DMODEL;
        const int ntot = n0 + n1 + n2 + n3;
        split_allh<<<(ntot + 255) / 256, 256>>>(
            w_qkv, wqkv, n0, w_out, wout, n1, w1, w1h, n2, w2, w2h, n3);
    }

    dim3 tb(32, 8);
    embed_kernel<<<dim3(32, 16, 8), tb>>>(x, t);

    for (int l = 0; l < DEPTH; l++) {
        ln_kernel<true><<<1024, 256>>>(t, attn_ln_w + l * DMODEL, attn_ln_b + l * DMODEL,
                                       nullptr, hhi, hlo);
        gemm_tc<3><<<dim3(12, 64), 256, GEMM_SMEM>>>(
            hhi, hlo, wqkv + (size_t)l * 3 * DMODEL * DMODEL,
            nullptr, nullptr, nullptr, qkvhi, qkvlo, 3 * DMODEL, DMODEL);
        attn_tc<<<dim3(8, 64), 256, ATT_SMEM>>>(qkvhi, qkvlo, ohi, olo);
        gemm_tc<1><<<dim3(4, 64), 256, GEMM_SMEM>>>(
            ohi, olo, wout + (size_t)l * DMODEL * DMODEL,
            b_out + l * DMODEL, t, t, nullptr, nullptr, DMODEL, DMODEL);
        ln_kernel<true><<<1024, 256>>>(t, ffn_ln_w, ffn_ln_b, nullptr, hhi, hlo);
        gemm_tc<2><<<dim3(8, 64), 256, GEMM_SMEM>>>(
            hhi, hlo, w1h, b1, nullptr, nullptr, f1hi, f1lo, 2 * DMODEL, DMODEL);
        gemm_tc<1><<<dim3(4, 64), 256, GEMM_SMEM>>>(
            f1hi, f1lo, w2h, b2, t, t, nullptr, nullptr, DMODEL, 2 * DMODEL);
    }

    ln_kernel<false><<<1024, 256>>>(t, ln_w, ln_b, h, nullptr, nullptr);
    unembed_kernel<<<dim3(32, 16, 8), tb>>>(h, out);
}

// round 13
// speedup vs baseline: 7.2321x; 1.5903x over previous
#include <cuda_runtime.h>
#include <cuda_fp16.h>
#include <math.h>
#include <stdint.h>

#define NTOK 1024
#define DMODEL 512
#define BATCH 8
#define DEPTH 4
#define ROWS (BATCH*NTOK)   // 8192

// ---------------- scratch (static device globals; no runtime allocation) ----
__device__ float g_t  [ROWS*DMODEL];
__device__ float g_h  [ROWS*DMODEL];
__device__ __half g_qkv[ROWS*3*DMODEL];
__device__ __half g_hh [ROWS*DMODEL];
__device__ __half g_oh [ROWS*DMODEL];
__device__ __half g_f1 [ROWS*2*DMODEL];
__device__ __half g_wqkv[DEPTH*3*DMODEL*DMODEL];
__device__ __half g_wout[DEPTH*DMODEL*DMODEL];
__device__ __half g_w1[2*DMODEL*DMODEL];
__device__ __half g_w2[2*DMODEL*DMODEL];

// ---------------- helpers ----------------------------------------------------
__device__ __forceinline__ uint32_t pack2h(float a, float b) {
    __half2 hp = __halves2half2(__float2half_rn(a), __float2half_rn(b));
    return *(uint32_t*)&hp;
}
__device__ __forceinline__ void ldsm4(uint32_t& r0, uint32_t& r1, uint32_t& r2, uint32_t& r3,
                                      uint32_t addr) {
    asm volatile("ldmatrix.sync.aligned.m8n8.x4.shared.b16 {%0,%1,%2,%3},[%4];"
                 : "=r"(r0), "=r"(r1), "=r"(r2), "=r"(r3) : "r"(addr));
}
__device__ __forceinline__ void ldsm4t(uint32_t& r0, uint32_t& r1, uint32_t& r2, uint32_t& r3,
                                       uint32_t addr) {
    asm volatile("ldmatrix.sync.aligned.m8n8.x4.trans.shared.b16 {%0,%1,%2,%3},[%4];"
                 : "=r"(r0), "=r"(r1), "=r"(r2), "=r"(r3) : "r"(addr));
}
__device__ __forceinline__ void mma_f16(float* c, const uint32_t* a, const uint32_t* b) {
    asm volatile(
        "mma.sync.aligned.m16n8k16.row.col.f32.f16.f16.f32 "
        "{%0,%1,%2,%3},{%4,%5,%6,%7},{%8,%9},{%0,%1,%2,%3};"
        : "+f"(c[0]), "+f"(c[1]), "+f"(c[2]), "+f"(c[3])
        : "r"(a[0]), "r"(a[1]), "r"(a[2]), "r"(a[3]), "r"(b[0]), "r"(b[1]));
}
__device__ __forceinline__ void cpasync16(uint32_t saddr, const void* g) {
    asm volatile("cp.async.cg.shared.global [%0],[%1],16;" :: "r"(saddr), "l"(g));
}
__device__ __forceinline__ float gelu_exact(float v) {
    return 0.5f * v * (1.0f + erff(v * 0.7071067811865476f));
}

// ---------------- fp16 convert of ALL weight tensors (one launch) -----------
__global__ void split_allh(const float* __restrict__ w0, __half* __restrict__ h0, int n0,
                           const float* __restrict__ w1, __half* __restrict__ h1, int n1,
                           const float* __restrict__ w2, __half* __restrict__ h2, int n2,
                           const float* __restrict__ w3, __half* __restrict__ h3, int n3) {
    int i = blockIdx.x * 256 + threadIdx.x;
    const float* w; __half* h;
    if (i < n0) { w = w0 + i; h = h0 + i; }
    else if (i < n0 + n1) { i -= n0; w = w1 + i; h = h1 + i; }
    else if (i < n0 + n1 + n2) { i -= n0 + n1; w = w2 + i; h = h2 + i; }
    else if (i < n0 + n1 + n2 + n3) { i -= n0 + n1 + n2; w = w3 + i; h = h3 + i; }
    else return;
    *h = __float2half_rn(*w);
}

// ---------------- embed / unembed -------------------------------------------
__global__ void embed_kernel(const float* __restrict__ x, float* __restrict__ t) {
    __shared__ float tile[32][33];
    int n0 = blockIdx.x * 32, c0 = blockIdx.y * 32, b = blockIdx.z;
    int tx = threadIdx.x, ty = threadIdx.y;
#pragma unroll
    for (int i = 0; i < 4; i++) {
        int c = c0 + ty + i * 8;
        tile[ty + i * 8][tx] = x[((size_t)b * DMODEL + c) * NTOK + n0 + tx];
    }
    __syncthreads();
#pragma unroll
    for (int i = 0; i < 4; i++) {
        int n = n0 + ty + i * 8;
        int c = c0 + tx;
        float e = (float)(c & ~1) * (1.0f / DMODEL);
        float ang = (float)n * expf(-9.210340371976184f * e);
        float pe = (c & 1) ? cosf(ang) : sinf(ang);
        t[((size_t)b * NTOK + n) * DMODEL + c] = tile[tx][ty + i * 8] + pe;
    }
}
__global__ void unembed_kernel(const float* __restrict__ h, float* __restrict__ out) {
    __shared__ float tile[32][33];
    int n0 = blockIdx.x * 32, c0 = blockIdx.y * 32, b = blockIdx.z;
    int tx = threadIdx.x, ty = threadIdx.y;
#pragma unroll
    for (int i = 0; i < 4; i++) {
        int n = n0 + ty + i * 8;
        tile[ty + i * 8][tx] = h[((size_t)b * NTOK + n) * DMODEL + c0 + tx];
    }
    __syncthreads();
#pragma unroll
    for (int i = 0; i < 4; i++) {
        int c = c0 + ty + i * 8;
        out[((size_t)b * DMODEL + c) * NTOK + n0 + tx] = tile[tx][ty + i * 8];
    }
}

// ---------------- layernorm: one warp per row; SPLIT -> fp16 plane ----------
template <bool SPLIT>
__global__ void ln_kernel(const float* __restrict__ x, const float* __restrict__ w,
                          const float* __restrict__ bias, float* __restrict__ y,
                          __half* __restrict__ yh) {
    int gw = (blockIdx.x * blockDim.x + threadIdx.x) >> 5;
    int lane = threadIdx.x & 31;
    if (gw >= ROWS) return;
    const float4* xr = (const float4*)(x + (size_t)gw * DMODEL);
    float4 v[4];
    float s = 0.0f;
#pragma unroll
    for (int u = 0; u < 4; u++) {
        v[u] = xr[u * 32 + lane];
        s += v[u].x + v[u].y + v[u].z + v[u].w;
    }
#pragma unroll
    for (int o = 16; o > 0; o >>= 1) s += __shfl_xor_sync(0xffffffffu, s, o);
    float mu = s * (1.0f / DMODEL);
    float q = 0.0f;
#pragma unroll
    for (int u = 0; u < 4; u++) {
        v[u].x -= mu; v[u].y -= mu; v[u].z -= mu; v[u].w -= mu;
        q += v[u].x * v[u].x + v[u].y * v[u].y + v[u].z * v[u].z + v[u].w * v[u].w;
    }
#pragma unroll
    for (int o = 16; o > 0; o >>= 1) q += __shfl_xor_sync(0xffffffffu, q, o);
    float rstd = rsqrtf(q * (1.0f / DMODEL) + 1e-5f);
    const float4* wr = (const float4*)w;
    const float4* br = (const float4*)bias;
#pragma unroll
    for (int u = 0; u < 4; u++) {
        float4 W = wr[u * 32 + lane], B = br[u * 32 + lane], o4;
        o4.x = v[u].x * rstd * W.x + B.x;
        o4.y = v[u].y * rstd * W.y + B.y;
        o4.z = v[u].z * rstd * W.z + B.z;
        o4.w = v[u].w * rstd * W.w + B.w;
        if (SPLIT) {
            size_t off = (size_t)gw * DMODEL + (u * 32 + lane) * 4;
            *(uint32_t*)(yh + off)     = pack2h(o4.x, o4.y);
            *(uint32_t*)(yh + off + 2) = pack2h(o4.z, o4.w);
        } else {
            ((float4*)(y + (size_t)gw * DMODEL))[u * 32 + lane] = o4;
        }
    }
}

// ---------------- tensor-core GEMM (fp16): C = A * W^T ----------------------
// 2 planes per stage: A, W. BK=64, row stride KST=72 halves (144B).
#define BK 64
#define KST 72
#define PLANE (128*KST)        // 9216 halves
#define STAGE (2*PLANE)        // 18432 halves per stage
#define GEMM_SMEM (2*STAGE*2)  // 73728 bytes

// MODE 1: fp32 = acc+bias+resid. MODE 2: fp16 = gelu(acc+bias). MODE 3: fp16 = acc.
template <int MODE>
__global__ void __launch_bounds__(256, 2) gemm_tc(
    const __half* __restrict__ Ah, const __half* __restrict__ Bh,
    const float* __restrict__ bias, const float* __restrict__ resid,
    float* __restrict__ C, __half* __restrict__ Ch,
    int N, int K) {
    extern __shared__ __half smbuf[];
    const int tid = threadIdx.x;
    const int lane = tid & 31, w = tid >> 5;
    const int wr = w >> 2, wc = w & 3;
    const int m0 = blockIdx.y * 128, n0 = blockIdx.x * 128;
    const uint32_t smbase = (uint32_t)__cvta_generic_to_shared(smbuf);

    auto load_stage = [&](int it, int buf) {
        const int k0 = it * BK;
#pragma unroll
        for (int i = 0; i < 8; i++) {
            int c = tid + 256 * i;          // 0..2047
            int plane = c >> 10;            // 0:A 1:B
            int rem = c & 1023;
            int r = rem >> 3;               // row 0..127
            int cc = (rem & 7) * 8;
            const __half* src = plane ? (Bh + (size_t)(n0 + r) * K + k0 + cc)
                                      : (Ah + (size_t)(m0 + r) * K + k0 + cc);
            cpasync16(smbase + (uint32_t)(buf * STAGE + plane * PLANE + r * KST + cc) * 2,
                      src);
        }
    };

    float acc[4][4][4] = {};

    const int arow = wr * 64 + (lane & 15);
    const int acol = (lane >> 4) * 8;
    const int bn   = wc * 32 + ((lane >> 4) << 3) + (lane & 7);
    const int bk   = ((lane >> 3) & 1) << 3;

    const int niter = K / BK;
    load_stage(0, 0);
    asm volatile("cp.async.commit_group;");
    for (int it = 0; it < niter; ++it) {
        if (it + 1 < niter) {
            load_stage(it + 1, (it + 1) & 1);
            asm volatile("cp.async.commit_group;");
            asm volatile("cp.async.wait_group 1;");
        } else {
            asm volatile("cp.async.wait_group 0;");
        }
        __syncthreads();
        const uint32_t base = smbase + (uint32_t)(it & 1) * STAGE * 2;
#pragma unroll
        for (int kk = 0; kk < BK; kk += 16) {
            uint32_t af[4][4];
#pragma unroll
            for (int mt = 0; mt < 4; ++mt) {
                uint32_t ai = base + (uint32_t)((arow + mt * 16) * KST + kk + acol) * 2;
                ldsm4(af[mt][0], af[mt][1], af[mt][2], af[mt][3], ai);
            }
#pragma unroll
            for (int g = 0; g < 2; ++g) {
                uint32_t bf[4];
                uint32_t bi = base + PLANE * 2 +
                              (uint32_t)((bn + g * 16) * KST + kk + bk) * 2;
                ldsm4(bf[0], bf[1], bf[2], bf[3], bi);
#pragma unroll
                for (int half = 0; half < 2; ++half) {
                    int nt = 2 * g + half;
#pragma unroll
                    for (int mt = 0; mt < 4; ++mt)
                        mma_f16(acc[mt][nt], af[mt], bf + 2 * half);
                }
            }
        }
        __syncthreads();
    }

    const int erow = m0 + wr * 64 + (lane >> 2);
    const int ecol = n0 + wc * 32 + (lane & 3) * 2;
#pragma unroll
    for (int mt = 0; mt < 4; ++mt)
#pragma unroll
        for (int nt = 0; nt < 4; ++nt) {
            int c = ecol + nt * 8;
#pragma unroll
            for (int half = 0; half < 2; ++half) {
                int rr = erow + mt * 16 + half * 8;
                float v0 = acc[mt][nt][half * 2 + 0];
                float v1 = acc[mt][nt][half * 2 + 1];
                size_t off = (size_t)rr * N + c;
                if (MODE == 1) {
                    float2 rv = *(const float2*)(resid + off);
                    v0 += bias[c] + rv.x;
                    v1 += bias[c + 1] + rv.y;
                    *(float2*)(C + off) = make_float2(v0, v1);
                } else if (MODE == 2) {
                    v0 = gelu_exact(v0 + bias[c]);
                    v1 = gelu_exact(v1 + bias[c + 1]);
                    *(uint32_t*)(Ch + off) = pack2h(v0, v1);
                } else {
                    *(uint32_t*)(Ch + off) = pack2h(v0, v1);
                }
            }
        }
}

// ---------------- tensor-core flash attention (fp16, cp.async) --------------
#define AST 72
#define Q_ELE (128*AST)        // single Q plane
#define KV_PLANE (64*AST)
#define STG_ELE (2*KV_PLANE)   // K + V
#define ATT_SMEM ((Q_ELE + 2*STG_ELE)*2)   // 55296 bytes

__global__ void __launch_bounds__(256, 2) attn_tc(
    const __half* __restrict__ qkv, __half* __restrict__ oh) {
    extern __shared__ __half sb[];
    const uint32_t smb = (uint32_t)__cvta_generic_to_shared(sb);
    const int tid = threadIdx.x, lane = tid & 31, wid = tid >> 5;
    const int q0 = blockIdx.x * 128;
    const int b = blockIdx.y >> 3, h = blockIdx.y & 7;

    const __half* hbase = qkv + (size_t)(b * NTOK) * 1536 + h * 64;

    // Q fill: 128 rows x 8 chunks = 1024 -> 4 per thread
#pragma unroll
    for (int i = 0; i < 4; i++) {
        int c = tid + 256 * i;
        int row = c >> 3, col = (c & 7) * 8;
        cpasync16(smb + (uint32_t)(row * AST + col) * 2,
                  hbase + (size_t)(q0 + row) * 1536 + col);
    }

    auto load_kv = [&](int kt, int buf) {
#pragma unroll
        for (int i = 0; i < 4; i++) {
            int c = tid + 256 * i;
            int plane = c >> 9, rem = c & 511;   // 0:K 1:V
            int row = rem >> 3, col = (rem & 7) * 8;
            const __half* src = hbase + (plane ? 1024 : 512) +
                                (size_t)(kt * 64 + row) * 1536 + col;
            uint32_t dst = (uint32_t)(Q_ELE + buf * STG_ELE + plane * KV_PLANE +
                                      row * AST + col) * 2;
            cpasync16(smb + dst, src);
        }
    };

    float oacc[8][4] = {};
    float m0s = -1e30f, m1s = -1e30f, l0s = 0.0f, l1s = 0.0f;
    const float sc = 0.18033688011112042f;   // 0.125 * log2(e)

    load_kv(0, 0);
    asm volatile("cp.async.commit_group;");

    for (int kt = 0; kt < 16; kt++) {
        if (kt + 1 < 16) {
            load_kv(kt + 1, (kt + 1) & 1);
            asm volatile("cp.async.commit_group;");
            asm volatile("cp.async.wait_group 1;");
        } else {
            asm volatile("cp.async.wait_group 0;");
        }
        __syncthreads();
        const uint32_t base = (uint32_t)(Q_ELE + (kt & 1) * STG_ELE) * 2;

        // ---- S = Q K^T ----
        float s[8][4] = {};
#pragma unroll
        for (int k8 = 0; k8 < 4; k8++) {
            uint32_t qf[4];
            uint32_t qa = smb + (uint32_t)((wid * 16 + (lane & 15)) * AST + k8 * 16 +
                                           ((lane >> 4) << 3)) * 2;
            ldsm4(qf[0], qf[1], qf[2], qf[3], qa);
#pragma unroll
            for (int g = 0; g < 4; g++) {
                int br = g * 16 + ((lane >> 4) << 3) + (lane & 7);
                int bc = k8 * 16 + (((lane >> 3) & 1) << 3);
                uint32_t ka = smb + base + (uint32_t)(br * AST + bc) * 2;
                uint32_t bh[4];
                ldsm4(bh[0], bh[1], bh[2], bh[3], ka);
                mma_f16(s[2 * g],     qf, bh);
                mma_f16(s[2 * g + 1], qf, bh + 2);
            }
        }

        // ---- online softmax in log2 units ----
        float m0 = -1e30f, m1 = -1e30f;
#pragma unroll
        for (int nt = 0; nt < 8; nt++) {
            s[nt][0] *= sc; s[nt][1] *= sc; s[nt][2] *= sc; s[nt][3] *= sc;
            m0 = fmaxf(m0, fmaxf(s[nt][0], s[nt][1]));
            m1 = fmaxf(m1, fmaxf(s[nt][2], s[nt][3]));
        }
        m0 = fmaxf(m0, __shfl_xor_sync(0xffffffffu, m0, 1));
        m0 = fmaxf(m0, __shfl_xor_sync(0xffffffffu, m0, 2));
        m1 = fmaxf(m1, __shfl_xor_sync(0xffffffffu, m1, 1));
        m1 = fmaxf(m1, __shfl_xor_sync(0xffffffffu, m1, 2));
        float mn0 = fmaxf(m0s, m0), mn1 = fmaxf(m1s, m1);
        float a0 = exp2f(m0s - mn0), a1 = exp2f(m1s - mn1);
        m0s = mn0; m1s = mn1;
        float rs0 = 0.0f, rs1 = 0.0f;
#pragma unroll
        for (int nt = 0; nt < 8; nt++) {
            s[nt][0] = exp2f(s[nt][0] - mn0); rs0 += s[nt][0];
            s[nt][1] = exp2f(s[nt][1] - mn0); rs0 += s[nt][1];
            s[nt][2] = exp2f(s[nt][2] - mn1); rs1 += s[nt][2];
            s[nt][3] = exp2f(s[nt][3] - mn1); rs1 += s[nt][3];
        }
        rs0 += __shfl_xor_sync(0xffffffffu, rs0, 1);
        rs0 += __shfl_xor_sync(0xffffffffu, rs0, 2);
        rs1 += __shfl_xor_sync(0xffffffffu, rs1, 1);
        rs1 += __shfl_xor_sync(0xffffffffu, rs1, 2);
        l0s = l0s * a0 + rs0;
        l1s = l1s * a1 + rs1;
#pragma unroll
        for (int nt = 0; nt < 8; nt++) {
            oacc[nt][0] *= a0; oacc[nt][1] *= a0;
            oacc[nt][2] *= a1; oacc[nt][3] *= a1;
        }

        // ---- pack P into fp16 A-fragments ----
        uint32_t pf[4][4];
#pragma unroll
        for (int j = 0; j < 4; j++) {
            pf[j][0] = pack2h(s[2 * j][0],     s[2 * j][1]);
            pf[j][1] = pack2h(s[2 * j][2],     s[2 * j][3]);
            pf[j][2] = pack2h(s[2 * j + 1][0], s[2 * j + 1][1]);
            pf[j][3] = pack2h(s[2 * j + 1][2], s[2 * j + 1][3]);
        }

        // ---- O += P V ----
#pragma unroll
        for (int j = 0; j < 4; j++) {
#pragma unroll
            for (int g = 0; g < 4; g++) {
                uint32_t va = smb + base + (uint32_t)(KV_PLANE +
                              (j * 16 + (lane & 15)) * AST + g * 16 +
                              ((lane >> 4) << 3)) * 2;
                uint32_t vh[4];
                ldsm4t(vh[0], vh[1], vh[2], vh[3], va);
                mma_f16(oacc[2 * g],     pf[j], vh);
                mma_f16(oacc[2 * g + 1], pf[j], vh + 2);
            }
        }
        __syncthreads();
    }

    // ---- epilogue ----
    float li0 = 1.0f / l0s, li1 = 1.0f / l1s;
#pragma unroll
    for (int half = 0; half < 2; half++) {
        int row = q0 + wid * 16 + half * 8 + (lane >> 2);
        float li = half ? li1 : li0;
        size_t baseo = (size_t)(b * NTOK + row) * DMODEL + h * 64 + (lane & 3) * 2;
#pragma unroll
        for (int nt = 0; nt < 8; nt++) {
            float v0 = oacc[nt][half * 2 + 0] * li;
            float v1 = oacc[nt][half * 2 + 1] * li;
            *(uint32_t*)(oh + baseo + nt * 8) = pack2h(v0, v1);
        }
    }
}

// ---------------- host orchestration ----------------------------------------
extern "C" void kernel_launch(void* const* d_in, const int* in_sizes, int n_in,
                              void* d_out, int out_size) {
    const float* x         = (const float*)d_in[0];
    const float* attn_ln_w = (const float*)d_in[1];
    const float* attn_ln_b = (const float*)d_in[2];
    const float* w_qkv     = (const float*)d_in[3];
    const float* w_out     = (const float*)d_in[4];
    const float* b_out     = (const float*)d_in[5];
    const float* ffn_ln_w  = (const float*)d_in[6];
    const float* ffn_ln_b  = (const float*)d_in[7];
    const float* w1        = (const float*)d_in[8];
    const float* b1        = (const float*)d_in[9];
    const float* w2        = (const float*)d_in[10];
    const float* b2        = (const float*)d_in[11];
    const float* ln_w      = (const float*)d_in[12];
    const float* ln_b      = (const float*)d_in[13];
    float* out = (float*)d_out;

    float *t, *h;
    __half *qkv, *hh, *oh, *f1;
    __half *wqkv, *wout, *w1h, *w2h;
    cudaGetSymbolAddress((void**)&t,    g_t);
    cudaGetSymbolAddress((void**)&h,    g_h);
    cudaGetSymbolAddress((void**)&qkv,  g_qkv);
    cudaGetSymbolAddress((void**)&hh,   g_hh);
    cudaGetSymbolAddress((void**)&oh,   g_oh);
    cudaGetSymbolAddress((void**)&f1,   g_f1);
    cudaGetSymbolAddress((void**)&wqkv, g_wqkv);
    cudaGetSymbolAddress((void**)&wout, g_wout);
    cudaGetSymbolAddress((void**)&w1h,  g_w1);
    cudaGetSymbolAddress((void**)&w2h,  g_w2);

    cudaFuncSetAttribute(attn_tc, cudaFuncAttributeMaxDynamicSharedMemorySize, ATT_SMEM);
    cudaFuncSetAttribute(gemm_tc<1>, cudaFuncAttributeMaxDynamicSharedMemorySize, GEMM_SMEM);
    cudaFuncSetAttribute(gemm_tc<2>, cudaFuncAttributeMaxDynamicSharedMemorySize, GEMM_SMEM);
    cudaFuncSetAttribute(gemm_tc<3>, cudaFuncAttributeMaxDynamicSharedMemorySize, GEMM_SMEM);

    {
        const int n0 = DEPTH * 3 * DMODEL * DMODEL;
        const int n1 = DEPTH * DMODEL * DMODEL;
        const int n2 = 2 * DMODEL * DMODEL;
        const int n3 = 2 * DMODEL * DMODEL;
        const int ntot = n0 + n1 + n2 + n3;
        split_allh<<<(ntot + 255) / 256, 256>>>(
            w_qkv, wqkv, n0, w_out, wout, n1, w1, w1h, n2, w2, w2h, n3);
    }

    dim3 tb(32, 8);
    embed_kernel<<<dim3(32, 16, 8), tb>>>(x, t);

    for (int l = 0; l < DEPTH; l++) {
        ln_kernel<true><<<1024, 256>>>(t, attn_ln_w + l * DMODEL, attn_ln_b + l * DMODEL,
                                       nullptr, hh);
        gemm_tc<3><<<dim3(12, 64), 256, GEMM_SMEM>>>(
            hh, wqkv + (size_t)l * 3 * DMODEL * DMODEL,
            nullptr, nullptr, nullptr, qkv, 3 * DMODEL, DMODEL);
        attn_tc<<<dim3(8, 64), 256, ATT_SMEM>>>(qkv, oh);
        gemm_tc<1><<<dim3(4, 64), 256, GEMM_SMEM>>>(
            oh, wout + (size_t)l * DMODEL * DMODEL,
            b_out + l * DMODEL, t, t, nullptr, DMODEL, DMODEL);
        ln_kernel<true><<<1024, 256>>>(t, ffn_ln_w, ffn_ln_b, nullptr, hh);
        gemm_tc<2><<<dim3(8, 64), 256, GEMM_SMEM>>>(
            hh, w1h, b1, nullptr, nullptr, f1, 2 * DMODEL, DMODEL);
        gemm_tc<1><<<dim3(4, 64), 256, GEMM_SMEM>>>(
            f1, w2h, b2, t, t, nullptr, DMODEL, 2 * DMODEL);
    }

    ln_kernel<false><<<1024, 256>>>(t, ln_w, ln_b, h, nullptr);
    unembed_kernel<<<dim3(32, 16, 8), tb>>>(h, out);
}

// round 14
// speedup vs baseline: 7.2863x; 1.0075x over previous
#include <cuda_runtime.h>
#include <cuda_fp16.h>
#include <math.h>
#include <stdint.h>

#define NTOK 1024
#define DMODEL 512
#define BATCH 8
#define DEPTH 4
#define ROWS (BATCH*NTOK)   // 8192

// ---------------- scratch (static device globals; no runtime allocation) ----
__device__ float g_t  [ROWS*DMODEL];
__device__ __half g_qkv[ROWS*3*DMODEL];
__device__ __half g_hh [ROWS*DMODEL];
__device__ __half g_oh [ROWS*DMODEL];
__device__ __half g_f1 [ROWS*2*DMODEL];
__device__ __half g_wqkv[DEPTH*3*DMODEL*DMODEL];
__device__ __half g_wout[DEPTH*DMODEL*DMODEL];
__device__ __half g_w1[2*DMODEL*DMODEL];
__device__ __half g_w2[2*DMODEL*DMODEL];

// ---------------- helpers ----------------------------------------------------
__device__ __forceinline__ uint32_t pack2h(float a, float b) {
    __half2 hp = __halves2half2(__float2half_rn(a), __float2half_rn(b));
    return *(uint32_t*)&hp;
}
__device__ __forceinline__ void ldsm4(uint32_t& r0, uint32_t& r1, uint32_t& r2, uint32_t& r3,
                                      uint32_t addr) {
    asm volatile("ldmatrix.sync.aligned.m8n8.x4.shared.b16 {%0,%1,%2,%3},[%4];"
                 : "=r"(r0), "=r"(r1), "=r"(r2), "=r"(r3) : "r"(addr));
}
__device__ __forceinline__ void ldsm4t(uint32_t& r0, uint32_t& r1, uint32_t& r2, uint32_t& r3,
                                       uint32_t addr) {
    asm volatile("ldmatrix.sync.aligned.m8n8.x4.trans.shared.b16 {%0,%1,%2,%3},[%4];"
                 : "=r"(r0), "=r"(r1), "=r"(r2), "=r"(r3) : "r"(addr));
}
__device__ __forceinline__ void mma_f16(float* c, const uint32_t* a, const uint32_t* b) {
    asm volatile(
        "mma.sync.aligned.m16n8k16.row.col.f32.f16.f16.f32 "
        "{%0,%1,%2,%3},{%4,%5,%6,%7},{%8,%9},{%0,%1,%2,%3};"
        : "+f"(c[0]), "+f"(c[1]), "+f"(c[2]), "+f"(c[3])
        : "r"(a[0]), "r"(a[1]), "r"(a[2]), "r"(a[3]), "r"(b[0]), "r"(b[1]));
}
__device__ __forceinline__ void cpasync16(uint32_t saddr, const void* g) {
    asm volatile("cp.async.cg.shared.global [%0],[%1],16;" :: "r"(saddr), "l"(g));
}
__device__ __forceinline__ float gelu_exact(float v) {
    return 0.5f * v * (1.0f + erff(v * 0.7071067811865476f));
}

// ---------------- fp16 convert of ALL weight tensors (one launch) -----------
__global__ void split_allh(const float* __restrict__ w0, __half* __restrict__ h0, int n0,
                           const float* __restrict__ w1, __half* __restrict__ h1, int n1,
                           const float* __restrict__ w2, __half* __restrict__ h2, int n2,
                           const float* __restrict__ w3, __half* __restrict__ h3, int n3) {
    int i = blockIdx.x * 256 + threadIdx.x;
    const float* w; __half* h;
    if (i < n0) { w = w0 + i; h = h0 + i; }
    else if (i < n0 + n1) { i -= n0; w = w1 + i; h = h1 + i; }
    else if (i < n0 + n1 + n2) { i -= n0 + n1; w = w2 + i; h = h2 + i; }
    else if (i < n0 + n1 + n2 + n3) { i -= n0 + n1 + n2; w = w3 + i; h = h3 + i; }
    else return;
    *h = __float2half_rn(*w);
}

// ---------------- embed: transpose [b,c,n] -> [b,n,c] + sinusoid PE ---------
__global__ void embed_kernel(const float* __restrict__ x, float* __restrict__ t) {
    __shared__ float tile[32][33];
    int n0 = blockIdx.x * 32, c0 = blockIdx.y * 32, b = blockIdx.z;
    int tx = threadIdx.x, ty = threadIdx.y;
#pragma unroll
    for (int i = 0; i < 4; i++) {
        int c = c0 + ty + i * 8;
        tile[ty + i * 8][tx] = x[((size_t)b * DMODEL + c) * NTOK + n0 + tx];
    }
    __syncthreads();
#pragma unroll
    for (int i = 0; i < 4; i++) {
        int n = n0 + ty + i * 8;
        int c = c0 + tx;
        float e = (float)(c & ~1) * (1.0f / DMODEL);
        float ang = (float)n * expf(-9.210340371976184f * e);
        float pe = (c & 1) ? cosf(ang) : sinf(ang);
        t[((size_t)b * NTOK + n) * DMODEL + c] = tile[tx][ty + i * 8] + pe;
    }
}

// ---------------- fused final LN + unembed transpose ------------------------
// block = 256 threads, handles 32 token rows of one batch; warp w -> rows 4w..4w+3.
#define FLN_ST 513
__global__ void __launch_bounds__(256) ln_unembed_kernel(
    const float* __restrict__ t, const float* __restrict__ lw,
    const float* __restrict__ lb, float* __restrict__ out) {
    extern __shared__ float fsm[];           // [32][FLN_ST]
    const int tid = threadIdx.x, lane = tid & 31, w = tid >> 5;
    const int n0 = blockIdx.x * 32, b = blockIdx.y;

    const float4* wr = (const float4*)lw;
    const float4* br = (const float4*)lb;
#pragma unroll
    for (int rr = 0; rr < 4; rr++) {
        int rloc = w * 4 + rr;
        const float4* xr = (const float4*)(t + (size_t)(b * NTOK + n0 + rloc) * DMODEL);
        float4 v[4];
        float s = 0.0f;
#pragma unroll
        for (int u = 0; u < 4; u++) {
            v[u] = xr[u * 32 + lane];
            s += v[u].x + v[u].y + v[u].z + v[u].w;
        }
#pragma unroll
        for (int o = 16; o > 0; o >>= 1) s += __shfl_xor_sync(0xffffffffu, s, o);
        float mu = s * (1.0f / DMODEL);
        float q = 0.0f;
#pragma unroll
        for (int u = 0; u < 4; u++) {
            v[u].x -= mu; v[u].y -= mu; v[u].z -= mu; v[u].w -= mu;
            q += v[u].x * v[u].x + v[u].y * v[u].y + v[u].z * v[u].z + v[u].w * v[u].w;
        }
#pragma unroll
        for (int o = 16; o > 0; o >>= 1) q += __shfl_xor_sync(0xffffffffu, q, o);
        float rstd = rsqrtf(q * (1.0f / DMODEL) + 1e-5f);
        float* dst = fsm + rloc * FLN_ST;
#pragma unroll
        for (int u = 0; u < 4; u++) {
            float4 W = wr[u * 32 + lane], B = br[u * 32 + lane];
            int c = (u * 32 + lane) * 4;
            dst[c + 0] = v[u].x * rstd * W.x + B.x;
            dst[c + 1] = v[u].y * rstd * W.y + B.y;
            dst[c + 2] = v[u].z * rstd * W.z + B.z;
            dst[c + 3] = v[u].w * rstd * W.w + B.w;
        }
    }
    __syncthreads();

    // coalesced channel-major write: thread -> (c = cb + tid>>5, n = n0 + lane)
    const int nl = lane;
#pragma unroll 8
    for (int cb = 0; cb < DMODEL; cb += 8) {
        int c = cb + w;
        out[((size_t)b * DMODEL + c) * NTOK + n0 + nl] = fsm[nl * FLN_ST + c];
    }
}

// ---------------- layernorm -> fp16 plane (per-layer) -----------------------
__global__ void ln_kernel(const float* __restrict__ x, const float* __restrict__ w,
                          const float* __restrict__ bias, __half* __restrict__ yh) {
    int gw = (blockIdx.x * blockDim.x + threadIdx.x) >> 5;
    int lane = threadIdx.x & 31;
    if (gw >= ROWS) return;
    const float4* xr = (const float4*)(x + (size_t)gw * DMODEL);
    float4 v[4];
    float s = 0.0f;
#pragma unroll
    for (int u = 0; u < 4; u++) {
        v[u] = xr[u * 32 + lane];
        s += v[u].x + v[u].y + v[u].z + v[u].w;
    }
#pragma unroll
    for (int o = 16; o > 0; o >>= 1) s += __shfl_xor_sync(0xffffffffu, s, o);
    float mu = s * (1.0f / DMODEL);
    float q = 0.0f;
#pragma unroll
    for (int u = 0; u < 4; u++) {
        v[u].x -= mu; v[u].y -= mu; v[u].z -= mu; v[u].w -= mu;
        q += v[u].x * v[u].x + v[u].y * v[u].y + v[u].z * v[u].z + v[u].w * v[u].w;
    }
#pragma unroll
    for (int o = 16; o > 0; o >>= 1) q += __shfl_xor_sync(0xffffffffu, q, o);
    float rstd = rsqrtf(q * (1.0f / DMODEL) + 1e-5f);
    const float4* wr = (const float4*)w;
    const float4* br = (const float4*)bias;
#pragma unroll
    for (int u = 0; u < 4; u++) {
        float4 W = wr[u * 32 + lane], B = br[u * 32 + lane];
        float o0 = v[u].x * rstd * W.x + B.x;
        float o1 = v[u].y * rstd * W.y + B.y;
        float o2 = v[u].z * rstd * W.z + B.z;
        float o3 = v[u].w * rstd * W.w + B.w;
        size_t off = (size_t)gw * DMODEL + (u * 32 + lane) * 4;
        *(uint32_t*)(yh + off)     = pack2h(o0, o1);
        *(uint32_t*)(yh + off + 2) = pack2h(o2, o3);
    }
}

// ---------------- tensor-core GEMM (fp16): C = A * W^T ----------------------
#define BK 64
#define KST 72
#define PLANE (128*KST)        // 9216 halves
#define STAGE (2*PLANE)        // 18432 halves per stage
#define GEMM_SMEM (2*STAGE*2)  // 73728 bytes

// MODE 1: fp32 = acc+bias+resid. MODE 2: fp16 = gelu(acc+bias). MODE 3: fp16 = acc.
template <int MODE>
__global__ void __launch_bounds__(256, 2) gemm_tc(
    const __half* __restrict__ Ah, const __half* __restrict__ Bh,
    const float* __restrict__ bias, const float* __restrict__ resid,
    float* __restrict__ C, __half* __restrict__ Ch,
    int N, int K) {
    extern __shared__ __half smbuf[];
    const int tid = threadIdx.x;
    const int lane = tid & 31, w = tid >> 5;
    const int wr = w >> 2, wc = w & 3;
    const int m0 = blockIdx.y * 128, n0 = blockIdx.x * 128;
    const uint32_t smbase = (uint32_t)__cvta_generic_to_shared(smbuf);

    auto load_stage = [&](int it, int buf) {
        const int k0 = it * BK;
#pragma unroll
        for (int i = 0; i < 8; i++) {
            int c = tid + 256 * i;          // 0..2047
            int plane = c >> 10;            // 0:A 1:B
            int rem = c & 1023;
            int r = rem >> 3;               // row 0..127
            int cc = (rem & 7) * 8;
            const __half* src = plane ? (Bh + (size_t)(n0 + r) * K + k0 + cc)
                                      : (Ah + (size_t)(m0 + r) * K + k0 + cc);
            cpasync16(smbase + (uint32_t)(buf * STAGE + plane * PLANE + r * KST + cc) * 2,
                      src);
        }
    };

    float acc[4][4][4] = {};

    const int arow = wr * 64 + (lane & 15);
    const int acol = (lane >> 4) * 8;
    const int bn   = wc * 32 + ((lane >> 4) << 3) + (lane & 7);
    const int bk   = ((lane >> 3) & 1) << 3;

    const int niter = K / BK;
    load_stage(0, 0);
    asm volatile("cp.async.commit_group;");
    for (int it = 0; it < niter; ++it) {
        if (it + 1 < niter) {
            load_stage(it + 1, (it + 1) & 1);
            asm volatile("cp.async.commit_group;");
            asm volatile("cp.async.wait_group 1;");
        } else {
            asm volatile("cp.async.wait_group 0;");
        }
        __syncthreads();
        const uint32_t base = smbase + (uint32_t)(it & 1) * STAGE * 2;
#pragma unroll
        for (int kk = 0; kk < BK; kk += 16) {
            uint32_t af[4][4];
#pragma unroll
            for (int mt = 0; mt < 4; ++mt) {
                uint32_t ai = base + (uint32_t)((arow + mt * 16) * KST + kk + acol) * 2;
                ldsm4(af[mt][0], af[mt][1], af[mt][2], af[mt][3], ai);
            }
#pragma unroll
            for (int g = 0; g < 2; ++g) {
                uint32_t bf[4];
                uint32_t bi = base + PLANE * 2 +
                              (uint32_t)((bn + g * 16) * KST + kk + bk) * 2;
                ldsm4(bf[0], bf[1], bf[2], bf[3], bi);
#pragma unroll
                for (int half = 0; half < 2; ++half) {
                    int nt = 2 * g + half;
#pragma unroll
                    for (int mt = 0; mt < 4; ++mt)
                        mma_f16(acc[mt][nt], af[mt], bf + 2 * half);
                }
            }
        }
        __syncthreads();
    }

    const int erow = m0 + wr * 64 + (lane >> 2);
    const int ecol = n0 + wc * 32 + (lane & 3) * 2;
#pragma unroll
    for (int mt = 0; mt < 4; ++mt)
#pragma unroll
        for (int nt = 0; nt < 4; ++nt) {
            int c = ecol + nt * 8;
#pragma unroll
            for (int half = 0; half < 2; ++half) {
                int rr = erow + mt * 16 + half * 8;
                float v0 = acc[mt][nt][half * 2 + 0];
                float v1 = acc[mt][nt][half * 2 + 1];
                size_t off = (size_t)rr * N + c;
                if (MODE == 1) {
                    float2 rv = *(const float2*)(resid + off);
                    v0 += bias[c] + rv.x;
                    v1 += bias[c + 1] + rv.y;
                    *(float2*)(C + off) = make_float2(v0, v1);
                } else if (MODE == 2) {
                    v0 = gelu_exact(v0 + bias[c]);
                    v1 = gelu_exact(v1 + bias[c + 1]);
                    *(uint32_t*)(Ch + off) = pack2h(v0, v1);
                } else {
                    *(uint32_t*)(Ch + off) = pack2h(v0, v1);
                }
            }
        }
}

// ---------------- tensor-core flash attention (fp16, cp.async) --------------
#define AST 72
#define Q_ELE (128*AST)
#define KV_PLANE (64*AST)
#define STG_ELE (2*KV_PLANE)
#define ATT_SMEM ((Q_ELE + 2*STG_ELE)*2)   // 55296 bytes

__global__ void __launch_bounds__(256, 2) attn_tc(
    const __half* __restrict__ qkv, __half* __restrict__ oh) {
    extern __shared__ __half sb[];
    const uint32_t smb = (uint32_t)__cvta_generic_to_shared(sb);
    const int tid = threadIdx.x, lane = tid & 31, wid = tid >> 5;
    const int q0 = blockIdx.x * 128;
    const int b = blockIdx.y >> 3, h = blockIdx.y & 7;

    const __half* hbase = qkv + (size_t)(b * NTOK) * 1536 + h * 64;

#pragma unroll
    for (int i = 0; i < 4; i++) {
        int c = tid + 256 * i;
        int row = c >> 3, col = (c & 7) * 8;
        cpasync16(smb + (uint32_t)(row * AST + col) * 2,
                  hbase + (size_t)(q0 + row) * 1536 + col);
    }

    auto load_kv = [&](int kt, int buf) {
#pragma unroll
        for (int i = 0; i < 4; i++) {
            int c = tid + 256 * i;
            int plane = c >> 9, rem = c & 511;
            int row = rem >> 3, col = (rem & 7) * 8;
            const __half* src = hbase + (plane ? 1024 : 512) +
                                (size_t)(kt * 64 + row) * 1536 + col;
            uint32_t dst = (uint32_t)(Q_ELE + buf * STG_ELE + plane * KV_PLANE +
                                      row * AST + col) * 2;
            cpasync16(smb + dst, src);
        }
    };

    float oacc[8][4] = {};
    float m0s = -1e30f, m1s = -1e30f, l0s = 0.0f, l1s = 0.0f;
    const float sc = 0.18033688011112042f;

    load_kv(0, 0);
    asm volatile("cp.async.commit_group;");

    for (int kt = 0; kt < 16; kt++) {
        if (kt + 1 < 16) {
            load_kv(kt + 1, (kt + 1) & 1);
            asm volatile("cp.async.commit_group;");
            asm volatile("cp.async.wait_group 1;");
        } else {
            asm volatile("cp.async.wait_group 0;");
        }
        __syncthreads();
        const uint32_t base = (uint32_t)(Q_ELE + (kt & 1) * STG_ELE) * 2;

        float s[8][4] = {};
#pragma unroll
        for (int k8 = 0; k8 < 4; k8++) {
            uint32_t qf[4];
            uint32_t qa = smb + (uint32_t)((wid * 16 + (lane & 15)) * AST + k8 * 16 +
                                           ((lane >> 4) << 3)) * 2;
            ldsm4(qf[0], qf[1], qf[2], qf[3], qa);
#pragma unroll
            for (int g = 0; g < 4; g++) {
                int br = g * 16 + ((lane >> 4) << 3) + (lane & 7);
                int bc = k8 * 16 + (((lane >> 3) & 1) << 3);
                uint32_t ka = smb + base + (uint32_t)(br * AST + bc) * 2;
                uint32_t bh[4];
                ldsm4(bh[0], bh[1], bh[2], bh[3], ka);
                mma_f16(s[2 * g],     qf, bh);
                mma_f16(s[2 * g + 1], qf, bh + 2);
            }
        }

        float m0 = -1e30f, m1 = -1e30f;
#pragma unroll
        for (int nt = 0; nt < 8; nt++) {
            s[nt][0] *= sc; s[nt][1] *= sc; s[nt][2] *= sc; s[nt][3] *= sc;
            m0 = fmaxf(m0, fmaxf(s[nt][0], s[nt][1]));
            m1 = fmaxf(m1, fmaxf(s[nt][2], s[nt][3]));
        }
        m0 = fmaxf(m0, __shfl_xor_sync(0xffffffffu, m0, 1));
        m0 = fmaxf(m0, __shfl_xor_sync(0xffffffffu, m0, 2));
        m1 = fmaxf(m1, __shfl_xor_sync(0xffffffffu, m1, 1));
        m1 = fmaxf(m1, __shfl_xor_sync(0xffffffffu, m1, 2));
        float mn0 = fmaxf(m0s, m0), mn1 = fmaxf(m1s, m1);
        float a0 = exp2f(m0s - mn0), a1 = exp2f(m1s - mn1);
        m0s = mn0; m1s = mn1;
        float rs0 = 0.0f, rs1 = 0.0f;
#pragma unroll
        for (int nt = 0; nt < 8; nt++) {
            s[nt][0] = exp2f(s[nt][0] - mn0); rs0 += s[nt][0];
            s[nt][1] = exp2f(s[nt][1] - mn0); rs0 += s[nt][1];
            s[nt][2] = exp2f(s[nt][2] - mn1); rs1 += s[nt][2];
            s[nt][3] = exp2f(s[nt][3] - mn1); rs1 += s[nt][3];
        }
        rs0 += __shfl_xor_sync(0xffffffffu, rs0, 1);
        rs0 += __shfl_xor_sync(0xffffffffu, rs0, 2);
        rs1 += __shfl_xor_sync(0xffffffffu, rs1, 1);
        rs1 += __shfl_xor_sync(0xffffffffu, rs1, 2);
        l0s = l0s * a0 + rs0;
        l1s = l1s * a1 + rs1;
#pragma unroll
        for (int nt = 0; nt < 8; nt++) {
            oacc[nt][0] *= a0; oacc[nt][1] *= a0;
            oacc[nt][2] *= a1; oacc[nt][3] *= a1;
        }

        uint32_t pf[4][4];
#pragma unroll
        for (int j = 0; j < 4; j++) {
            pf[j][0] = pack2h(s[2 * j][0],     s[2 * j][1]);
            pf[j][1] = pack2h(s[2 * j][2],     s[2 * j][3]);
            pf[j][2] = pack2h(s[2 * j + 1][0], s[2 * j + 1][1]);
            pf[j][3] = pack2h(s[2 * j + 1][2], s[2 * j + 1][3]);
        }

#pragma unroll
        for (int j = 0; j < 4; j++) {
#pragma unroll
            for (int g = 0; g < 4; g++) {
                uint32_t va = smb + base + (uint32_t)(KV_PLANE +
                              (j * 16 + (lane & 15)) * AST + g * 16 +
                              ((lane >> 4) << 3)) * 2;
                uint32_t vh[4];
                ldsm4t(vh[0], vh[1], vh[2], vh[3], va);
                mma_f16(oacc[2 * g],     pf[j], vh);
                mma_f16(oacc[2 * g + 1], pf[j], vh + 2);
            }
        }
        __syncthreads();
    }

    float li0 = 1.0f / l0s, li1 = 1.0f / l1s;
#pragma unroll
    for (int half = 0; half < 2; half++) {
        int row = q0 + wid * 16 + half * 8 + (lane >> 2);
        float li = half ? li1 : li0;
        size_t baseo = (size_t)(b * NTOK + row) * DMODEL + h * 64 + (lane & 3) * 2;
#pragma unroll
        for (int nt = 0; nt < 8; nt++) {
            float v0 = oacc[nt][half * 2 + 0] * li;
            float v1 = oacc[nt][half * 2 + 1] * li;
            *(uint32_t*)(oh + baseo + nt * 8) = pack2h(v0, v1);
        }
    }
}

// ---------------- host orchestration ----------------------------------------
extern "C" void kernel_launch(void* const* d_in, const int* in_sizes, int n_in,
                              void* d_out, int out_size) {
    const float* x         = (const float*)d_in[0];
    const float* attn_ln_w = (const float*)d_in[1];
    const float* attn_ln_b = (const float*)d_in[2];
    const float* w_qkv     = (const float*)d_in[3];
    const float* w_out     = (const float*)d_in[4];
    const float* b_out     = (const float*)d_in[5];
    const float* ffn_ln_w  = (const float*)d_in[6];
    const float* ffn_ln_b  = (const float*)d_in[7];
    const float* w1        = (const float*)d_in[8];
    const float* b1        = (const float*)d_in[9];
    const float* w2        = (const float*)d_in[10];
    const float* b2        = (const float*)d_in[11];
    const float* ln_w      = (const float*)d_in[12];
    const float* ln_b      = (const float*)d_in[13];
    float* out = (float*)d_out;

    float* t;
    __half *qkv, *hh, *oh, *f1;
    __half *wqkv, *wout, *w1h, *w2h;
    cudaGetSymbolAddress((void**)&t,    g_t);
    cudaGetSymbolAddress((void**)&qkv,  g_qkv);
    cudaGetSymbolAddress((void**)&hh,   g_hh);
    cudaGetSymbolAddress((void**)&oh,   g_oh);
    cudaGetSymbolAddress((void**)&f1,   g_f1);
    cudaGetSymbolAddress((void**)&wqkv, g_wqkv);
    cudaGetSymbolAddress((void**)&wout, g_wout);
    cudaGetSymbolAddress((void**)&w1h,  g_w1);
    cudaGetSymbolAddress((void**)&w2h,  g_w2);

    cudaFuncSetAttribute(attn_tc, cudaFuncAttributeMaxDynamicSharedMemorySize, ATT_SMEM);
    cudaFuncSetAttribute(gemm_tc<1>, cudaFuncAttributeMaxDynamicSharedMemorySize, GEMM_SMEM);
    cudaFuncSetAttribute(gemm_tc<2>, cudaFuncAttributeMaxDynamicSharedMemorySize, GEMM_SMEM);
    cudaFuncSetAttribute(gemm_tc<3>, cudaFuncAttributeMaxDynamicSharedMemorySize, GEMM_SMEM);
    cudaFuncSetAttribute(ln_unembed_kernel, cudaFuncAttributeMaxDynamicSharedMemorySize,
                         32 * FLN_ST * 4);

    {
        const int n0 = DEPTH * 3 * DMODEL * DMODEL;
        const int n1 = DEPTH * DMODEL * DMODEL;
        const int n2 = 2 * DMODEL * DMODEL;
        const int n3 = 2 * DMODEL * DMODEL;
        const int ntot = n0 + n1 + n2 + n3;
        split_allh<<<(ntot + 255) / 256, 256>>>(
            w_qkv, wqkv, n0, w_out, wout, n1, w1, w1h, n2, w2, w2h, n3);
    }

    dim3 tb(32, 8);
    embed_kernel<<<dim3(32, 16, 8), tb>>>(x, t);

    for (int l = 0; l < DEPTH; l++) {
        ln_kernel<<<1024, 256>>>(t, attn_ln_w + l * DMODEL, attn_ln_b + l * DMODEL, hh);
        gemm_tc<3><<<dim3(12, 64), 256, GEMM_SMEM>>>(
            hh, wqkv + (size_t)l * 3 * DMODEL * DMODEL,
            nullptr, nullptr, nullptr, qkv, 3 * DMODEL, DMODEL);
        attn_tc<<<dim3(8, 64), 256, ATT_SMEM>>>(qkv, oh);
        gemm_tc<1><<<dim3(4, 64), 256, GEMM_SMEM>>>(
            oh, wout + (size_t)l * DMODEL * DMODEL,
            b_out + l * DMODEL, t, t, nullptr, DMODEL, DMODEL);
        ln_kernel<<<1024, 256>>>(t, ffn_ln_w, ffn_ln_b, hh);
        gemm_tc<2><<<dim3(8, 64), 256, GEMM_SMEM>>>(
            hh, w1h, b1, nullptr, nullptr, f1, 2 * DMODEL, DMODEL);
        gemm_tc<1><<<dim3(4, 64), 256, GEMM_SMEM>>>(
            f1, w2h, b2, t, t, nullptr, DMODEL, 2 * DMODEL);
    }

    ln_unembed_kernel<<<dim3(32, 8), 256, 32 * FLN_ST * 4>>>(t, ln_w, ln_b, out);
}